// round 1
// baseline (speedup 1.0000x reference)
#include <cuda_runtime.h>
#include <cuda_bf16.h>
#include <math.h>

// ---------------------------------------------------------------------------
// Problem constants
// ---------------------------------------------------------------------------
#define BATCH      4096
#define NUM_PAIRS  28
#define PAIR_DIM   128
#define MACRO_DIM  256
#define NUM_SLOTS  64
#define D_ALL      3584          // NUM_PAIRS * PAIR_DIM
#define D_CAT      7168          // 2 * D_ALL
#define LN_EPS     1e-5f

// ---------------------------------------------------------------------------
// Scratch (device globals: allocation-free per harness rules)
// ---------------------------------------------------------------------------
__device__ float g_attn_pair[BATCH * NUM_SLOTS];
__device__ float g_attn_macro[BATCH * NUM_SLOTS];
__device__ float g_concat[(size_t)BATCH * D_CAT];   // [pair_corr | macro_corr]
__device__ float g_h[(size_t)BATCH * D_ALL];        // fusion hidden (in-place LN+GELU)
__device__ float g_fused[(size_t)BATCH * D_ALL];    // output of fusion MLP

// ---------------------------------------------------------------------------
// Kernel 1: pair-query mean + scores + softmax  -> attn_pair (B,64)
// ---------------------------------------------------------------------------
__global__ __launch_bounds__(128) void attn_pair_kernel(
    const float* __restrict__ ps,      // (B, 28, 128)
    const float* __restrict__ keys,    // (64, 128)
    float* __restrict__ attn)          // (B, 64)
{
    int b = blockIdx.x, tid = threadIdx.x;
    __shared__ float q[PAIR_DIM];
    __shared__ float sc[NUM_SLOTS];
    __shared__ float red[NUM_SLOTS];

    float s = 0.f;
    #pragma unroll
    for (int p = 0; p < NUM_PAIRS; p++)
        s += ps[(size_t)b * D_ALL + p * PAIR_DIM + tid];
    q[tid] = s * (1.0f / NUM_PAIRS);
    __syncthreads();

    if (tid < NUM_SLOTS) {
        float acc = 0.f;
        #pragma unroll 4
        for (int d = 0; d < PAIR_DIM; d++)
            acc = fmaf(q[d], keys[tid * PAIR_DIM + d], acc);
        sc[tid] = acc * 0.08838834764831845f;   // 1/sqrt(128)
    }
    __syncthreads();

    if (tid < NUM_SLOTS) red[tid] = sc[tid];
    __syncthreads();
    for (int o = 32; o > 0; o >>= 1) {
        if (tid < o) red[tid] = fmaxf(red[tid], red[tid + o]);
        __syncthreads();
    }
    float mx = red[0];
    __syncthreads();

    float e = 0.f;
    if (tid < NUM_SLOTS) { e = expf(sc[tid] - mx); red[tid] = e; }
    __syncthreads();
    for (int o = 32; o > 0; o >>= 1) {
        if (tid < o) red[tid] += red[tid + o];
        __syncthreads();
    }
    if (tid < NUM_SLOTS)
        attn[(size_t)b * NUM_SLOTS + tid] = e / red[0];
}

// ---------------------------------------------------------------------------
// Kernel 2: macro scores + softmax -> attn_macro (B,64)
// ---------------------------------------------------------------------------
__global__ __launch_bounds__(128) void attn_macro_kernel(
    const float* __restrict__ ms,      // (B, 256)
    const float* __restrict__ keys,    // (64, 256)
    float* __restrict__ attn)          // (B, 64)
{
    int b = blockIdx.x, tid = threadIdx.x;
    __shared__ float q[MACRO_DIM];
    __shared__ float sc[NUM_SLOTS];
    __shared__ float red[NUM_SLOTS];

    q[tid]       = ms[(size_t)b * MACRO_DIM + tid];
    q[tid + 128] = ms[(size_t)b * MACRO_DIM + tid + 128];
    __syncthreads();

    if (tid < NUM_SLOTS) {
        float acc = 0.f;
        #pragma unroll 4
        for (int d = 0; d < MACRO_DIM; d++)
            acc = fmaf(q[d], keys[tid * MACRO_DIM + d], acc);
        sc[tid] = acc * 0.0625f;   // 1/sqrt(256)
    }
    __syncthreads();

    if (tid < NUM_SLOTS) red[tid] = sc[tid];
    __syncthreads();
    for (int o = 32; o > 0; o >>= 1) {
        if (tid < o) red[tid] = fmaxf(red[tid], red[tid + o]);
        __syncthreads();
    }
    float mx = red[0];
    __syncthreads();

    float e = 0.f;
    if (tid < NUM_SLOTS) { e = expf(sc[tid] - mx); red[tid] = e; }
    __syncthreads();
    for (int o = 32; o > 0; o >>= 1) {
        if (tid < o) red[tid] += red[tid + o];
        __syncthreads();
    }
    if (tid < NUM_SLOTS)
        attn[(size_t)b * NUM_SLOTS + tid] = e / red[0];
}

// ---------------------------------------------------------------------------
// Generic fp32 SIMT GEMM: C[M,N] = A[M,K]*B[K,N] (+bias), row-major, strided.
// 128x128 block tile, BK=8, 8x8 per thread, 256 threads.
// All dims used here are multiples of the tile factors.
// ---------------------------------------------------------------------------
#define BM 128
#define BN 128
#define BKK 8
#define TM 8
#define TN 8

__global__ __launch_bounds__(256) void sgemm_kernel(
    const float* __restrict__ A, const float* __restrict__ B,
    const float* __restrict__ bias, float* __restrict__ C,
    int M, int N, int K, int lda, int ldb, int ldc)
{
    __shared__ float As[BKK][BM];
    __shared__ float Bs[BKK][BN];

    int tid = threadIdx.x;
    int bx = blockIdx.x;           // N tile
    int by = blockIdx.y;           // M tile
    int tx = tid & 15;             // 0..15 -> col micro
    int ty = tid >> 4;             // 0..15 -> row micro

    int rowA = tid >> 1;           // 0..127
    int colA = (tid & 1) * 4;      // 0 or 4
    int rowB = tid >> 5;           // 0..7
    int colB = (tid & 31) * 4;     // 0..124

    const float* Ag = A + (size_t)(by * BM + rowA) * lda + colA;
    const float* Bg = B + (size_t)rowB * ldb + bx * BN + colB;

    float acc[TM][TN];
    #pragma unroll
    for (int i = 0; i < TM; i++)
        #pragma unroll
        for (int j = 0; j < TN; j++)
            acc[i][j] = 0.f;

    for (int k0 = 0; k0 < K; k0 += BKK) {
        float4 av = *reinterpret_cast<const float4*>(Ag + k0);
        float4 bv = *reinterpret_cast<const float4*>(Bg + (size_t)k0 * ldb);
        As[colA + 0][rowA] = av.x;
        As[colA + 1][rowA] = av.y;
        As[colA + 2][rowA] = av.z;
        As[colA + 3][rowA] = av.w;
        *reinterpret_cast<float4*>(&Bs[rowB][colB]) = bv;
        __syncthreads();

        #pragma unroll
        for (int kk = 0; kk < BKK; kk++) {
            float a[TM], bb[TN];
            #pragma unroll
            for (int i = 0; i < TM; i++) a[i] = As[kk][ty * TM + i];
            #pragma unroll
            for (int j = 0; j < TN; j++) bb[j] = Bs[kk][tx * TN + j];
            #pragma unroll
            for (int i = 0; i < TM; i++)
                #pragma unroll
                for (int j = 0; j < TN; j++)
                    acc[i][j] = fmaf(a[i], bb[j], acc[i][j]);
        }
        __syncthreads();
    }

    #pragma unroll
    for (int i = 0; i < TM; i++) {
        int r = by * BM + ty * TM + i;
        #pragma unroll
        for (int j = 0; j < TN; j++) {
            int c = bx * BN + tx * TN + j;
            float v = acc[i][j];
            if (bias) v += bias[c];
            C[(size_t)r * ldc + c] = v;
        }
    }
}

// ---------------------------------------------------------------------------
// Kernel: in-place LayerNorm + exact GELU over rows of length D_ALL
// ---------------------------------------------------------------------------
__global__ __launch_bounds__(256) void ln_gelu_kernel(
    float* __restrict__ h, const float* __restrict__ g, const float* __restrict__ b)
{
    __shared__ float row[D_ALL];
    __shared__ float red[256];
    int bi = blockIdx.x, tid = threadIdx.x;
    float* hrow = h + (size_t)bi * D_ALL;

    float s = 0.f;
    for (int i = tid; i < D_ALL; i += 256) { float v = hrow[i]; row[i] = v; s += v; }
    red[tid] = s; __syncthreads();
    for (int o = 128; o > 0; o >>= 1) { if (tid < o) red[tid] += red[tid + o]; __syncthreads(); }
    float mu = red[0] * (1.0f / D_ALL);
    __syncthreads();

    float s2 = 0.f;
    for (int i = tid; i < D_ALL; i += 256) { float d = row[i] - mu; s2 += d * d; }
    red[tid] = s2; __syncthreads();
    for (int o = 128; o > 0; o >>= 1) { if (tid < o) red[tid] += red[tid + o]; __syncthreads(); }
    float rstd = rsqrtf(red[0] * (1.0f / D_ALL) + LN_EPS);

    for (int i = tid; i < D_ALL; i += 256) {
        float y = (row[i] - mu) * rstd * g[i] + b[i];
        hrow[i] = 0.5f * y * (1.0f + erff(y * 0.70710678118654752f));  // exact GELU
    }
}

// ---------------------------------------------------------------------------
// Kernel: per-pair Linear (K=256) + bias + LayerNorm(128) -> d_out
// Block: (b-tile of 32, pair p). 256 threads, 4x4 micro tile.
// ---------------------------------------------------------------------------
#define PKT 32
__global__ __launch_bounds__(256) void pair_out_kernel(
    const float* __restrict__ ps,      // (B,28,128)
    const float* __restrict__ fused,   // (B,28,128) flattened as (B, D_ALL)
    const float* __restrict__ pw,      // (28,256,128)
    const float* __restrict__ pb,      // (28,128)
    const float* __restrict__ lng,     // (28,128)
    const float* __restrict__ lnb,     // (28,128)
    float* __restrict__ out)           // (B,28,128)
{
    int p  = blockIdx.y;
    int b0 = blockIdx.x * 32;
    int tid = threadIdx.x;

    __shared__ float xs[PKT][33];      // [k][row], padded
    __shared__ float ws[PKT][128];     // [k][e]
    __shared__ float os[32][128];      // output staging for LN

    int warp = tid >> 5;               // 0..7
    int lane = tid & 31;               // 0..31
    int ty = warp;                     // row-micro group (4 rows each)
    int tx = lane;                     // col-micro group (4 cols each)

    float acc[4][4];
    #pragma unroll
    for (int i = 0; i < 4; i++)
        #pragma unroll
        for (int j = 0; j < 4; j++) acc[i][j] = 0.f;

    for (int k0 = 0; k0 < 2 * PAIR_DIM; k0 += PKT) {
        // load x chunk: 32 rows x 32 k  (x = [pair_states | fused] along k)
        #pragma unroll
        for (int l = 0; l < 4; l++) {
            int idx = tid + l * 256;       // 0..1023
            int r  = idx >> 5;
            int kk = idx & 31;
            int d  = k0 + kk;
            int b  = b0 + r;
            float v;
            if (d < PAIR_DIM)
                v = ps[(size_t)b * D_ALL + p * PAIR_DIM + d];
            else
                v = fused[(size_t)b * D_ALL + p * PAIR_DIM + (d - PAIR_DIM)];
            xs[kk][r] = v;
        }
        // load w chunk: 32 k x 128 e
        #pragma unroll
        for (int l = 0; l < 4; l++) {
            int idx = tid + l * 256;       // float4 index 0..1023
            int kk = idx >> 5;
            int e4 = (idx & 31) * 4;
            *reinterpret_cast<float4*>(&ws[kk][e4]) =
                *reinterpret_cast<const float4*>(
                    &pw[((size_t)p * 256 + k0 + kk) * 128 + e4]);
        }
        __syncthreads();

        #pragma unroll
        for (int kk = 0; kk < PKT; kk++) {
            float a[4], bb[4];
            #pragma unroll
            for (int i = 0; i < 4; i++) a[i] = xs[kk][ty * 4 + i];
            #pragma unroll
            for (int j = 0; j < 4; j++) bb[j] = ws[kk][tx * 4 + j];
            #pragma unroll
            for (int i = 0; i < 4; i++)
                #pragma unroll
                for (int j = 0; j < 4; j++)
                    acc[i][j] = fmaf(a[i], bb[j], acc[i][j]);
        }
        __syncthreads();
    }

    // stage with bias
    #pragma unroll
    for (int i = 0; i < 4; i++)
        #pragma unroll
        for (int j = 0; j < 4; j++)
            os[ty * 4 + i][tx * 4 + j] = acc[i][j] + pb[p * PAIR_DIM + tx * 4 + j];
    __syncthreads();

    // LayerNorm over 128 per row: 8 warps x 4 rows
    #pragma unroll
    for (int rr = 0; rr < 4; rr++) {
        int r = warp * 4 + rr;
        float v0 = os[r][lane], v1 = os[r][lane + 32];
        float v2 = os[r][lane + 64], v3 = os[r][lane + 96];
        float s = v0 + v1 + v2 + v3;
        #pragma unroll
        for (int o = 16; o > 0; o >>= 1) s += __shfl_xor_sync(0xffffffff, s, o);
        float mu = s * (1.0f / 128.0f);
        float d0 = v0 - mu, d1 = v1 - mu, d2 = v2 - mu, d3 = v3 - mu;
        float s2 = d0 * d0 + d1 * d1 + d2 * d2 + d3 * d3;
        #pragma unroll
        for (int o = 16; o > 0; o >>= 1) s2 += __shfl_xor_sync(0xffffffff, s2, o);
        float rstd = rsqrtf(s2 * (1.0f / 128.0f) + LN_EPS);

        int b = b0 + r;
        size_t base = (size_t)b * D_ALL + p * PAIR_DIM;
        int gi = p * PAIR_DIM;
        out[base + lane]      = d0 * rstd * lng[gi + lane]      + lnb[gi + lane];
        out[base + lane + 32] = d1 * rstd * lng[gi + lane + 32] + lnb[gi + lane + 32];
        out[base + lane + 64] = d2 * rstd * lng[gi + lane + 64] + lnb[gi + lane + 64];
        out[base + lane + 96] = d3 * rstd * lng[gi + lane + 96] + lnb[gi + lane + 96];
    }
}

// ---------------------------------------------------------------------------
// Launch
// ---------------------------------------------------------------------------
extern "C" void kernel_launch(void* const* d_in, const int* in_sizes, int n_in,
                              void* d_out, int out_size)
{
    const float* pair_states    = (const float*)d_in[0];
    const float* macro_state    = (const float*)d_in[1];
    const float* mem_pair_keys  = (const float*)d_in[2];
    const float* mem_pair_vals  = (const float*)d_in[3];
    const float* mem_macro_keys = (const float*)d_in[4];
    const float* mem_macro_vals = (const float*)d_in[5];
    const float* fusion_w1      = (const float*)d_in[6];
    const float* fusion_b1      = (const float*)d_in[7];
    const float* fusion_ln_g    = (const float*)d_in[8];
    const float* fusion_ln_b    = (const float*)d_in[9];
    const float* fusion_w2      = (const float*)d_in[10];
    const float* fusion_b2      = (const float*)d_in[11];
    const float* pair_w         = (const float*)d_in[12];
    const float* pair_b         = (const float*)d_in[13];
    const float* pair_ln_g      = (const float*)d_in[14];
    const float* pair_ln_b      = (const float*)d_in[15];
    float* out = (float*)d_out;

    float *attn_p, *attn_m, *concat, *h, *fused;
    cudaGetSymbolAddress((void**)&attn_p, g_attn_pair);
    cudaGetSymbolAddress((void**)&attn_m, g_attn_macro);
    cudaGetSymbolAddress((void**)&concat, g_concat);
    cudaGetSymbolAddress((void**)&h,      g_h);
    cudaGetSymbolAddress((void**)&fused,  g_fused);

    // 1) attention weights
    attn_pair_kernel<<<BATCH, 128>>>(pair_states, mem_pair_keys, attn_p);
    attn_macro_kernel<<<BATCH, 128>>>(macro_state, mem_macro_keys, attn_m);

    // 2) memory value reads, written into the two halves of concat (ldc = 7168)
    sgemm_kernel<<<dim3(D_ALL / BN, BATCH / BM), 256>>>(
        attn_p, mem_pair_vals, nullptr, concat,
        BATCH, D_ALL, NUM_SLOTS, NUM_SLOTS, D_ALL, D_CAT);
    sgemm_kernel<<<dim3(D_ALL / BN, BATCH / BM), 256>>>(
        attn_m, mem_macro_vals, nullptr, concat + D_ALL,
        BATCH, D_ALL, NUM_SLOTS, NUM_SLOTS, D_ALL, D_CAT);

    // 3) fusion MLP
    sgemm_kernel<<<dim3(D_ALL / BN, BATCH / BM), 256>>>(
        concat, fusion_w1, fusion_b1, h,
        BATCH, D_ALL, D_CAT, D_CAT, D_ALL, D_ALL);
    ln_gelu_kernel<<<BATCH, 256>>>(h, fusion_ln_g, fusion_ln_b);
    sgemm_kernel<<<dim3(D_ALL / BN, BATCH / BM), 256>>>(
        h, fusion_w2, fusion_b2, fused,
        BATCH, D_ALL, D_ALL, D_ALL, D_ALL, D_ALL);

    // 4) per-pair linear + LN -> output
    pair_out_kernel<<<dim3(BATCH / 32, NUM_PAIRS), 256>>>(
        pair_states, fused, pair_w, pair_b, pair_ln_g, pair_ln_b, out);
}

// round 3
// speedup vs baseline: 2.3559x; 2.3559x over previous
#include <cuda_runtime.h>
#include <cuda_bf16.h>
#include <math.h>
#include <stdint.h>

// ---------------------------------------------------------------------------
// Problem constants
// ---------------------------------------------------------------------------
#define BATCH      4096
#define NUM_PAIRS  28
#define PAIR_DIM   128
#define MACRO_DIM  256
#define NUM_SLOTS  64
#define D_ALL      3584          // NUM_PAIRS * PAIR_DIM
#define D_CAT      7168          // 2 * D_ALL
#define LN_EPS     1e-5f

typedef __nv_bfloat16 bf16;

// ---------------------------------------------------------------------------
// Scratch (device globals: allocation-free per harness rules)
// ---------------------------------------------------------------------------
__device__ float g_attn_pair[BATCH * NUM_SLOTS];
__device__ float g_attn_macro[BATCH * NUM_SLOTS];

__device__ bf16  g_concat_hi[(size_t)BATCH * D_CAT];
__device__ bf16  g_concat_lo[(size_t)BATCH * D_CAT];
__device__ bf16  g_w1_hi[(size_t)D_CAT * D_ALL];
__device__ bf16  g_w1_lo[(size_t)D_CAT * D_ALL];
__device__ bf16  g_w2_hi[(size_t)D_ALL * D_ALL];
__device__ bf16  g_w2_lo[(size_t)D_ALL * D_ALL];
__device__ float g_h[(size_t)BATCH * D_ALL];
__device__ bf16  g_h_hi[(size_t)BATCH * D_ALL];
__device__ bf16  g_h_lo[(size_t)BATCH * D_ALL];
__device__ float g_fused[(size_t)BATCH * D_ALL];

// ---------------------------------------------------------------------------
// Small helpers
// ---------------------------------------------------------------------------
__device__ __forceinline__ uint32_t smem_u32(const void* p) {
    uint32_t a;
    asm("{ .reg .u64 t; cvta.to.shared.u64 t, %1; cvt.u32.u64 %0, t; }" : "=r"(a) : "l"(p));
    return a;
}

__device__ __forceinline__ void cp16(uint32_t dst, const void* src) {
    asm volatile("cp.async.cg.shared.global [%0], [%1], 16;" :: "r"(dst), "l"(src));
}
__device__ __forceinline__ void cp_commit() {
    asm volatile("cp.async.commit_group;" ::: "memory");
}
__device__ __forceinline__ void cp_wait2() {
    asm volatile("cp.async.wait_group 2;" ::: "memory");
}

__device__ __forceinline__ void ldsm_x4(uint32_t* r, uint32_t addr) {
    asm volatile("ldmatrix.sync.aligned.m8n8.x4.shared.b16 {%0,%1,%2,%3}, [%4];"
        : "=r"(r[0]), "=r"(r[1]), "=r"(r[2]), "=r"(r[3]) : "r"(addr));
}
__device__ __forceinline__ void ldsm_x2_trans(uint32_t* r, uint32_t addr) {
    asm volatile("ldmatrix.sync.aligned.m8n8.x2.trans.shared.b16 {%0,%1}, [%2];"
        : "=r"(r[0]), "=r"(r[1]) : "r"(addr));
}

__device__ __forceinline__ void mma_bf16(float* c, const uint32_t* a, const uint32_t* b) {
    asm volatile(
        "mma.sync.aligned.m16n8k16.row.col.f32.bf16.bf16.f32 "
        "{%0,%1,%2,%3}, {%4,%5,%6,%7}, {%8,%9}, {%0,%1,%2,%3};"
        : "+f"(c[0]), "+f"(c[1]), "+f"(c[2]), "+f"(c[3])
        : "r"(a[0]), "r"(a[1]), "r"(a[2]), "r"(a[3]), "r"(b[0]), "r"(b[1]));
}

__device__ __forceinline__ void split_hl(float v, bf16& h, bf16& l) {
    h = __float2bfloat16_rn(v);
    l = __float2bfloat16_rn(v - __bfloat162float(h));
}

// ---------------------------------------------------------------------------
// Tensor-core bf16x3 GEMM: C[M,N] = A[M,K]*B[K,N] + bias  (fp32 in/out split
// to bf16 hi/lo beforehand). 128x128 CTA tile, BK=32, 3-stage cp.async.
// ---------------------------------------------------------------------------
#define TCB_K      32
// smem stage layout (bytes): A rows padded to 40 bf16 (80B), B rows to 136 bf16 (272B)
#define OFF_AHI    0
#define OFF_ALO    10240
#define OFF_BHI    20480
#define OFF_BLO    29184
#define STAGE_B    37888
#define NSTAGE     3
#define TC_SMEM    (STAGE_B * NSTAGE)

__global__ void __launch_bounds__(256, 1)
tc_gemm_kernel(const bf16* __restrict__ Ahi, const bf16* __restrict__ Alo,
               const bf16* __restrict__ Bhi, const bf16* __restrict__ Blo,
               const float* __restrict__ bias, float* __restrict__ C,
               int M, int N, int K, int lda, int ldb, int ldc)
{
    extern __shared__ __align__(16) char sm[];
    const uint32_t smb = smem_u32(sm);

    const int tid  = threadIdx.x;
    const int wid  = tid >> 5;
    const int lane = tid & 31;
    const int wm   = wid & 1;          // m half (64 rows)
    const int wn   = wid >> 1;         // n quarter (32 cols)
    const int m0   = blockIdx.y * 128;
    const int n0   = blockIdx.x * 128;

    // per-thread staging indices
    const int arow = tid >> 2, ac = tid & 3;            // A: 128 rows x 4 chunks
    const int brow = tid >> 4, bc = tid & 15;           // B: 32(x2) rows x 16 chunks

    // ldmatrix lane-derived offsets
    const int tA = lane >> 3, rA = lane & 7;
    const int a_row_off = (tA & 1) * 8 + rA;            // 0..15 within m16
    const int a_kcol    = (tA >> 1) * 8;                // 0 or 8
    const uint32_t a_const = (uint32_t)((wm * 64 + a_row_off) * 40 + a_kcol) * 2;
    const int lB = lane & 15;
    const int b_krow = (lB >> 3) * 8 + (lB & 7);        // 0..15 within k16
    const uint32_t b_const = (uint32_t)(b_krow * 136 + wn * 32) * 2;

    float acc[4][4][4];
    #pragma unroll
    for (int i = 0; i < 4; i++)
        #pragma unroll
        for (int j = 0; j < 4; j++)
            #pragma unroll
            for (int q = 0; q < 4; q++) acc[i][j][q] = 0.f;

    const int nk = K / TCB_K;

    // -------- stage issue lambda-ish macro
    #define ISSUE_STAGE(slot, kt) do {                                            \
        uint32_t base = smb + (uint32_t)(slot) * STAGE_B;                         \
        int k0 = (kt) * TCB_K;                                                    \
        _Pragma("unroll")                                                         \
        for (int l = 0; l < 2; ++l) {                                             \
            int idx = tid + l * 256;                                              \
            int r = idx >> 2, c = idx & 3;                                        \
            const bf16* gh = Ahi + (size_t)(m0 + r) * lda + k0 + c * 8;           \
            const bf16* gl = Alo + (size_t)(m0 + r) * lda + k0 + c * 8;           \
            cp16(base + OFF_AHI + r * 80 + c * 16, gh);                           \
            cp16(base + OFF_ALO + r * 80 + c * 16, gl);                           \
        }                                                                         \
        _Pragma("unroll")                                                         \
        for (int l = 0; l < 2; ++l) {                                             \
            int idx = tid + l * 256;                                              \
            int r = idx >> 4, c = idx & 15;                                       \
            const bf16* gh = Bhi + (size_t)(k0 + r) * ldb + n0 + c * 8;           \
            const bf16* gl = Blo + (size_t)(k0 + r) * ldb + n0 + c * 8;           \
            cp16(base + OFF_BHI + r * 272 + c * 16, gh);                          \
            cp16(base + OFF_BLO + r * 272 + c * 16, gl);                          \
        }                                                                         \
    } while (0)

    // prologue: stages 0 and 1
    ISSUE_STAGE(0, 0); cp_commit();
    ISSUE_STAGE(1, 1); cp_commit();

    for (int kt = 0; kt < nk; ++kt) {
        __syncthreads();   // protect slot being refilled vs prev compute
        if (kt + 2 < nk) { ISSUE_STAGE((kt + 2) % NSTAGE, kt + 2); }
        cp_commit();       // always commit (possibly empty group)
        cp_wait2();
        __syncthreads();

        const uint32_t base = smb + (uint32_t)(kt % NSTAGE) * STAGE_B;
        const uint32_t aHb = base + OFF_AHI + a_const;
        const uint32_t aLb = base + OFF_ALO + a_const;
        const uint32_t bHb = base + OFF_BHI + b_const;
        const uint32_t bLb = base + OFF_BLO + b_const;

        #pragma unroll
        for (int kk = 0; kk < 2; ++kk) {
            uint32_t aH[4][4], aL[4][4], bH[4][2], bL[4][2];
            const uint32_t akk = (uint32_t)(kk * 16 * 2);
            const uint32_t bkk = (uint32_t)(kk * 16 * 136 * 2);
            #pragma unroll
            for (int mf = 0; mf < 4; ++mf) {
                uint32_t off = (uint32_t)(mf * 16 * 40) * 2 + akk;
                ldsm_x4(aH[mf], aHb + off);
                ldsm_x4(aL[mf], aLb + off);
            }
            #pragma unroll
            for (int nf = 0; nf < 4; ++nf) {
                uint32_t off = (uint32_t)(nf * 8) * 2 + bkk;
                ldsm_x2_trans(bH[nf], bHb + off);
                ldsm_x2_trans(bL[nf], bLb + off);
            }
            #pragma unroll
            for (int mf = 0; mf < 4; ++mf)
                #pragma unroll
                for (int nf = 0; nf < 4; ++nf) {
                    mma_bf16(acc[mf][nf], aH[mf], bH[nf]);
                    mma_bf16(acc[mf][nf], aH[mf], bL[nf]);
                    mma_bf16(acc[mf][nf], aL[mf], bH[nf]);
                }
        }
    }
    #undef ISSUE_STAGE

    // -------- epilogue
    const int g  = lane >> 2;
    const int tg = lane & 3;
    #pragma unroll
    for (int mf = 0; mf < 4; ++mf) {
        int r0 = m0 + wm * 64 + mf * 16 + g;
        #pragma unroll
        for (int nf = 0; nf < 4; ++nf) {
            int c = n0 + wn * 32 + nf * 8 + tg * 2;
            float b0 = bias[c], b1 = bias[c + 1];
            float2 v0 = make_float2(acc[mf][nf][0] + b0, acc[mf][nf][1] + b1);
            float2 v1 = make_float2(acc[mf][nf][2] + b0, acc[mf][nf][3] + b1);
            *reinterpret_cast<float2*>(C + (size_t)r0 * ldc + c) = v0;
            *reinterpret_cast<float2*>(C + (size_t)(r0 + 8) * ldc + c) = v1;
        }
    }
}

// ---------------------------------------------------------------------------
// fp32 -> bf16 hi/lo split (elementwise, vectorized)
// ---------------------------------------------------------------------------
__global__ __launch_bounds__(256) void cvt_split_kernel(
    const float4* __restrict__ x, uint2* __restrict__ hi, uint2* __restrict__ lo, int n4)
{
    int i = blockIdx.x * 256 + threadIdx.x;
    if (i >= n4) return;
    float4 v = x[i];
    bf16 h0, l0, h1, l1, h2, l2, h3, l3;
    split_hl(v.x, h0, l0); split_hl(v.y, h1, l1);
    split_hl(v.z, h2, l2); split_hl(v.w, h3, l3);
    __nv_bfloat162 ha = __halves2bfloat162(h0, h1), hb = __halves2bfloat162(h2, h3);
    __nv_bfloat162 la = __halves2bfloat162(l0, l1), lb = __halves2bfloat162(l2, l3);
    hi[i] = make_uint2(*reinterpret_cast<uint32_t*>(&ha), *reinterpret_cast<uint32_t*>(&hb));
    lo[i] = make_uint2(*reinterpret_cast<uint32_t*>(&la), *reinterpret_cast<uint32_t*>(&lb));
}

// ---------------------------------------------------------------------------
// Kernel 1: pair-query mean + scores + softmax  -> attn_pair (B,64)
// ---------------------------------------------------------------------------
__global__ __launch_bounds__(128) void attn_pair_kernel(
    const float* __restrict__ ps, const float* __restrict__ keys,
    float* __restrict__ attn)
{
    int b = blockIdx.x, tid = threadIdx.x;
    __shared__ float q[PAIR_DIM];
    __shared__ float sc[NUM_SLOTS];
    __shared__ float red[NUM_SLOTS];

    float s = 0.f;
    #pragma unroll
    for (int p = 0; p < NUM_PAIRS; p++)
        s += ps[(size_t)b * D_ALL + p * PAIR_DIM + tid];
    q[tid] = s * (1.0f / NUM_PAIRS);
    __syncthreads();

    if (tid < NUM_SLOTS) {
        float acc = 0.f;
        #pragma unroll 4
        for (int d = 0; d < PAIR_DIM; d++)
            acc = fmaf(q[d], keys[tid * PAIR_DIM + d], acc);
        sc[tid] = acc * 0.08838834764831845f;
    }
    __syncthreads();

    if (tid < NUM_SLOTS) red[tid] = sc[tid];
    __syncthreads();
    for (int o = 32; o > 0; o >>= 1) {
        if (tid < o) red[tid] = fmaxf(red[tid], red[tid + o]);
        __syncthreads();
    }
    float mx = red[0];
    __syncthreads();

    float e = 0.f;
    if (tid < NUM_SLOTS) { e = expf(sc[tid] - mx); red[tid] = e; }
    __syncthreads();
    for (int o = 32; o > 0; o >>= 1) {
        if (tid < o) red[tid] += red[tid + o];
        __syncthreads();
    }
    if (tid < NUM_SLOTS)
        attn[(size_t)b * NUM_SLOTS + tid] = e / red[0];
}

__global__ __launch_bounds__(128) void attn_macro_kernel(
    const float* __restrict__ ms, const float* __restrict__ keys,
    float* __restrict__ attn)
{
    int b = blockIdx.x, tid = threadIdx.x;
    __shared__ float q[MACRO_DIM];
    __shared__ float sc[NUM_SLOTS];
    __shared__ float red[NUM_SLOTS];

    q[tid]       = ms[(size_t)b * MACRO_DIM + tid];
    q[tid + 128] = ms[(size_t)b * MACRO_DIM + tid + 128];
    __syncthreads();

    if (tid < NUM_SLOTS) {
        float acc = 0.f;
        #pragma unroll 4
        for (int d = 0; d < MACRO_DIM; d++)
            acc = fmaf(q[d], keys[tid * MACRO_DIM + d], acc);
        sc[tid] = acc * 0.0625f;
    }
    __syncthreads();

    if (tid < NUM_SLOTS) red[tid] = sc[tid];
    __syncthreads();
    for (int o = 32; o > 0; o >>= 1) {
        if (tid < o) red[tid] = fmaxf(red[tid], red[tid + o]);
        __syncthreads();
    }
    float mx = red[0];
    __syncthreads();

    float e = 0.f;
    if (tid < NUM_SLOTS) { e = expf(sc[tid] - mx); red[tid] = e; }
    __syncthreads();
    for (int o = 32; o > 0; o >>= 1) {
        if (tid < o) red[tid] += red[tid + o];
        __syncthreads();
    }
    if (tid < NUM_SLOTS)
        attn[(size_t)b * NUM_SLOTS + tid] = e / red[0];
}

// ---------------------------------------------------------------------------
// SIMT GEMM for the small K=64 value reads; writes bf16 hi/lo output.
// ---------------------------------------------------------------------------
#define BM 128
#define BN 128
#define BKK 8
#define TM 8
#define TN 8

__global__ __launch_bounds__(256) void sgemm_bf16out_kernel(
    const float* __restrict__ A, const float* __restrict__ B,
    bf16* __restrict__ Chi, bf16* __restrict__ Clo,
    int M, int N, int K, int lda, int ldb, int ldc)
{
    __shared__ float As[BKK][BM];
    __shared__ float Bs[BKK][BN];

    int tid = threadIdx.x;
    int bx = blockIdx.x, by = blockIdx.y;
    int tx = tid & 15, ty = tid >> 4;
    int rowA = tid >> 1, colA = (tid & 1) * 4;
    int rowB = tid >> 5, colB = (tid & 31) * 4;

    const float* Ag = A + (size_t)(by * BM + rowA) * lda + colA;
    const float* Bg = B + (size_t)rowB * ldb + bx * BN + colB;

    float acc[TM][TN];
    #pragma unroll
    for (int i = 0; i < TM; i++)
        #pragma unroll
        for (int j = 0; j < TN; j++) acc[i][j] = 0.f;

    for (int k0 = 0; k0 < K; k0 += BKK) {
        float4 av = *reinterpret_cast<const float4*>(Ag + k0);
        float4 bv = *reinterpret_cast<const float4*>(Bg + (size_t)k0 * ldb);
        As[colA + 0][rowA] = av.x; As[colA + 1][rowA] = av.y;
        As[colA + 2][rowA] = av.z; As[colA + 3][rowA] = av.w;
        *reinterpret_cast<float4*>(&Bs[rowB][colB]) = bv;
        __syncthreads();
        #pragma unroll
        for (int kk = 0; kk < BKK; kk++) {
            float a[TM], bb[TN];
            #pragma unroll
            for (int i = 0; i < TM; i++) a[i] = As[kk][ty * TM + i];
            #pragma unroll
            for (int j = 0; j < TN; j++) bb[j] = Bs[kk][tx * TN + j];
            #pragma unroll
            for (int i = 0; i < TM; i++)
                #pragma unroll
                for (int j = 0; j < TN; j++)
                    acc[i][j] = fmaf(a[i], bb[j], acc[i][j]);
        }
        __syncthreads();
    }

    #pragma unroll
    for (int i = 0; i < TM; i++) {
        int r = by * BM + ty * TM + i;
        #pragma unroll
        for (int j = 0; j < TN; j++) {
            int c = bx * BN + tx * TN + j;
            bf16 h, l;
            split_hl(acc[i][j], h, l);
            Chi[(size_t)r * ldc + c] = h;
            Clo[(size_t)r * ldc + c] = l;
        }
    }
}

// ---------------------------------------------------------------------------
// LayerNorm + exact GELU over rows of length D_ALL; writes bf16 hi/lo
// ---------------------------------------------------------------------------
__global__ __launch_bounds__(256) void ln_gelu_kernel(
    const float* __restrict__ h, const float* __restrict__ g, const float* __restrict__ b,
    bf16* __restrict__ ohi, bf16* __restrict__ olo)
{
    __shared__ float row[D_ALL];
    __shared__ float red[256];
    int bi = blockIdx.x, tid = threadIdx.x;
    const float* hrow = h + (size_t)bi * D_ALL;

    float s = 0.f;
    for (int i = tid; i < D_ALL; i += 256) { float v = hrow[i]; row[i] = v; s += v; }
    red[tid] = s; __syncthreads();
    for (int o = 128; o > 0; o >>= 1) { if (tid < o) red[tid] += red[tid + o]; __syncthreads(); }
    float mu = red[0] * (1.0f / D_ALL);
    __syncthreads();

    float s2 = 0.f;
    for (int i = tid; i < D_ALL; i += 256) { float d = row[i] - mu; s2 += d * d; }
    red[tid] = s2; __syncthreads();
    for (int o = 128; o > 0; o >>= 1) { if (tid < o) red[tid] += red[tid + o]; __syncthreads(); }
    float rstd = rsqrtf(red[0] * (1.0f / D_ALL) + LN_EPS);

    for (int i = tid; i < D_ALL; i += 256) {
        float y = (row[i] - mu) * rstd * g[i] + b[i];
        float gl = 0.5f * y * (1.0f + erff(y * 0.70710678118654752f));
        bf16 hh, ll;
        split_hl(gl, hh, ll);
        ohi[(size_t)bi * D_ALL + i] = hh;
        olo[(size_t)bi * D_ALL + i] = ll;
    }
}

// ---------------------------------------------------------------------------
// per-pair Linear (K=256) + bias + LayerNorm(128) -> d_out
// ---------------------------------------------------------------------------
#define PKT 32
__global__ __launch_bounds__(256) void pair_out_kernel(
    const float* __restrict__ ps, const float* __restrict__ fused,
    const float* __restrict__ pw, const float* __restrict__ pb,
    const float* __restrict__ lng, const float* __restrict__ lnb,
    float* __restrict__ out)
{
    int p  = blockIdx.y;
    int b0 = blockIdx.x * 32;
    int tid = threadIdx.x;

    __shared__ float xs[PKT][33];
    __shared__ float ws[PKT][128];
    __shared__ float os[32][128];

    int warp = tid >> 5, lane = tid & 31;
    int ty = warp, tx = lane;

    float acc[4][4];
    #pragma unroll
    for (int i = 0; i < 4; i++)
        #pragma unroll
        for (int j = 0; j < 4; j++) acc[i][j] = 0.f;

    for (int k0 = 0; k0 < 2 * PAIR_DIM; k0 += PKT) {
        #pragma unroll
        for (int l = 0; l < 4; l++) {
            int idx = tid + l * 256;
            int r = idx >> 5, kk = idx & 31;
            int d = k0 + kk, b = b0 + r;
            float v = (d < PAIR_DIM)
                ? ps[(size_t)b * D_ALL + p * PAIR_DIM + d]
                : fused[(size_t)b * D_ALL + p * PAIR_DIM + (d - PAIR_DIM)];
            xs[kk][r] = v;
        }
        #pragma unroll
        for (int l = 0; l < 4; l++) {
            int idx = tid + l * 256;
            int kk = idx >> 5, e4 = (idx & 31) * 4;
            *reinterpret_cast<float4*>(&ws[kk][e4]) =
                *reinterpret_cast<const float4*>(&pw[((size_t)p * 256 + k0 + kk) * 128 + e4]);
        }
        __syncthreads();

        #pragma unroll
        for (int kk = 0; kk < PKT; kk++) {
            float a[4], bb[4];
            #pragma unroll
            for (int i = 0; i < 4; i++) a[i] = xs[kk][ty * 4 + i];
            #pragma unroll
            for (int j = 0; j < 4; j++) bb[j] = ws[kk][tx * 4 + j];
            #pragma unroll
            for (int i = 0; i < 4; i++)
                #pragma unroll
                for (int j = 0; j < 4; j++)
                    acc[i][j] = fmaf(a[i], bb[j], acc[i][j]);
        }
        __syncthreads();
    }

    #pragma unroll
    for (int i = 0; i < 4; i++)
        #pragma unroll
        for (int j = 0; j < 4; j++)
            os[ty * 4 + i][tx * 4 + j] = acc[i][j] + pb[p * PAIR_DIM + tx * 4 + j];
    __syncthreads();

    #pragma unroll
    for (int rr = 0; rr < 4; rr++) {
        int r = warp * 4 + rr;
        float v0 = os[r][lane], v1 = os[r][lane + 32];
        float v2 = os[r][lane + 64], v3 = os[r][lane + 96];
        float s = v0 + v1 + v2 + v3;
        #pragma unroll
        for (int o = 16; o > 0; o >>= 1) s += __shfl_xor_sync(0xffffffff, s, o);
        float mu = s * (1.0f / 128.0f);
        float d0 = v0 - mu, d1 = v1 - mu, d2 = v2 - mu, d3 = v3 - mu;
        float s2 = d0 * d0 + d1 * d1 + d2 * d2 + d3 * d3;
        #pragma unroll
        for (int o = 16; o > 0; o >>= 1) s2 += __shfl_xor_sync(0xffffffff, s2, o);
        float rstd = rsqrtf(s2 * (1.0f / 128.0f) + LN_EPS);

        int b = b0 + r;
        size_t base = (size_t)b * D_ALL + p * PAIR_DIM;
        int gi = p * PAIR_DIM;
        out[base + lane]      = d0 * rstd * lng[gi + lane]      + lnb[gi + lane];
        out[base + lane + 32] = d1 * rstd * lng[gi + lane + 32] + lnb[gi + lane + 32];
        out[base + lane + 64] = d2 * rstd * lng[gi + lane + 64] + lnb[gi + lane + 64];
        out[base + lane + 96] = d3 * rstd * lng[gi + lane + 96] + lnb[gi + lane + 96];
    }
}

// ---------------------------------------------------------------------------
// Launch
// ---------------------------------------------------------------------------
extern "C" void kernel_launch(void* const* d_in, const int* in_sizes, int n_in,
                              void* d_out, int out_size)
{
    const float* pair_states    = (const float*)d_in[0];
    const float* macro_state    = (const float*)d_in[1];
    const float* mem_pair_keys  = (const float*)d_in[2];
    const float* mem_pair_vals  = (const float*)d_in[3];
    const float* mem_macro_keys = (const float*)d_in[4];
    const float* mem_macro_vals = (const float*)d_in[5];
    const float* fusion_w1      = (const float*)d_in[6];
    const float* fusion_b1      = (const float*)d_in[7];
    const float* fusion_ln_g    = (const float*)d_in[8];
    const float* fusion_ln_b    = (const float*)d_in[9];
    const float* fusion_w2      = (const float*)d_in[10];
    const float* fusion_b2      = (const float*)d_in[11];
    const float* pair_w         = (const float*)d_in[12];
    const float* pair_b         = (const float*)d_in[13];
    const float* pair_ln_g      = (const float*)d_in[14];
    const float* pair_ln_b      = (const float*)d_in[15];
    float* out = (float*)d_out;

    float *attn_p, *attn_m, *h, *fused;
    bf16 *c_hi, *c_lo, *w1_hi, *w1_lo, *w2_hi, *w2_lo, *h_hi, *h_lo;
    cudaGetSymbolAddress((void**)&attn_p, g_attn_pair);
    cudaGetSymbolAddress((void**)&attn_m, g_attn_macro);
    cudaGetSymbolAddress((void**)&c_hi,   g_concat_hi);
    cudaGetSymbolAddress((void**)&c_lo,   g_concat_lo);
    cudaGetSymbolAddress((void**)&w1_hi,  g_w1_hi);
    cudaGetSymbolAddress((void**)&w1_lo,  g_w1_lo);
    cudaGetSymbolAddress((void**)&w2_hi,  g_w2_hi);
    cudaGetSymbolAddress((void**)&w2_lo,  g_w2_lo);
    cudaGetSymbolAddress((void**)&h,      g_h);
    cudaGetSymbolAddress((void**)&h_hi,   g_h_hi);
    cudaGetSymbolAddress((void**)&h_lo,   g_h_lo);
    cudaGetSymbolAddress((void**)&fused,  g_fused);

    cudaFuncSetAttribute(tc_gemm_kernel,
                         cudaFuncAttributeMaxDynamicSharedMemorySize, TC_SMEM);

    // 1) attention weights
    attn_pair_kernel<<<BATCH, 128>>>(pair_states, mem_pair_keys, attn_p);
    attn_macro_kernel<<<BATCH, 128>>>(macro_state, mem_macro_keys, attn_m);

    // 1b) weight splits (independent of 1)
    {
        int n4 = (D_CAT * D_ALL) / 4;
        cvt_split_kernel<<<(n4 + 255) / 256, 256>>>(
            (const float4*)fusion_w1, (uint2*)w1_hi, (uint2*)w1_lo, n4);
        n4 = (D_ALL * D_ALL) / 4;
        cvt_split_kernel<<<(n4 + 255) / 256, 256>>>(
            (const float4*)fusion_w2, (uint2*)w2_hi, (uint2*)w2_lo, n4);
    }

    // 2) memory value reads -> concat halves (bf16 hi/lo, ldc = 7168)
    sgemm_bf16out_kernel<<<dim3(D_ALL / BN, BATCH / BM), 256>>>(
        attn_p, mem_pair_vals, c_hi, c_lo,
        BATCH, D_ALL, NUM_SLOTS, NUM_SLOTS, D_ALL, D_CAT);
    sgemm_bf16out_kernel<<<dim3(D_ALL / BN, BATCH / BM), 256>>>(
        attn_m, mem_macro_vals, c_hi + D_ALL, c_lo + D_ALL,
        BATCH, D_ALL, NUM_SLOTS, NUM_SLOTS, D_ALL, D_CAT);

    // 3) fusion MLP via tensor cores (bf16x3)
    tc_gemm_kernel<<<dim3(D_ALL / 128, BATCH / 128), 256, TC_SMEM>>>(
        c_hi, c_lo, w1_hi, w1_lo, fusion_b1, h,
        BATCH, D_ALL, D_CAT, D_CAT, D_ALL, D_ALL);
    ln_gelu_kernel<<<BATCH, 256>>>(h, fusion_ln_g, fusion_ln_b, h_hi, h_lo);
    tc_gemm_kernel<<<dim3(D_ALL / 128, BATCH / 128), 256, TC_SMEM>>>(
        h_hi, h_lo, w2_hi, w2_lo, fusion_b2, fused,
        BATCH, D_ALL, D_ALL, D_ALL, D_ALL, D_ALL);

    // 4) per-pair linear + LN -> output
    pair_out_kernel<<<dim3(BATCH / 32, NUM_PAIRS), 256>>>(
        pair_states, fused, pair_w, pair_b, pair_ln_g, pair_ln_b, out);
}

// round 4
// speedup vs baseline: 3.3077x; 1.4040x over previous
#include <cuda_runtime.h>
#include <cuda_fp16.h>
#include <math.h>
#include <stdint.h>

// ---------------------------------------------------------------------------
// Problem constants
// ---------------------------------------------------------------------------
#define BATCH      4096
#define NUM_PAIRS  28
#define PAIR_DIM   128
#define MACRO_DIM  256
#define NUM_SLOTS  64
#define D_ALL      3584          // NUM_PAIRS * PAIR_DIM
#define D_CAT      7168          // 2 * D_ALL
#define LN_EPS     1e-5f

// ---------------------------------------------------------------------------
// Scratch (device globals: allocation-free per harness rules)
// ---------------------------------------------------------------------------
__device__ float g_attn_pair[BATCH * NUM_SLOTS];
__device__ float g_attn_macro[BATCH * NUM_SLOTS];

__device__ half  g_concat_hi[(size_t)BATCH * D_CAT];          // GEMM1 A (hi only)
__device__ half  g_w1_hi[(size_t)D_CAT * D_ALL];
__device__ half  g_w1_lo[(size_t)D_CAT * D_ALL];
__device__ half  g_w2_hi[(size_t)D_ALL * D_ALL];
__device__ half  g_w2_lo[(size_t)D_ALL * D_ALL];
__device__ float g_h[(size_t)BATCH * D_ALL];
__device__ half  g_h_hi[(size_t)BATCH * D_ALL];               // GEMM2 A (hi only)
__device__ float g_fused[(size_t)BATCH * D_ALL];
__device__ half  g_xcat_hi[(size_t)NUM_PAIRS * BATCH * 256];  // (p,b,256)
__device__ half  g_xcat_lo[(size_t)NUM_PAIRS * BATCH * 256];
__device__ half  g_pw_hi[(size_t)NUM_PAIRS * 256 * 128];
__device__ half  g_pw_lo[(size_t)NUM_PAIRS * 256 * 128];
__device__ float g_pair_tmp[(size_t)NUM_PAIRS * BATCH * 128]; // (p,b,128)

// ---------------------------------------------------------------------------
// Small helpers
// ---------------------------------------------------------------------------
__device__ __forceinline__ uint32_t smem_u32(const void* p) {
    uint32_t a;
    asm("{ .reg .u64 t; cvta.to.shared.u64 t, %1; cvt.u32.u64 %0, t; }" : "=r"(a) : "l"(p));
    return a;
}
__device__ __forceinline__ void cp16(uint32_t dst, const void* src) {
    asm volatile("cp.async.cg.shared.global [%0], [%1], 16;" :: "r"(dst), "l"(src));
}
__device__ __forceinline__ void cp_commit() {
    asm volatile("cp.async.commit_group;" ::: "memory");
}
__device__ __forceinline__ void cp_wait2() {
    asm volatile("cp.async.wait_group 2;" ::: "memory");
}
__device__ __forceinline__ void ldsm_x4(uint32_t* r, uint32_t addr) {
    asm volatile("ldmatrix.sync.aligned.m8n8.x4.shared.b16 {%0,%1,%2,%3}, [%4];"
        : "=r"(r[0]), "=r"(r[1]), "=r"(r[2]), "=r"(r[3]) : "r"(addr));
}
__device__ __forceinline__ void ldsm_x2_trans(uint32_t* r, uint32_t addr) {
    asm volatile("ldmatrix.sync.aligned.m8n8.x2.trans.shared.b16 {%0,%1}, [%2];"
        : "=r"(r[0]), "=r"(r[1]) : "r"(addr));
}
__device__ __forceinline__ void mma_f16(float* c, const uint32_t* a, const uint32_t* b) {
    asm volatile(
        "mma.sync.aligned.m16n8k16.row.col.f32.f16.f16.f32 "
        "{%0,%1,%2,%3}, {%4,%5,%6,%7}, {%8,%9}, {%0,%1,%2,%3};"
        : "+f"(c[0]), "+f"(c[1]), "+f"(c[2]), "+f"(c[3])
        : "r"(a[0]), "r"(a[1]), "r"(a[2]), "r"(a[3]), "r"(b[0]), "r"(b[1]));
}
__device__ __forceinline__ void split_hl(float v, half& h, half& l) {
    h = __float2half_rn(v);
    l = __float2half_rn(v - __half2float(h));
}

// ---------------------------------------------------------------------------
// Tensor-core fp16 GEMM: C[M,N] = A[M,K]*B[K,N] + bias
//   TERMS==2: D = Ahi*(Bhi+Blo)            (drops Alo*B, ~1.4e-4)
//   TERMS==3: D = Ahi*Bhi + Ahi*Blo + Alo*Bhi
// 128x128 CTA tile, BK=32, 4-stage cp.async, 1 sync/iter.
// Batched over blockIdx.z via strides.
// ---------------------------------------------------------------------------
#define TCB_K   32
#define NSTAGE  4

template<int TERMS>
__global__ void __launch_bounds__(256, 1)
tc_gemm_kernel(const half* __restrict__ Ahi, const half* __restrict__ Alo,
               const half* __restrict__ Bhi, const half* __restrict__ Blo,
               const float* __restrict__ bias, float* __restrict__ C,
               int M, int N, int K, int lda, int ldb, int ldc,
               long long sA, long long sB, long long sC, int sBias)
{
    constexpr int A_BYTES  = 10240;                    // 128 rows x 40 half
    constexpr int B_BYTES  = 8704;                     // 32 rows x 136 half
    constexpr int OFF_ALO  = A_BYTES;
    constexpr int OFF_BHI  = (TERMS == 3) ? 2 * A_BYTES : A_BYTES;
    constexpr int OFF_BLO  = OFF_BHI + B_BYTES;
    constexpr int STAGE    = OFF_BLO + B_BYTES;

    extern __shared__ __align__(16) char sm[];
    const uint32_t smb = smem_u32(sm);

    const int z = blockIdx.z;
    Ahi += (long long)z * sA;
    if (TERMS == 3) Alo += (long long)z * sA;
    Bhi += (long long)z * sB;
    Blo += (long long)z * sB;
    C   += (long long)z * sC;
    const float* biasz = bias + (long long)z * sBias;

    const int tid  = threadIdx.x;
    const int wid  = tid >> 5;
    const int lane = tid & 31;
    const int wm   = wid & 1;
    const int wn   = wid >> 1;
    const int m0   = blockIdx.y * 128;
    const int n0   = blockIdx.x * 128;

    // ldmatrix lane-derived offsets
    const int tA = lane >> 3, rA = lane & 7;
    const int a_row_off = (tA & 1) * 8 + rA;
    const int a_kcol    = (tA >> 1) * 8;
    const uint32_t a_const = (uint32_t)((wm * 64 + a_row_off) * 40 + a_kcol) * 2;
    const int lB = lane & 15;
    const int b_krow = (lB >> 3) * 8 + (lB & 7);
    const uint32_t b_const = (uint32_t)(b_krow * 136 + wn * 32) * 2;

    float acc[4][4][4];
    #pragma unroll
    for (int i = 0; i < 4; i++)
        #pragma unroll
        for (int j = 0; j < 4; j++)
            #pragma unroll
            for (int q = 0; q < 4; q++) acc[i][j][q] = 0.f;

    const int nk = K / TCB_K;

    #define ISSUE_STAGE(slot, kt) do {                                         \
        uint32_t base = smb + (uint32_t)(slot) * STAGE;                        \
        int k0 = (kt) * TCB_K;                                                 \
        _Pragma("unroll")                                                      \
        for (int l = 0; l < 2; ++l) {                                          \
            int idx = tid + l * 256;                                           \
            int r = idx >> 2, c = idx & 3;                                     \
            cp16(base + r * 80 + c * 16,                                       \
                 Ahi + (size_t)(m0 + r) * lda + k0 + c * 8);                   \
            if constexpr (TERMS == 3)                                          \
                cp16(base + OFF_ALO + r * 80 + c * 16,                         \
                     Alo + (size_t)(m0 + r) * lda + k0 + c * 8);               \
        }                                                                      \
        _Pragma("unroll")                                                      \
        for (int l = 0; l < 2; ++l) {                                          \
            int idx = tid + l * 256;                                           \
            int r = idx >> 4, c = idx & 15;                                    \
            cp16(base + OFF_BHI + r * 272 + c * 16,                            \
                 Bhi + (size_t)(k0 + r) * ldb + n0 + c * 8);                   \
            cp16(base + OFF_BLO + r * 272 + c * 16,                            \
                 Blo + (size_t)(k0 + r) * ldb + n0 + c * 8);                   \
        }                                                                      \
    } while (0)

    // prologue: issue NSTAGE-1 = 3 stages
    ISSUE_STAGE(0, 0); cp_commit();
    ISSUE_STAGE(1, 1); cp_commit();
    ISSUE_STAGE(2, 2); cp_commit();

    for (int kt = 0; kt < nk; ++kt) {
        cp_wait2();            // stage kt arrived (3 groups in flight, oldest done)
        __syncthreads();       // all warps done computing iter kt-1 (slot (kt+3)%4)
        if (kt + 3 < nk) { ISSUE_STAGE((kt + 3) & 3, kt + 3); }
        cp_commit();           // always commit (empty groups keep the count uniform)

        const uint32_t base = smb + (uint32_t)(kt & 3) * STAGE;
        const uint32_t aHb = base + a_const;
        const uint32_t aLb = base + OFF_ALO + a_const;
        const uint32_t bHb = base + OFF_BHI + b_const;
        const uint32_t bLb = base + OFF_BLO + b_const;

        #pragma unroll
        for (int kk = 0; kk < 2; ++kk) {
            uint32_t aH[4][4], aL[4][4], bH[4][2], bL[4][2];
            const uint32_t akk = (uint32_t)(kk * 16 * 2);
            const uint32_t bkk = (uint32_t)(kk * 16 * 136 * 2);
            #pragma unroll
            for (int mf = 0; mf < 4; ++mf) {
                uint32_t off = (uint32_t)(mf * 16 * 40) * 2 + akk;
                ldsm_x4(aH[mf], aHb + off);
                if constexpr (TERMS == 3) ldsm_x4(aL[mf], aLb + off);
            }
            #pragma unroll
            for (int nf = 0; nf < 4; ++nf) {
                uint32_t off = (uint32_t)(nf * 8) * 2 + bkk;
                ldsm_x2_trans(bH[nf], bHb + off);
                ldsm_x2_trans(bL[nf], bLb + off);
            }
            #pragma unroll
            for (int mf = 0; mf < 4; ++mf)
                #pragma unroll
                for (int nf = 0; nf < 4; ++nf) {
                    mma_f16(acc[mf][nf], aH[mf], bH[nf]);
                    mma_f16(acc[mf][nf], aH[mf], bL[nf]);
                    if constexpr (TERMS == 3) mma_f16(acc[mf][nf], aL[mf], bH[nf]);
                }
        }
    }
    #undef ISSUE_STAGE

    // -------- epilogue
    const int g  = lane >> 2;
    const int tg = lane & 3;
    #pragma unroll
    for (int mf = 0; mf < 4; ++mf) {
        int r0 = m0 + wm * 64 + mf * 16 + g;
        #pragma unroll
        for (int nf = 0; nf < 4; ++nf) {
            int c = n0 + wn * 32 + nf * 8 + tg * 2;
            float b0 = biasz[c], b1 = biasz[c + 1];
            float2 v0 = make_float2(acc[mf][nf][0] + b0, acc[mf][nf][1] + b1);
            float2 v1 = make_float2(acc[mf][nf][2] + b0, acc[mf][nf][3] + b1);
            *reinterpret_cast<float2*>(C + (size_t)r0 * ldc + c) = v0;
            *reinterpret_cast<float2*>(C + (size_t)(r0 + 8) * ldc + c) = v1;
        }
    }
}

// ---------------------------------------------------------------------------
// fp32 -> fp16 hi/lo split (elementwise, vectorized)
// ---------------------------------------------------------------------------
__global__ __launch_bounds__(256) void cvt_split_kernel(
    const float4* __restrict__ x, uint2* __restrict__ hi, uint2* __restrict__ lo, int n4)
{
    int i = blockIdx.x * 256 + threadIdx.x;
    if (i >= n4) return;
    float4 v = x[i];
    half h0, l0, h1, l1, h2, l2, h3, l3;
    split_hl(v.x, h0, l0); split_hl(v.y, h1, l1);
    split_hl(v.z, h2, l2); split_hl(v.w, h3, l3);
    half2 ha = __halves2half2(h0, h1), hb = __halves2half2(h2, h3);
    half2 la = __halves2half2(l0, l1), lb = __halves2half2(l2, l3);
    hi[i] = make_uint2(*reinterpret_cast<uint32_t*>(&ha), *reinterpret_cast<uint32_t*>(&hb));
    lo[i] = make_uint2(*reinterpret_cast<uint32_t*>(&la), *reinterpret_cast<uint32_t*>(&lb));
}

// ---------------------------------------------------------------------------
// attention weight kernels (unchanged)
// ---------------------------------------------------------------------------
__global__ __launch_bounds__(128) void attn_pair_kernel(
    const float* __restrict__ ps, const float* __restrict__ keys,
    float* __restrict__ attn)
{
    int b = blockIdx.x, tid = threadIdx.x;
    __shared__ float q[PAIR_DIM];
    __shared__ float sc[NUM_SLOTS];
    __shared__ float red[NUM_SLOTS];

    float s = 0.f;
    #pragma unroll
    for (int p = 0; p < NUM_PAIRS; p++)
        s += ps[(size_t)b * D_ALL + p * PAIR_DIM + tid];
    q[tid] = s * (1.0f / NUM_PAIRS);
    __syncthreads();

    if (tid < NUM_SLOTS) {
        float acc = 0.f;
        #pragma unroll 4
        for (int d = 0; d < PAIR_DIM; d++)
            acc = fmaf(q[d], keys[tid * PAIR_DIM + d], acc);
        sc[tid] = acc * 0.08838834764831845f;
    }
    __syncthreads();

    if (tid < NUM_SLOTS) red[tid] = sc[tid];
    __syncthreads();
    for (int o = 32; o > 0; o >>= 1) {
        if (tid < o) red[tid] = fmaxf(red[tid], red[tid + o]);
        __syncthreads();
    }
    float mx = red[0];
    __syncthreads();

    float e = 0.f;
    if (tid < NUM_SLOTS) { e = expf(sc[tid] - mx); red[tid] = e; }
    __syncthreads();
    for (int o = 32; o > 0; o >>= 1) {
        if (tid < o) red[tid] += red[tid + o];
        __syncthreads();
    }
    if (tid < NUM_SLOTS)
        attn[(size_t)b * NUM_SLOTS + tid] = e / red[0];
}

__global__ __launch_bounds__(128) void attn_macro_kernel(
    const float* __restrict__ ms, const float* __restrict__ keys,
    float* __restrict__ attn)
{
    int b = blockIdx.x, tid = threadIdx.x;
    __shared__ float q[MACRO_DIM];
    __shared__ float sc[NUM_SLOTS];
    __shared__ float red[NUM_SLOTS];

    q[tid]       = ms[(size_t)b * MACRO_DIM + tid];
    q[tid + 128] = ms[(size_t)b * MACRO_DIM + tid + 128];
    __syncthreads();

    if (tid < NUM_SLOTS) {
        float acc = 0.f;
        #pragma unroll 4
        for (int d = 0; d < MACRO_DIM; d++)
            acc = fmaf(q[d], keys[tid * MACRO_DIM + d], acc);
        sc[tid] = acc * 0.0625f;
    }
    __syncthreads();

    if (tid < NUM_SLOTS) red[tid] = sc[tid];
    __syncthreads();
    for (int o = 32; o > 0; o >>= 1) {
        if (tid < o) red[tid] = fmaxf(red[tid], red[tid + o]);
        __syncthreads();
    }
    float mx = red[0];
    __syncthreads();

    float e = 0.f;
    if (tid < NUM_SLOTS) { e = expf(sc[tid] - mx); red[tid] = e; }
    __syncthreads();
    for (int o = 32; o > 0; o >>= 1) {
        if (tid < o) red[tid] += red[tid + o];
        __syncthreads();
    }
    if (tid < NUM_SLOTS)
        attn[(size_t)b * NUM_SLOTS + tid] = e / red[0];
}

// ---------------------------------------------------------------------------
// SIMT GEMM for the small K=64 value reads; writes fp16 (hi only).
// ---------------------------------------------------------------------------
#define BM 128
#define BN 128
#define BKK 8
#define TM 8
#define TN 8

__global__ __launch_bounds__(256) void sgemm_halfout_kernel(
    const float* __restrict__ A, const float* __restrict__ B,
    half* __restrict__ Chi,
    int M, int N, int K, int lda, int ldb, int ldc)
{
    __shared__ float As[BKK][BM];
    __shared__ float Bs[BKK][BN];

    int tid = threadIdx.x;
    int bx = blockIdx.x, by = blockIdx.y;
    int tx = tid & 15, ty = tid >> 4;
    int rowA = tid >> 1, colA = (tid & 1) * 4;
    int rowB = tid >> 5, colB = (tid & 31) * 4;

    const float* Ag = A + (size_t)(by * BM + rowA) * lda + colA;
    const float* Bg = B + (size_t)rowB * ldb + bx * BN + colB;

    float acc[TM][TN];
    #pragma unroll
    for (int i = 0; i < TM; i++)
        #pragma unroll
        for (int j = 0; j < TN; j++) acc[i][j] = 0.f;

    for (int k0 = 0; k0 < K; k0 += BKK) {
        float4 av = *reinterpret_cast<const float4*>(Ag + k0);
        float4 bv = *reinterpret_cast<const float4*>(Bg + (size_t)k0 * ldb);
        As[colA + 0][rowA] = av.x; As[colA + 1][rowA] = av.y;
        As[colA + 2][rowA] = av.z; As[colA + 3][rowA] = av.w;
        *reinterpret_cast<float4*>(&Bs[rowB][colB]) = bv;
        __syncthreads();
        #pragma unroll
        for (int kk = 0; kk < BKK; kk++) {
            float a[TM], bb[TN];
            #pragma unroll
            for (int i = 0; i < TM; i++) a[i] = As[kk][ty * TM + i];
            #pragma unroll
            for (int j = 0; j < TN; j++) bb[j] = Bs[kk][tx * TN + j];
            #pragma unroll
            for (int i = 0; i < TM; i++)
                #pragma unroll
                for (int j = 0; j < TN; j++)
                    acc[i][j] = fmaf(a[i], bb[j], acc[i][j]);
        }
        __syncthreads();
    }

    #pragma unroll
    for (int i = 0; i < TM; i++) {
        int r = by * BM + ty * TM + i;
        #pragma unroll
        for (int j = 0; j < TN; j++) {
            int c = bx * BN + tx * TN + j;
            Chi[(size_t)r * ldc + c] = __float2half_rn(acc[i][j]);
        }
    }
}

// ---------------------------------------------------------------------------
// LayerNorm + exact GELU over rows of length D_ALL; writes fp16 hi
// ---------------------------------------------------------------------------
__global__ __launch_bounds__(256) void ln_gelu_kernel(
    const float* __restrict__ h, const float* __restrict__ g, const float* __restrict__ b,
    half* __restrict__ ohi)
{
    __shared__ float row[D_ALL];
    __shared__ float red[256];
    int bi = blockIdx.x, tid = threadIdx.x;
    const float* hrow = h + (size_t)bi * D_ALL;

    float s = 0.f;
    for (int i = tid; i < D_ALL; i += 256) { float v = hrow[i]; row[i] = v; s += v; }
    red[tid] = s; __syncthreads();
    for (int o = 128; o > 0; o >>= 1) { if (tid < o) red[tid] += red[tid + o]; __syncthreads(); }
    float mu = red[0] * (1.0f / D_ALL);
    __syncthreads();

    float s2 = 0.f;
    for (int i = tid; i < D_ALL; i += 256) { float d = row[i] - mu; s2 += d * d; }
    red[tid] = s2; __syncthreads();
    for (int o = 128; o > 0; o >>= 1) { if (tid < o) red[tid] += red[tid + o]; __syncthreads(); }
    float rstd = rsqrtf(red[0] * (1.0f / D_ALL) + LN_EPS);

    for (int i = tid; i < D_ALL; i += 256) {
        float y = (row[i] - mu) * rstd * g[i] + b[i];
        float gl = 0.5f * y * (1.0f + erff(y * 0.70710678118654752f));
        ohi[(size_t)bi * D_ALL + i] = __float2half_rn(gl);
    }
}

// ---------------------------------------------------------------------------
// Build xcat (p, b, 256) fp16 hi/lo from pair_states | fused
// ---------------------------------------------------------------------------
__global__ __launch_bounds__(256) void build_xcat_kernel(
    const float* __restrict__ ps, const float* __restrict__ fused,
    half* __restrict__ xhi, half* __restrict__ xlo)
{
    size_t i = (size_t)blockIdx.x * 256 + threadIdx.x;   // 8-elem chunk id
    int kc = (int)(i & 31);
    size_t pb = i >> 5;
    int b = (int)(pb & 4095);
    int p = (int)(pb >> 12);
    const float* src = (kc < 16)
        ? ps    + (size_t)b * D_ALL + p * 128 + kc * 8
        : fused + (size_t)b * D_ALL + p * 128 + (kc - 16) * 8;
    half h[8], l[8];
    #pragma unroll
    for (int j = 0; j < 8; j++) split_hl(src[j], h[j], l[j]);
    size_t dst = ((size_t)p * BATCH + b) * 256 + kc * 8;
    *reinterpret_cast<uint4*>(xhi + dst) = *reinterpret_cast<uint4*>(h);
    *reinterpret_cast<uint4*>(xlo + dst) = *reinterpret_cast<uint4*>(l);
}

// ---------------------------------------------------------------------------
// Per-row LayerNorm(128) over g_pair_tmp (p,b,128) -> out (b, p*128+c)
// ---------------------------------------------------------------------------
__global__ __launch_bounds__(256) void pair_ln_kernel(
    const float* __restrict__ tmp, const float* __restrict__ lng,
    const float* __restrict__ lnb, float* __restrict__ out)
{
    int row  = blockIdx.x * 8 + (threadIdx.x >> 5);  // 0..28*4096-1
    int lane = threadIdx.x & 31;
    int p = row >> 12;
    int b = row & 4095;
    const float* t = tmp + (size_t)row * 128;
    float v0 = t[lane], v1 = t[lane + 32], v2 = t[lane + 64], v3 = t[lane + 96];
    float s = v0 + v1 + v2 + v3;
    #pragma unroll
    for (int o = 16; o > 0; o >>= 1) s += __shfl_xor_sync(0xffffffff, s, o);
    float mu = s * (1.0f / 128.0f);
    float d0 = v0 - mu, d1 = v1 - mu, d2 = v2 - mu, d3 = v3 - mu;
    float s2 = d0 * d0 + d1 * d1 + d2 * d2 + d3 * d3;
    #pragma unroll
    for (int o = 16; o > 0; o >>= 1) s2 += __shfl_xor_sync(0xffffffff, s2, o);
    float rstd = rsqrtf(s2 * (1.0f / 128.0f) + LN_EPS);

    size_t base = (size_t)b * D_ALL + p * 128;
    int gi = p * 128;
    out[base + lane]      = d0 * rstd * lng[gi + lane]      + lnb[gi + lane];
    out[base + lane + 32] = d1 * rstd * lng[gi + lane + 32] + lnb[gi + lane + 32];
    out[base + lane + 64] = d2 * rstd * lng[gi + lane + 64] + lnb[gi + lane + 64];
    out[base + lane + 96] = d3 * rstd * lng[gi + lane + 96] + lnb[gi + lane + 96];
}

// ---------------------------------------------------------------------------
// Launch
// ---------------------------------------------------------------------------
extern "C" void kernel_launch(void* const* d_in, const int* in_sizes, int n_in,
                              void* d_out, int out_size)
{
    const float* pair_states    = (const float*)d_in[0];
    const float* macro_state    = (const float*)d_in[1];
    const float* mem_pair_keys  = (const float*)d_in[2];
    const float* mem_pair_vals  = (const float*)d_in[3];
    const float* mem_macro_keys = (const float*)d_in[4];
    const float* mem_macro_vals = (const float*)d_in[5];
    const float* fusion_w1      = (const float*)d_in[6];
    const float* fusion_b1      = (const float*)d_in[7];
    const float* fusion_ln_g    = (const float*)d_in[8];
    const float* fusion_ln_b    = (const float*)d_in[9];
    const float* fusion_w2      = (const float*)d_in[10];
    const float* fusion_b2      = (const float*)d_in[11];
    const float* pair_w         = (const float*)d_in[12];
    const float* pair_b         = (const float*)d_in[13];
    const float* pair_ln_g      = (const float*)d_in[14];
    const float* pair_ln_b      = (const float*)d_in[15];
    float* out = (float*)d_out;

    float *attn_p, *attn_m, *h, *fused, *pair_tmp;
    half *c_hi, *w1_hi, *w1_lo, *w2_hi, *w2_lo, *h_hi;
    half *x_hi, *x_lo, *pw_hi, *pw_lo;
    cudaGetSymbolAddress((void**)&attn_p,  g_attn_pair);
    cudaGetSymbolAddress((void**)&attn_m,  g_attn_macro);
    cudaGetSymbolAddress((void**)&c_hi,    g_concat_hi);
    cudaGetSymbolAddress((void**)&w1_hi,   g_w1_hi);
    cudaGetSymbolAddress((void**)&w1_lo,   g_w1_lo);
    cudaGetSymbolAddress((void**)&w2_hi,   g_w2_hi);
    cudaGetSymbolAddress((void**)&w2_lo,   g_w2_lo);
    cudaGetSymbolAddress((void**)&h,       g_h);
    cudaGetSymbolAddress((void**)&h_hi,    g_h_hi);
    cudaGetSymbolAddress((void**)&fused,   g_fused);
    cudaGetSymbolAddress((void**)&x_hi,    g_xcat_hi);
    cudaGetSymbolAddress((void**)&x_lo,    g_xcat_lo);
    cudaGetSymbolAddress((void**)&pw_hi,   g_pw_hi);
    cudaGetSymbolAddress((void**)&pw_lo,   g_pw_lo);
    cudaGetSymbolAddress((void**)&pair_tmp,g_pair_tmp);

    const int SMEM2 = NSTAGE * 27648;   // 110592
    const int SMEM3 = NSTAGE * 37888;   // 151552
    cudaFuncSetAttribute(tc_gemm_kernel<2>,
                         cudaFuncAttributeMaxDynamicSharedMemorySize, SMEM2);
    cudaFuncSetAttribute(tc_gemm_kernel<3>,
                         cudaFuncAttributeMaxDynamicSharedMemorySize, SMEM3);

    // 1) attention weights
    attn_pair_kernel<<<BATCH, 128>>>(pair_states, mem_pair_keys, attn_p);
    attn_macro_kernel<<<BATCH, 128>>>(macro_state, mem_macro_keys, attn_m);

    // 1b) weight splits
    {
        int n4 = (D_CAT * D_ALL) / 4;
        cvt_split_kernel<<<(n4 + 255) / 256, 256>>>(
            (const float4*)fusion_w1, (uint2*)w1_hi, (uint2*)w1_lo, n4);
        n4 = (D_ALL * D_ALL) / 4;
        cvt_split_kernel<<<(n4 + 255) / 256, 256>>>(
            (const float4*)fusion_w2, (uint2*)w2_hi, (uint2*)w2_lo, n4);
        n4 = (NUM_PAIRS * 256 * 128) / 4;
        cvt_split_kernel<<<(n4 + 255) / 256, 256>>>(
            (const float4*)pair_w, (uint2*)pw_hi, (uint2*)pw_lo, n4);
    }

    // 2) memory value reads -> concat halves (fp16 hi, ldc = 7168)
    sgemm_halfout_kernel<<<dim3(D_ALL / BN, BATCH / BM), 256>>>(
        attn_p, mem_pair_vals, c_hi,
        BATCH, D_ALL, NUM_SLOTS, NUM_SLOTS, D_ALL, D_CAT);
    sgemm_halfout_kernel<<<dim3(D_ALL / BN, BATCH / BM), 256>>>(
        attn_m, mem_macro_vals, c_hi + D_ALL,
        BATCH, D_ALL, NUM_SLOTS, NUM_SLOTS, D_ALL, D_CAT);

    // 3) fusion MLP via tensor cores (fp16 2-term)
    tc_gemm_kernel<2><<<dim3(D_ALL / 128, BATCH / 128, 1), 256, SMEM2>>>(
        c_hi, nullptr, w1_hi, w1_lo, fusion_b1, h,
        BATCH, D_ALL, D_CAT, D_CAT, D_ALL, D_ALL, 0, 0, 0, 0);
    ln_gelu_kernel<<<BATCH, 256>>>(h, fusion_ln_g, fusion_ln_b, h_hi);
    tc_gemm_kernel<2><<<dim3(D_ALL / 128, BATCH / 128, 1), 256, SMEM2>>>(
        h_hi, nullptr, w2_hi, w2_lo, fusion_b2, fused,
        BATCH, D_ALL, D_ALL, D_ALL, D_ALL, D_ALL, 0, 0, 0, 0);

    // 4) per-pair linear via batched tensor GEMM (3-term), then LN
    {
        size_t nchunk = (size_t)NUM_PAIRS * BATCH * 32;
        build_xcat_kernel<<<(unsigned)(nchunk / 256), 256>>>(pair_states, fused, x_hi, x_lo);
        tc_gemm_kernel<3><<<dim3(1, BATCH / 128, NUM_PAIRS), 256, SMEM3>>>(
            x_hi, x_lo, pw_hi, pw_lo, pair_b, pair_tmp,
            BATCH, 128, 256, 256, 128, 128,
            (long long)BATCH * 256, 256LL * 128, (long long)BATCH * 128, 128);
        pair_ln_kernel<<<(NUM_PAIRS * BATCH) / 8, 256>>>(pair_tmp, pair_ln_g, pair_ln_b, out);
    }
}

// round 5
// speedup vs baseline: 5.9572x; 1.8010x over previous
#include <cuda_runtime.h>
#include <cuda_fp16.h>
#include <math.h>
#include <stdint.h>

// ---------------------------------------------------------------------------
// Problem constants
// ---------------------------------------------------------------------------
#define BATCH      4096
#define NUM_PAIRS  28
#define PAIR_DIM   128
#define MACRO_DIM  256
#define NUM_SLOTS  64
#define D_ALL      3584          // NUM_PAIRS * PAIR_DIM
#define D_CAT      7168          // 2 * D_ALL
#define LN_EPS     1e-5f

// ---------------------------------------------------------------------------
// Scratch (device globals: allocation-free per harness rules)
// ---------------------------------------------------------------------------
__device__ float g_attn[BATCH * 128];                         // [attn_p | attn_m]
__device__ float g_V[(size_t)128 * D_ALL];                    // [Vp@W1top ; Vm@W1bot]
__device__ half  g_w2_hi[(size_t)D_ALL * D_ALL];
__device__ half  g_w2_lo[(size_t)D_ALL * D_ALL];
__device__ float g_h[(size_t)BATCH * D_ALL];
__device__ half  g_h_hi[(size_t)BATCH * D_ALL];
__device__ float g_fused[(size_t)BATCH * D_ALL];
__device__ half  g_xcat_hi[(size_t)NUM_PAIRS * BATCH * 256];  // (p,b,256)
__device__ half  g_xcat_lo[(size_t)NUM_PAIRS * BATCH * 256];
__device__ half  g_pw_hi[(size_t)NUM_PAIRS * 256 * 128];
__device__ half  g_pw_lo[(size_t)NUM_PAIRS * 256 * 128];
__device__ float g_pair_tmp[(size_t)NUM_PAIRS * BATCH * 128]; // (p,b,128)

// ---------------------------------------------------------------------------
// Small helpers
// ---------------------------------------------------------------------------
__device__ __forceinline__ uint32_t smem_u32(const void* p) {
    uint32_t a;
    asm("{ .reg .u64 t; cvta.to.shared.u64 t, %1; cvt.u32.u64 %0, t; }" : "=r"(a) : "l"(p));
    return a;
}
__device__ __forceinline__ void cp16(uint32_t dst, const void* src) {
    asm volatile("cp.async.cg.shared.global [%0], [%1], 16;" :: "r"(dst), "l"(src));
}
__device__ __forceinline__ void cp_commit() {
    asm volatile("cp.async.commit_group;" ::: "memory");
}
__device__ __forceinline__ void cp_wait2() {
    asm volatile("cp.async.wait_group 2;" ::: "memory");
}
__device__ __forceinline__ void ldsm_x4(uint32_t* r, uint32_t addr) {
    asm volatile("ldmatrix.sync.aligned.m8n8.x4.shared.b16 {%0,%1,%2,%3}, [%4];"
        : "=r"(r[0]), "=r"(r[1]), "=r"(r[2]), "=r"(r[3]) : "r"(addr));
}
__device__ __forceinline__ void ldsm_x2_trans(uint32_t* r, uint32_t addr) {
    asm volatile("ldmatrix.sync.aligned.m8n8.x2.trans.shared.b16 {%0,%1}, [%2];"
        : "=r"(r[0]), "=r"(r[1]) : "r"(addr));
}
__device__ __forceinline__ void mma_f16(float* c, const uint32_t* a, const uint32_t* b) {
    asm volatile(
        "mma.sync.aligned.m16n8k16.row.col.f32.f16.f16.f32 "
        "{%0,%1,%2,%3}, {%4,%5,%6,%7}, {%8,%9}, {%0,%1,%2,%3};"
        : "+f"(c[0]), "+f"(c[1]), "+f"(c[2]), "+f"(c[3])
        : "r"(a[0]), "r"(a[1]), "r"(a[2]), "r"(a[3]), "r"(b[0]), "r"(b[1]));
}
__device__ __forceinline__ void split_hl(float v, half& h, half& l) {
    h = __float2half_rn(v);
    l = __float2half_rn(v - __half2float(h));
}

// ---------------------------------------------------------------------------
// Tensor-core fp16 GEMM: C[M,N] = A[M,K]*B[K,N] + bias
//   TERMS==2: D = Ahi*(Bhi+Blo)
//   TERMS==3: D = Ahi*Bhi + Ahi*Blo + Alo*Bhi
// 128x128 CTA tile, BK=32, 4-stage cp.async, batched over blockIdx.z.
// ---------------------------------------------------------------------------
#define TCB_K   32
#define NSTAGE  4

template<int TERMS>
__global__ void __launch_bounds__(256, 1)
tc_gemm_kernel(const half* __restrict__ Ahi, const half* __restrict__ Alo,
               const half* __restrict__ Bhi, const half* __restrict__ Blo,
               const float* __restrict__ bias, float* __restrict__ C,
               int M, int N, int K, int lda, int ldb, int ldc,
               long long sA, long long sB, long long sC, int sBias)
{
    constexpr int A_BYTES  = 10240;                    // 128 rows x 40 half
    constexpr int B_BYTES  = 8704;                     // 32 rows x 136 half
    constexpr int OFF_ALO  = A_BYTES;
    constexpr int OFF_BHI  = (TERMS == 3) ? 2 * A_BYTES : A_BYTES;
    constexpr int OFF_BLO  = OFF_BHI + B_BYTES;
    constexpr int STAGE    = OFF_BLO + B_BYTES;

    extern __shared__ __align__(16) char sm[];
    const uint32_t smb = smem_u32(sm);

    const int z = blockIdx.z;
    Ahi += (long long)z * sA;
    if (TERMS == 3) Alo += (long long)z * sA;
    Bhi += (long long)z * sB;
    Blo += (long long)z * sB;
    C   += (long long)z * sC;
    const float* biasz = bias + (long long)z * sBias;

    const int tid  = threadIdx.x;
    const int wid  = tid >> 5;
    const int lane = tid & 31;
    const int wm   = wid & 1;
    const int wn   = wid >> 1;
    const int m0   = blockIdx.y * 128;
    const int n0   = blockIdx.x * 128;

    const int tA = lane >> 3, rA = lane & 7;
    const int a_row_off = (tA & 1) * 8 + rA;
    const int a_kcol    = (tA >> 1) * 8;
    const uint32_t a_const = (uint32_t)((wm * 64 + a_row_off) * 40 + a_kcol) * 2;
    const int lB = lane & 15;
    const int b_krow = (lB >> 3) * 8 + (lB & 7);
    const uint32_t b_const = (uint32_t)(b_krow * 136 + wn * 32) * 2;

    float acc[4][4][4];
    #pragma unroll
    for (int i = 0; i < 4; i++)
        #pragma unroll
        for (int j = 0; j < 4; j++)
            #pragma unroll
            for (int q = 0; q < 4; q++) acc[i][j][q] = 0.f;

    const int nk = K / TCB_K;

    #define ISSUE_STAGE(slot, kt) do {                                         \
        uint32_t base = smb + (uint32_t)(slot) * STAGE;                        \
        int k0 = (kt) * TCB_K;                                                 \
        _Pragma("unroll")                                                      \
        for (int l = 0; l < 2; ++l) {                                          \
            int idx = tid + l * 256;                                           \
            int r = idx >> 2, c = idx & 3;                                     \
            cp16(base + r * 80 + c * 16,                                       \
                 Ahi + (size_t)(m0 + r) * lda + k0 + c * 8);                   \
            if constexpr (TERMS == 3)                                          \
                cp16(base + OFF_ALO + r * 80 + c * 16,                         \
                     Alo + (size_t)(m0 + r) * lda + k0 + c * 8);               \
        }                                                                      \
        _Pragma("unroll")                                                      \
        for (int l = 0; l < 2; ++l) {                                          \
            int idx = tid + l * 256;                                           \
            int r = idx >> 4, c = idx & 15;                                    \
            cp16(base + OFF_BHI + r * 272 + c * 16,                            \
                 Bhi + (size_t)(k0 + r) * ldb + n0 + c * 8);                   \
            cp16(base + OFF_BLO + r * 272 + c * 16,                            \
                 Blo + (size_t)(k0 + r) * ldb + n0 + c * 8);                   \
        }                                                                      \
    } while (0)

    ISSUE_STAGE(0, 0); cp_commit();
    ISSUE_STAGE(1, 1); cp_commit();
    ISSUE_STAGE(2, 2); cp_commit();

    for (int kt = 0; kt < nk; ++kt) {
        cp_wait2();
        __syncthreads();
        if (kt + 3 < nk) { ISSUE_STAGE((kt + 3) & 3, kt + 3); }
        cp_commit();

        const uint32_t base = smb + (uint32_t)(kt & 3) * STAGE;
        const uint32_t aHb = base + a_const;
        const uint32_t aLb = base + OFF_ALO + a_const;
        const uint32_t bHb = base + OFF_BHI + b_const;
        const uint32_t bLb = base + OFF_BLO + b_const;

        #pragma unroll
        for (int kk = 0; kk < 2; ++kk) {
            uint32_t aH[4][4], aL[4][4], bH[4][2], bL[4][2];
            const uint32_t akk = (uint32_t)(kk * 16 * 2);
            const uint32_t bkk = (uint32_t)(kk * 16 * 136 * 2);
            #pragma unroll
            for (int mf = 0; mf < 4; ++mf) {
                uint32_t off = (uint32_t)(mf * 16 * 40) * 2 + akk;
                ldsm_x4(aH[mf], aHb + off);
                if constexpr (TERMS == 3) ldsm_x4(aL[mf], aLb + off);
            }
            #pragma unroll
            for (int nf = 0; nf < 4; ++nf) {
                uint32_t off = (uint32_t)(nf * 8) * 2 + bkk;
                ldsm_x2_trans(bH[nf], bHb + off);
                ldsm_x2_trans(bL[nf], bLb + off);
            }
            #pragma unroll
            for (int mf = 0; mf < 4; ++mf)
                #pragma unroll
                for (int nf = 0; nf < 4; ++nf) {
                    mma_f16(acc[mf][nf], aH[mf], bH[nf]);
                    mma_f16(acc[mf][nf], aH[mf], bL[nf]);
                    if constexpr (TERMS == 3) mma_f16(acc[mf][nf], aL[mf], bH[nf]);
                }
        }
    }
    #undef ISSUE_STAGE

    const int g  = lane >> 2;
    const int tg = lane & 3;
    #pragma unroll
    for (int mf = 0; mf < 4; ++mf) {
        int r0 = m0 + wm * 64 + mf * 16 + g;
        #pragma unroll
        for (int nf = 0; nf < 4; ++nf) {
            int c = n0 + wn * 32 + nf * 8 + tg * 2;
            float b0 = biasz[c], b1 = biasz[c + 1];
            float2 v0 = make_float2(acc[mf][nf][0] + b0, acc[mf][nf][1] + b1);
            float2 v1 = make_float2(acc[mf][nf][2] + b0, acc[mf][nf][3] + b1);
            *reinterpret_cast<float2*>(C + (size_t)r0 * ldc + c) = v0;
            *reinterpret_cast<float2*>(C + (size_t)(r0 + 8) * ldc + c) = v1;
        }
    }
}

// ---------------------------------------------------------------------------
// fp32 -> fp16 hi/lo split (elementwise, vectorized)
// ---------------------------------------------------------------------------
__global__ __launch_bounds__(256) void cvt_split_kernel(
    const float4* __restrict__ x, uint2* __restrict__ hi, uint2* __restrict__ lo, int n4)
{
    int i = blockIdx.x * 256 + threadIdx.x;
    if (i >= n4) return;
    float4 v = x[i];
    half h0, l0, h1, l1, h2, l2, h3, l3;
    split_hl(v.x, h0, l0); split_hl(v.y, h1, l1);
    split_hl(v.z, h2, l2); split_hl(v.w, h3, l3);
    half2 ha = __halves2half2(h0, h1), hb = __halves2half2(h2, h3);
    half2 la = __halves2half2(l0, l1), lb = __halves2half2(l2, l3);
    hi[i] = make_uint2(*reinterpret_cast<uint32_t*>(&ha), *reinterpret_cast<uint32_t*>(&hb));
    lo[i] = make_uint2(*reinterpret_cast<uint32_t*>(&la), *reinterpret_cast<uint32_t*>(&lb));
}

// ---------------------------------------------------------------------------
// attention weight kernels -> g_attn (B, 128): [pair | macro]
// ---------------------------------------------------------------------------
__global__ __launch_bounds__(128) void attn_pair_kernel(
    const float* __restrict__ ps, const float* __restrict__ keys,
    float* __restrict__ attn)          // stride 128, cols [0,64)
{
    int b = blockIdx.x, tid = threadIdx.x;
    __shared__ float q[PAIR_DIM];
    __shared__ float sc[NUM_SLOTS];
    __shared__ float red[NUM_SLOTS];

    float s = 0.f;
    #pragma unroll
    for (int p = 0; p < NUM_PAIRS; p++)
        s += ps[(size_t)b * D_ALL + p * PAIR_DIM + tid];
    q[tid] = s * (1.0f / NUM_PAIRS);
    __syncthreads();

    if (tid < NUM_SLOTS) {
        float acc = 0.f;
        #pragma unroll 4
        for (int d = 0; d < PAIR_DIM; d++)
            acc = fmaf(q[d], keys[tid * PAIR_DIM + d], acc);
        sc[tid] = acc * 0.08838834764831845f;
    }
    __syncthreads();

    if (tid < NUM_SLOTS) red[tid] = sc[tid];
    __syncthreads();
    for (int o = 32; o > 0; o >>= 1) {
        if (tid < o) red[tid] = fmaxf(red[tid], red[tid + o]);
        __syncthreads();
    }
    float mx = red[0];
    __syncthreads();

    float e = 0.f;
    if (tid < NUM_SLOTS) { e = expf(sc[tid] - mx); red[tid] = e; }
    __syncthreads();
    for (int o = 32; o > 0; o >>= 1) {
        if (tid < o) red[tid] += red[tid + o];
        __syncthreads();
    }
    if (tid < NUM_SLOTS)
        attn[(size_t)b * 128 + tid] = e / red[0];
}

__global__ __launch_bounds__(128) void attn_macro_kernel(
    const float* __restrict__ ms, const float* __restrict__ keys,
    float* __restrict__ attn)          // stride 128, cols [64,128)
{
    int b = blockIdx.x, tid = threadIdx.x;
    __shared__ float q[MACRO_DIM];
    __shared__ float sc[NUM_SLOTS];
    __shared__ float red[NUM_SLOTS];

    q[tid]       = ms[(size_t)b * MACRO_DIM + tid];
    q[tid + 128] = ms[(size_t)b * MACRO_DIM + tid + 128];
    __syncthreads();

    if (tid < NUM_SLOTS) {
        float acc = 0.f;
        #pragma unroll 4
        for (int d = 0; d < MACRO_DIM; d++)
            acc = fmaf(q[d], keys[tid * MACRO_DIM + d], acc);
        sc[tid] = acc * 0.0625f;
    }
    __syncthreads();

    if (tid < NUM_SLOTS) red[tid] = sc[tid];
    __syncthreads();
    for (int o = 32; o > 0; o >>= 1) {
        if (tid < o) red[tid] = fmaxf(red[tid], red[tid + o]);
        __syncthreads();
    }
    float mx = red[0];
    __syncthreads();

    float e = 0.f;
    if (tid < NUM_SLOTS) { e = expf(sc[tid] - mx); red[tid] = e; }
    __syncthreads();
    for (int o = 32; o > 0; o >>= 1) {
        if (tid < o) red[tid] += red[tid + o];
        __syncthreads();
    }
    if (tid < NUM_SLOTS)
        attn[(size_t)b * 128 + 64 + tid] = e / red[0];
}

// ---------------------------------------------------------------------------
// Zero kernel (for g_V before atomic fold)
// ---------------------------------------------------------------------------
__global__ __launch_bounds__(256) void zero_kernel(float* __restrict__ p, int n)
{
    int i = blockIdx.x * 256 + threadIdx.x;
    if (i < n) p[i] = 0.f;
}

// ---------------------------------------------------------------------------
// Fold kernel: V[z*64 + m, n] += sum_k vals_z[m, k] * W1[z*3584 + k, n]
// Split-K via blockIdx.y (atomics). Tile: 64(M) x 128(N), BK=8.
// ---------------------------------------------------------------------------
#define FK_KS  8
#define FK_KCH (D_ALL / FK_KS)   // 448

__global__ __launch_bounds__(256) void fold_kernel(
    const float* __restrict__ vals_p, const float* __restrict__ vals_m,
    const float* __restrict__ w1, float* __restrict__ V)
{
    const int nb = blockIdx.x;           // n tile
    const int ks = blockIdx.y;           // k chunk
    const int z  = blockIdx.z;           // 0=pair, 1=macro
    const float* vals = z ? vals_m : vals_p;
    const float* W    = w1 + (size_t)z * D_ALL * D_ALL;
    float* Vout       = V  + (size_t)z * 64 * D_ALL;

    __shared__ float As[8][65];
    __shared__ float Bs[8][128];

    const int tid = threadIdx.x;
    const int tx = tid & 15;             // n group (8 wide)
    const int ty = tid >> 4;             // m group (4 tall)
    const int n0 = nb * 128;

    float acc[4][8];
    #pragma unroll
    for (int i = 0; i < 4; i++)
        #pragma unroll
        for (int j = 0; j < 8; j++) acc[i][j] = 0.f;

    const int kb = ks * FK_KCH;
    for (int k0 = kb; k0 < kb + FK_KCH; k0 += 8) {
        {   // A: 64 rows x 8 k, 2 floats/thread
            int m = tid >> 2;
            int kk = (tid & 3) * 2;
            float2 v = *reinterpret_cast<const float2*>(
                vals + (size_t)m * D_ALL + k0 + kk);
            As[kk][m] = v.x;
            As[kk + 1][m] = v.y;
        }
        {   // B: 8 rows x 128, 1 float4/thread
            int r = tid >> 5, c = (tid & 31) * 4;
            *reinterpret_cast<float4*>(&Bs[r][c]) =
                *reinterpret_cast<const float4*>(W + (size_t)(k0 + r) * D_ALL + n0 + c);
        }
        __syncthreads();

        #pragma unroll
        for (int kk = 0; kk < 8; kk++) {
            float a[4], b[8];
            #pragma unroll
            for (int i = 0; i < 4; i++) a[i] = As[kk][ty * 4 + i];
            #pragma unroll
            for (int j = 0; j < 8; j++) b[j] = Bs[kk][tx * 8 + j];
            #pragma unroll
            for (int i = 0; i < 4; i++)
                #pragma unroll
                for (int j = 0; j < 8; j++)
                    acc[i][j] = fmaf(a[i], b[j], acc[i][j]);
        }
        __syncthreads();
    }

    #pragma unroll
    for (int i = 0; i < 4; i++) {
        int m = ty * 4 + i;
        #pragma unroll
        for (int j = 0; j < 8; j++)
            atomicAdd(Vout + (size_t)m * D_ALL + n0 + tx * 8 + j, acc[i][j]);
    }
}

// ---------------------------------------------------------------------------
// fp32 SIMT GEMM with bias (h = attn @ V + b1): M=4096, N=3584, K=128
// 128x128 tile, BK=8, 8x8 micro.
// ---------------------------------------------------------------------------
#define BM 128
#define BN 128
#define BKK 8
#define TM 8
#define TN 8

__global__ __launch_bounds__(256) void sgemm_kernel(
    const float* __restrict__ A, const float* __restrict__ B,
    const float* __restrict__ bias, float* __restrict__ C,
    int M, int N, int K, int lda, int ldb, int ldc)
{
    __shared__ float As[BKK][BM];
    __shared__ float Bs[BKK][BN];

    int tid = threadIdx.x;
    int bx = blockIdx.x, by = blockIdx.y;
    int tx = tid & 15, ty = tid >> 4;
    int rowA = tid >> 1, colA = (tid & 1) * 4;
    int rowB = tid >> 5, colB = (tid & 31) * 4;

    const float* Ag = A + (size_t)(by * BM + rowA) * lda + colA;
    const float* Bg = B + (size_t)rowB * ldb + bx * BN + colB;

    float acc[TM][TN];
    #pragma unroll
    for (int i = 0; i < TM; i++)
        #pragma unroll
        for (int j = 0; j < TN; j++) acc[i][j] = 0.f;

    for (int k0 = 0; k0 < K; k0 += BKK) {
        float4 av = *reinterpret_cast<const float4*>(Ag + k0);
        float4 bv = *reinterpret_cast<const float4*>(Bg + (size_t)k0 * ldb);
        As[colA + 0][rowA] = av.x; As[colA + 1][rowA] = av.y;
        As[colA + 2][rowA] = av.z; As[colA + 3][rowA] = av.w;
        *reinterpret_cast<float4*>(&Bs[rowB][colB]) = bv;
        __syncthreads();
        #pragma unroll
        for (int kk = 0; kk < BKK; kk++) {
            float a[TM], bb[TN];
            #pragma unroll
            for (int i = 0; i < TM; i++) a[i] = As[kk][ty * TM + i];
            #pragma unroll
            for (int j = 0; j < TN; j++) bb[j] = Bs[kk][tx * TN + j];
            #pragma unroll
            for (int i = 0; i < TM; i++)
                #pragma unroll
                for (int j = 0; j < TN; j++)
                    acc[i][j] = fmaf(a[i], bb[j], acc[i][j]);
        }
        __syncthreads();
    }

    #pragma unroll
    for (int i = 0; i < TM; i++) {
        int r = by * BM + ty * TM + i;
        #pragma unroll
        for (int j = 0; j < TN; j++) {
            int c = bx * BN + tx * TN + j;
            C[(size_t)r * ldc + c] = acc[i][j] + bias[c];
        }
    }
}

// ---------------------------------------------------------------------------
// LayerNorm + exact GELU over rows of length D_ALL; writes fp16 hi
// ---------------------------------------------------------------------------
__global__ __launch_bounds__(256) void ln_gelu_kernel(
    const float* __restrict__ h, const float* __restrict__ g, const float* __restrict__ b,
    half* __restrict__ ohi)
{
    __shared__ float row[D_ALL];
    __shared__ float red[256];
    int bi = blockIdx.x, tid = threadIdx.x;
    const float* hrow = h + (size_t)bi * D_ALL;

    float s = 0.f;
    for (int i = tid; i < D_ALL; i += 256) { float v = hrow[i]; row[i] = v; s += v; }
    red[tid] = s; __syncthreads();
    for (int o = 128; o > 0; o >>= 1) { if (tid < o) red[tid] += red[tid + o]; __syncthreads(); }
    float mu = red[0] * (1.0f / D_ALL);
    __syncthreads();

    float s2 = 0.f;
    for (int i = tid; i < D_ALL; i += 256) { float d = row[i] - mu; s2 += d * d; }
    red[tid] = s2; __syncthreads();
    for (int o = 128; o > 0; o >>= 1) { if (tid < o) red[tid] += red[tid + o]; __syncthreads(); }
    float rstd = rsqrtf(red[0] * (1.0f / D_ALL) + LN_EPS);

    for (int i = tid; i < D_ALL; i += 256) {
        float y = (row[i] - mu) * rstd * g[i] + b[i];
        float gl = 0.5f * y * (1.0f + erff(y * 0.70710678118654752f));
        ohi[(size_t)bi * D_ALL + i] = __float2half_rn(gl);
    }
}

// ---------------------------------------------------------------------------
// Build xcat (p, b, 256) fp16 hi/lo from pair_states | fused
// ---------------------------------------------------------------------------
__global__ __launch_bounds__(256) void build_xcat_kernel(
    const float* __restrict__ ps, const float* __restrict__ fused,
    half* __restrict__ xhi, half* __restrict__ xlo)
{
    size_t i = (size_t)blockIdx.x * 256 + threadIdx.x;   // 8-elem chunk id
    int kc = (int)(i & 31);
    size_t pb = i >> 5;
    int b = (int)(pb & 4095);
    int p = (int)(pb >> 12);
    const float* src = (kc < 16)
        ? ps    + (size_t)b * D_ALL + p * 128 + kc * 8
        : fused + (size_t)b * D_ALL + p * 128 + (kc - 16) * 8;
    half h[8], l[8];
    #pragma unroll
    for (int j = 0; j < 8; j++) split_hl(src[j], h[j], l[j]);
    size_t dst = ((size_t)p * BATCH + b) * 256 + kc * 8;
    *reinterpret_cast<uint4*>(xhi + dst) = *reinterpret_cast<uint4*>(h);
    *reinterpret_cast<uint4*>(xlo + dst) = *reinterpret_cast<uint4*>(l);
}

// ---------------------------------------------------------------------------
// Per-row LayerNorm(128) over g_pair_tmp (p,b,128) -> out (b, p*128+c)
// ---------------------------------------------------------------------------
__global__ __launch_bounds__(256) void pair_ln_kernel(
    const float* __restrict__ tmp, const float* __restrict__ lng,
    const float* __restrict__ lnb, float* __restrict__ out)
{
    int row  = blockIdx.x * 8 + (threadIdx.x >> 5);
    int lane = threadIdx.x & 31;
    int p = row >> 12;
    int b = row & 4095;
    const float* t = tmp + (size_t)row * 128;
    float v0 = t[lane], v1 = t[lane + 32], v2 = t[lane + 64], v3 = t[lane + 96];
    float s = v0 + v1 + v2 + v3;
    #pragma unroll
    for (int o = 16; o > 0; o >>= 1) s += __shfl_xor_sync(0xffffffff, s, o);
    float mu = s * (1.0f / 128.0f);
    float d0 = v0 - mu, d1 = v1 - mu, d2 = v2 - mu, d3 = v3 - mu;
    float s2 = d0 * d0 + d1 * d1 + d2 * d2 + d3 * d3;
    #pragma unroll
    for (int o = 16; o > 0; o >>= 1) s2 += __shfl_xor_sync(0xffffffff, s2, o);
    float rstd = rsqrtf(s2 * (1.0f / 128.0f) + LN_EPS);

    size_t base = (size_t)b * D_ALL + p * 128;
    int gi = p * 128;
    out[base + lane]      = d0 * rstd * lng[gi + lane]      + lnb[gi + lane];
    out[base + lane + 32] = d1 * rstd * lng[gi + lane + 32] + lnb[gi + lane + 32];
    out[base + lane + 64] = d2 * rstd * lng[gi + lane + 64] + lnb[gi + lane + 64];
    out[base + lane + 96] = d3 * rstd * lng[gi + lane + 96] + lnb[gi + lane + 96];
}

// ---------------------------------------------------------------------------
// Launch
// ---------------------------------------------------------------------------
extern "C" void kernel_launch(void* const* d_in, const int* in_sizes, int n_in,
                              void* d_out, int out_size)
{
    const float* pair_states    = (const float*)d_in[0];
    const float* macro_state    = (const float*)d_in[1];
    const float* mem_pair_keys  = (const float*)d_in[2];
    const float* mem_pair_vals  = (const float*)d_in[3];
    const float* mem_macro_keys = (const float*)d_in[4];
    const float* mem_macro_vals = (const float*)d_in[5];
    const float* fusion_w1      = (const float*)d_in[6];
    const float* fusion_b1      = (const float*)d_in[7];
    const float* fusion_ln_g    = (const float*)d_in[8];
    const float* fusion_ln_b    = (const float*)d_in[9];
    const float* fusion_w2      = (const float*)d_in[10];
    const float* fusion_b2      = (const float*)d_in[11];
    const float* pair_w         = (const float*)d_in[12];
    const float* pair_b         = (const float*)d_in[13];
    const float* pair_ln_g      = (const float*)d_in[14];
    const float* pair_ln_b      = (const float*)d_in[15];
    float* out = (float*)d_out;

    float *attn, *V, *h, *fused, *pair_tmp;
    half *w2_hi, *w2_lo, *h_hi, *x_hi, *x_lo, *pw_hi, *pw_lo;
    cudaGetSymbolAddress((void**)&attn,    g_attn);
    cudaGetSymbolAddress((void**)&V,       g_V);
    cudaGetSymbolAddress((void**)&w2_hi,   g_w2_hi);
    cudaGetSymbolAddress((void**)&w2_lo,   g_w2_lo);
    cudaGetSymbolAddress((void**)&h,       g_h);
    cudaGetSymbolAddress((void**)&h_hi,    g_h_hi);
    cudaGetSymbolAddress((void**)&fused,   g_fused);
    cudaGetSymbolAddress((void**)&x_hi,    g_xcat_hi);
    cudaGetSymbolAddress((void**)&x_lo,    g_xcat_lo);
    cudaGetSymbolAddress((void**)&pw_hi,   g_pw_hi);
    cudaGetSymbolAddress((void**)&pw_lo,   g_pw_lo);
    cudaGetSymbolAddress((void**)&pair_tmp,g_pair_tmp);

    const int SMEM2 = NSTAGE * 27648;   // 110592
    const int SMEM3 = NSTAGE * 37888;   // 151552
    cudaFuncSetAttribute(tc_gemm_kernel<2>,
                         cudaFuncAttributeMaxDynamicSharedMemorySize, SMEM2);
    cudaFuncSetAttribute(tc_gemm_kernel<3>,
                         cudaFuncAttributeMaxDynamicSharedMemorySize, SMEM3);

    // 1) attention weights -> g_attn (B, 128)
    attn_pair_kernel<<<BATCH, 128>>>(pair_states, mem_pair_keys, attn);
    attn_macro_kernel<<<BATCH, 128>>>(macro_state, mem_macro_keys, attn);

    // 2) fold: V = [vals_p @ W1top ; vals_m @ W1bot]  (128 x 3584 fp32)
    zero_kernel<<<(128 * D_ALL + 255) / 256, 256>>>(V, 128 * D_ALL);
    fold_kernel<<<dim3(D_ALL / 128, FK_KS, 2), 256>>>(
        mem_pair_vals, mem_macro_vals, fusion_w1, V);

    // 2b) weight splits (w2, pair_w)
    {
        int n4 = (D_ALL * D_ALL) / 4;
        cvt_split_kernel<<<(n4 + 255) / 256, 256>>>(
            (const float4*)fusion_w2, (uint2*)w2_hi, (uint2*)w2_lo, n4);
        n4 = (NUM_PAIRS * 256 * 128) / 4;
        cvt_split_kernel<<<(n4 + 255) / 256, 256>>>(
            (const float4*)pair_w, (uint2*)pw_hi, (uint2*)pw_lo, n4);
    }

    // 3) h = attn @ V + b1  (fp32 SIMT, K=128)
    sgemm_kernel<<<dim3(D_ALL / BN, BATCH / BM), 256>>>(
        attn, V, fusion_b1, h,
        BATCH, D_ALL, 128, 128, D_ALL, D_ALL);

    // 4) LN + GELU -> h_hi; GEMM2 via tensor cores (fp16 2-term)
    ln_gelu_kernel<<<BATCH, 256>>>(h, fusion_ln_g, fusion_ln_b, h_hi);
    tc_gemm_kernel<2><<<dim3(D_ALL / 128, BATCH / 128, 1), 256, SMEM2>>>(
        h_hi, nullptr, w2_hi, w2_lo, fusion_b2, fused,
        BATCH, D_ALL, D_ALL, D_ALL, D_ALL, D_ALL, 0, 0, 0, 0);

    // 5) per-pair linear via batched tensor GEMM (3-term), then LN
    {
        size_t nchunk = (size_t)NUM_PAIRS * BATCH * 32;
        build_xcat_kernel<<<(unsigned)(nchunk / 256), 256>>>(pair_states, fused, x_hi, x_lo);
        tc_gemm_kernel<3><<<dim3(1, BATCH / 128, NUM_PAIRS), 256, SMEM3>>>(
            x_hi, x_lo, pw_hi, pw_lo, pair_b, pair_tmp,
            BATCH, 128, 256, 256, 128, 128,
            (long long)BATCH * 256, 256LL * 128, (long long)BATCH * 128, 128);
        pair_ln_kernel<<<(NUM_PAIRS * BATCH) / 8, 256>>>(pair_tmp, pair_ln_g, pair_ln_b, out);
    }
}

// round 7
// speedup vs baseline: 7.1619x; 1.2022x over previous
#include <cuda_runtime.h>
#include <cuda_fp16.h>
#include <math.h>
#include <stdint.h>

// ---------------------------------------------------------------------------
// Problem constants
// ---------------------------------------------------------------------------
#define BATCH      4096
#define NUM_PAIRS  28
#define PAIR_DIM   128
#define MACRO_DIM  256
#define NUM_SLOTS  64
#define D_ALL      3584          // NUM_PAIRS * PAIR_DIM
#define D_CAT      7168          // 2 * D_ALL
#define LN_EPS     1e-5f

// ---------------------------------------------------------------------------
// Scratch (device globals: allocation-free per harness rules)
// ---------------------------------------------------------------------------
__device__ half  g_attn_hi[BATCH * 128];                      // [attn_p | attn_m]
__device__ half  g_attn_lo[BATCH * 128];
__device__ float g_V[(size_t)128 * D_ALL];                    // [Vp@W1top ; Vm@W1bot]
__device__ half  g_V_hi[(size_t)128 * D_ALL];
__device__ half  g_V_lo[(size_t)128 * D_ALL];
__device__ half  g_w2_hi[(size_t)D_ALL * D_ALL];
__device__ half  g_w2_lo[(size_t)D_ALL * D_ALL];
__device__ float g_h[(size_t)BATCH * D_ALL];
__device__ half  g_h_hi[(size_t)BATCH * D_ALL];
__device__ float g_fused[(size_t)BATCH * D_ALL];
__device__ half  g_xcat_hi[(size_t)NUM_PAIRS * BATCH * 256];  // (p,b,256)
__device__ half  g_xcat_lo[(size_t)NUM_PAIRS * BATCH * 256];
__device__ half  g_pw_hi[(size_t)NUM_PAIRS * 256 * 128];
__device__ half  g_pw_lo[(size_t)NUM_PAIRS * 256 * 128];

// ---------------------------------------------------------------------------
// Small helpers
// ---------------------------------------------------------------------------
__device__ __forceinline__ uint32_t smem_u32(const void* p) {
    uint32_t a;
    asm("{ .reg .u64 t; cvta.to.shared.u64 t, %1; cvt.u32.u64 %0, t; }" : "=r"(a) : "l"(p));
    return a;
}
__device__ __forceinline__ void cp16(uint32_t dst, const void* src) {
    asm volatile("cp.async.cg.shared.global [%0], [%1], 16;" :: "r"(dst), "l"(src));
}
__device__ __forceinline__ void cp_commit() {
    asm volatile("cp.async.commit_group;" ::: "memory");
}
__device__ __forceinline__ void cp_wait0() {
    asm volatile("cp.async.wait_group 0;" ::: "memory");
}
__device__ __forceinline__ void cp_wait1() {
    asm volatile("cp.async.wait_group 1;" ::: "memory");
}
__device__ __forceinline__ void ldsm_x4(uint32_t* r, uint32_t addr) {
    asm volatile("ldmatrix.sync.aligned.m8n8.x4.shared.b16 {%0,%1,%2,%3}, [%4];"
        : "=r"(r[0]), "=r"(r[1]), "=r"(r[2]), "=r"(r[3]) : "r"(addr));
}
__device__ __forceinline__ void ldsm_x2_trans(uint32_t* r, uint32_t addr) {
    asm volatile("ldmatrix.sync.aligned.m8n8.x2.trans.shared.b16 {%0,%1}, [%2];"
        : "=r"(r[0]), "=r"(r[1]) : "r"(addr));
}
__device__ __forceinline__ void mma_f16(float* c, const uint32_t* a, const uint32_t* b) {
    asm volatile(
        "mma.sync.aligned.m16n8k16.row.col.f32.f16.f16.f32 "
        "{%0,%1,%2,%3}, {%4,%5,%6,%7}, {%8,%9}, {%0,%1,%2,%3};"
        : "+f"(c[0]), "+f"(c[1]), "+f"(c[2]), "+f"(c[3])
        : "r"(a[0]), "r"(a[1]), "r"(a[2]), "r"(a[3]), "r"(b[0]), "r"(b[1]));
}
__device__ __forceinline__ void split_hl(float v, half& h, half& l) {
    h = __float2half_rn(v);
    l = __float2half_rn(v - __half2float(h));
}

// ---------------------------------------------------------------------------
// Generic tensor-core fp16 GEMM: C = A*B + bias. 128x128 tile, BK=32,
// 3-stage cp.async, 2 CTAs/SM. TERMS as in prior rounds.
// ---------------------------------------------------------------------------
#define TCB_K   32
#define NSTAGE  3

template<int TERMS>
__global__ void __launch_bounds__(256, 2)
tc_gemm_kernel(const half* __restrict__ Ahi, const half* __restrict__ Alo,
               const half* __restrict__ Bhi, const half* __restrict__ Blo,
               const float* __restrict__ bias, float* __restrict__ C,
               int M, int N, int K, int lda, int ldb, int ldc)
{
    constexpr int A_BYTES  = 10240;                    // 128 rows x 40 half
    constexpr int B_BYTES  = 8704;                     // 32 rows x 136 half
    constexpr int OFF_ALO  = A_BYTES;
    constexpr int OFF_BHI  = (TERMS == 3) ? 2 * A_BYTES : A_BYTES;
    constexpr int OFF_BLO  = OFF_BHI + B_BYTES;
    constexpr int STAGE    = OFF_BLO + B_BYTES;

    extern __shared__ __align__(16) char sm[];
    const uint32_t smb = smem_u32(sm);

    const int tid  = threadIdx.x;
    const int wid  = tid >> 5;
    const int lane = tid & 31;
    const int wm   = wid & 1;
    const int wn   = wid >> 1;
    const int m0   = blockIdx.y * 128;
    const int n0   = blockIdx.x * 128;

    const int tA = lane >> 3, rA = lane & 7;
    const int a_row_off = (tA & 1) * 8 + rA;
    const int a_kcol    = (tA >> 1) * 8;
    const uint32_t a_const = (uint32_t)((wm * 64 + a_row_off) * 40 + a_kcol) * 2;
    const int lB = lane & 15;
    const int b_krow = (lB >> 3) * 8 + (lB & 7);
    const uint32_t b_const = (uint32_t)(b_krow * 136 + wn * 32) * 2;

    float acc[4][4][4];
    #pragma unroll
    for (int i = 0; i < 4; i++)
        #pragma unroll
        for (int j = 0; j < 4; j++)
            #pragma unroll
            for (int q = 0; q < 4; q++) acc[i][j][q] = 0.f;

    const int nk = K / TCB_K;

    #define ISSUE_STAGE(slot, kt) do {                                         \
        uint32_t base = smb + (uint32_t)(slot) * STAGE;                        \
        int k0 = (kt) * TCB_K;                                                 \
        _Pragma("unroll")                                                      \
        for (int l = 0; l < 2; ++l) {                                          \
            int idx = tid + l * 256;                                           \
            int r = idx >> 2, c = idx & 3;                                     \
            cp16(base + r * 80 + c * 16,                                       \
                 Ahi + (size_t)(m0 + r) * lda + k0 + c * 8);                   \
            if constexpr (TERMS == 3)                                          \
                cp16(base + OFF_ALO + r * 80 + c * 16,                         \
                     Alo + (size_t)(m0 + r) * lda + k0 + c * 8);               \
        }                                                                      \
        _Pragma("unroll")                                                      \
        for (int l = 0; l < 2; ++l) {                                          \
            int idx = tid + l * 256;                                           \
            int r = idx >> 4, c = idx & 15;                                    \
            cp16(base + OFF_BHI + r * 272 + c * 16,                            \
                 Bhi + (size_t)(k0 + r) * ldb + n0 + c * 8);                   \
            cp16(base + OFF_BLO + r * 272 + c * 16,                            \
                 Blo + (size_t)(k0 + r) * ldb + n0 + c * 8);                   \
        }                                                                      \
    } while (0)

    ISSUE_STAGE(0, 0); cp_commit();
    ISSUE_STAGE(1, 1); cp_commit();

    for (int kt = 0; kt < nk; ++kt) {
        cp_wait1();
        __syncthreads();
        if (kt + 2 < nk) { ISSUE_STAGE((kt + 2) % NSTAGE, kt + 2); }
        cp_commit();

        const int slot = kt % NSTAGE;
        const uint32_t base = smb + (uint32_t)slot * STAGE;
        const uint32_t aHb = base + a_const;
        const uint32_t aLb = base + OFF_ALO + a_const;
        const uint32_t bHb = base + OFF_BHI + b_const;
        const uint32_t bLb = base + OFF_BLO + b_const;

        #pragma unroll
        for (int kk = 0; kk < 2; ++kk) {
            uint32_t aH[4][4], aL[4][4], bH[4][2], bL[4][2];
            const uint32_t akk = (uint32_t)(kk * 16 * 2);
            const uint32_t bkk = (uint32_t)(kk * 16 * 136 * 2);
            #pragma unroll
            for (int mf = 0; mf < 4; ++mf) {
                uint32_t off = (uint32_t)(mf * 16 * 40) * 2 + akk;
                ldsm_x4(aH[mf], aHb + off);
                if constexpr (TERMS == 3) ldsm_x4(aL[mf], aLb + off);
            }
            #pragma unroll
            for (int nf = 0; nf < 4; ++nf) {
                uint32_t off = (uint32_t)(nf * 8) * 2 + bkk;
                ldsm_x2_trans(bH[nf], bHb + off);
                ldsm_x2_trans(bL[nf], bLb + off);
            }
            #pragma unroll
            for (int mf = 0; mf < 4; ++mf)
                #pragma unroll
                for (int nf = 0; nf < 4; ++nf) {
                    mma_f16(acc[mf][nf], aH[mf], bH[nf]);
                    mma_f16(acc[mf][nf], aH[mf], bL[nf]);
                    if constexpr (TERMS == 3) mma_f16(acc[mf][nf], aL[mf], bH[nf]);
                }
        }
    }
    #undef ISSUE_STAGE

    const int g  = lane >> 2;
    const int tg = lane & 3;
    #pragma unroll
    for (int mf = 0; mf < 4; ++mf) {
        int r0 = m0 + wm * 64 + mf * 16 + g;
        #pragma unroll
        for (int nf = 0; nf < 4; ++nf) {
            int c = n0 + wn * 32 + nf * 8 + tg * 2;
            float b0 = bias[c], b1 = bias[c + 1];
            float2 v0 = make_float2(acc[mf][nf][0] + b0, acc[mf][nf][1] + b1);
            float2 v1 = make_float2(acc[mf][nf][2] + b0, acc[mf][nf][3] + b1);
            *reinterpret_cast<float2*>(C + (size_t)r0 * ldc + c) = v0;
            *reinterpret_cast<float2*>(C + (size_t)(r0 + 8) * ldc + c) = v1;
        }
    }
}

// ---------------------------------------------------------------------------
// Pair GEMM + fused LayerNorm: per p (blockIdx.y), C-tile 128(b) x 128(e),
// K=256, 3-term fp16, LN over the full 128-wide row in the epilogue.
// ---------------------------------------------------------------------------
__global__ void __launch_bounds__(256, 1)
pair_gemm_ln_kernel(const half* __restrict__ Xhi, const half* __restrict__ Xlo,
                    const half* __restrict__ PWhi, const half* __restrict__ PWlo,
                    const float* __restrict__ pb, const float* __restrict__ lng,
                    const float* __restrict__ lnb, float* __restrict__ out)
{
    constexpr int A_BYTES = 10240;
    constexpr int B_BYTES = 8704;
    constexpr int OFF_ALO = A_BYTES;
    constexpr int OFF_BHI = 2 * A_BYTES;
    constexpr int OFF_BLO = OFF_BHI + B_BYTES;
    constexpr int STAGE   = OFF_BLO + B_BYTES;   // 37888

    extern __shared__ __align__(16) char sm[];
    const uint32_t smb = smem_u32(sm);

    const int p   = blockIdx.y;
    const int m0  = blockIdx.x * 128;
    const int tid  = threadIdx.x;
    const int wid  = tid >> 5;
    const int lane = tid & 31;
    const int wm   = wid & 1;
    const int wn   = wid >> 1;

    const half* Ahi = Xhi + ((size_t)p * BATCH) * 256;
    const half* Alo = Xlo + ((size_t)p * BATCH) * 256;
    const half* Bhi = PWhi + (size_t)p * 256 * 128;
    const half* Blo = PWlo + (size_t)p * 256 * 128;

    const int tA = lane >> 3, rA = lane & 7;
    const int a_row_off = (tA & 1) * 8 + rA;
    const int a_kcol    = (tA >> 1) * 8;
    const uint32_t a_const = (uint32_t)((wm * 64 + a_row_off) * 40 + a_kcol) * 2;
    const int lB = lane & 15;
    const int b_krow = (lB >> 3) * 8 + (lB & 7);
    const uint32_t b_const = (uint32_t)(b_krow * 136 + wn * 32) * 2;

    float acc[4][4][4];
    #pragma unroll
    for (int i = 0; i < 4; i++)
        #pragma unroll
        for (int j = 0; j < 4; j++)
            #pragma unroll
            for (int q = 0; q < 4; q++) acc[i][j][q] = 0.f;

    #define P_ISSUE(slot, kt) do {                                             \
        uint32_t base = smb + (uint32_t)(slot) * STAGE;                        \
        int k0 = (kt) * TCB_K;                                                 \
        _Pragma("unroll")                                                      \
        for (int l = 0; l < 2; ++l) {                                          \
            int idx = tid + l * 256;                                           \
            int r = idx >> 2, c = idx & 3;                                     \
            cp16(base + r * 80 + c * 16,                                       \
                 Ahi + (size_t)(m0 + r) * 256 + k0 + c * 8);                   \
            cp16(base + OFF_ALO + r * 80 + c * 16,                             \
                 Alo + (size_t)(m0 + r) * 256 + k0 + c * 8);                   \
        }                                                                      \
        _Pragma("unroll")                                                      \
        for (int l = 0; l < 2; ++l) {                                          \
            int idx = tid + l * 256;                                           \
            int r = idx >> 4, c = idx & 15;                                    \
            cp16(base + OFF_BHI + r * 272 + c * 16,                            \
                 Bhi + (size_t)(k0 + r) * 128 + c * 8);                        \
            cp16(base + OFF_BLO + r * 272 + c * 16,                            \
                 Blo + (size_t)(k0 + r) * 128 + c * 8);                        \
        }                                                                      \
    } while (0)

    P_ISSUE(0, 0); cp_commit();

    #pragma unroll
    for (int kt = 0; kt < 8; ++kt) {           // K=256 -> 8 iters of 32
        cp_wait0();
        __syncthreads();
        if (kt + 1 < 8) { P_ISSUE((kt + 1) & 1, kt + 1); cp_commit(); }

        const uint32_t base = smb + (uint32_t)(kt & 1) * STAGE;
        const uint32_t aHb = base + a_const;
        const uint32_t aLb = base + OFF_ALO + a_const;
        const uint32_t bHb = base + OFF_BHI + b_const;
        const uint32_t bLb = base + OFF_BLO + b_const;

        #pragma unroll
        for (int kk = 0; kk < 2; ++kk) {
            uint32_t aH[4][4], aL[4][4], bH[4][2], bL[4][2];
            const uint32_t akk = (uint32_t)(kk * 16 * 2);
            const uint32_t bkk = (uint32_t)(kk * 16 * 136 * 2);
            #pragma unroll
            for (int mf = 0; mf < 4; ++mf) {
                uint32_t off = (uint32_t)(mf * 16 * 40) * 2 + akk;
                ldsm_x4(aH[mf], aHb + off);
                ldsm_x4(aL[mf], aLb + off);
            }
            #pragma unroll
            for (int nf = 0; nf < 4; ++nf) {
                uint32_t off = (uint32_t)(nf * 8) * 2 + bkk;
                ldsm_x2_trans(bH[nf], bHb + off);
                ldsm_x2_trans(bL[nf], bLb + off);
            }
            #pragma unroll
            for (int mf = 0; mf < 4; ++mf)
                #pragma unroll
                for (int nf = 0; nf < 4; ++nf) {
                    mma_f16(acc[mf][nf], aH[mf], bH[nf]);
                    mma_f16(acc[mf][nf], aH[mf], bL[nf]);
                    mma_f16(acc[mf][nf], aL[mf], bH[nf]);
                }
        }
    }
    #undef P_ISSUE

    // ---- epilogue: stage (bias-added) outputs in smem, then LN per row
    __syncthreads();                       // done with stage buffers
    float* os = reinterpret_cast<float*>(sm);   // [128][132]
    const int g  = lane >> 2;
    const int tg = lane & 3;
    #pragma unroll
    for (int mf = 0; mf < 4; ++mf) {
        int r0 = wm * 64 + mf * 16 + g;
        #pragma unroll
        for (int nf = 0; nf < 4; ++nf) {
            int c = wn * 32 + nf * 8 + tg * 2;
            float b0 = pb[p * 128 + c], b1 = pb[p * 128 + c + 1];
            os[r0 * 132 + c]           = acc[mf][nf][0] + b0;
            os[r0 * 132 + c + 1]       = acc[mf][nf][1] + b1;
            os[(r0 + 8) * 132 + c]     = acc[mf][nf][2] + b0;
            os[(r0 + 8) * 132 + c + 1] = acc[mf][nf][3] + b1;
        }
    }
    __syncthreads();

    #pragma unroll
    for (int rr = 0; rr < 16; ++rr) {
        int r = wid * 16 + rr;
        const float* t = os + r * 132;
        float v0 = t[lane], v1 = t[lane + 32], v2 = t[lane + 64], v3 = t[lane + 96];
        float s = v0 + v1 + v2 + v3;
        #pragma unroll
        for (int o = 16; o > 0; o >>= 1) s += __shfl_xor_sync(0xffffffff, s, o);
        float mu = s * (1.0f / 128.0f);
        float d0 = v0 - mu, d1 = v1 - mu, d2 = v2 - mu, d3 = v3 - mu;
        float s2 = d0 * d0 + d1 * d1 + d2 * d2 + d3 * d3;
        #pragma unroll
        for (int o = 16; o > 0; o >>= 1) s2 += __shfl_xor_sync(0xffffffff, s2, o);
        float rstd = rsqrtf(s2 * (1.0f / 128.0f) + LN_EPS);

        int b = m0 + r;
        size_t base = (size_t)b * D_ALL + p * 128;
        int gi = p * 128;
        out[base + lane]      = d0 * rstd * lng[gi + lane]      + lnb[gi + lane];
        out[base + lane + 32] = d1 * rstd * lng[gi + lane + 32] + lnb[gi + lane + 32];
        out[base + lane + 64] = d2 * rstd * lng[gi + lane + 64] + lnb[gi + lane + 64];
        out[base + lane + 96] = d3 * rstd * lng[gi + lane + 96] + lnb[gi + lane + 96];
    }
}

// ---------------------------------------------------------------------------
// fp32 -> fp16 hi/lo split (elementwise, vectorized)
// ---------------------------------------------------------------------------
__global__ __launch_bounds__(256) void cvt_split_kernel(
    const float4* __restrict__ x, uint2* __restrict__ hi, uint2* __restrict__ lo, int n4)
{
    int i = blockIdx.x * 256 + threadIdx.x;
    if (i >= n4) return;
    float4 v = x[i];
    half h0, l0, h1, l1, h2, l2, h3, l3;
    split_hl(v.x, h0, l0); split_hl(v.y, h1, l1);
    split_hl(v.z, h2, l2); split_hl(v.w, h3, l3);
    half2 ha = __halves2half2(h0, h1), hb = __halves2half2(h2, h3);
    half2 la = __halves2half2(l0, l1), lb = __halves2half2(l2, l3);
    hi[i] = make_uint2(*reinterpret_cast<uint32_t*>(&ha), *reinterpret_cast<uint32_t*>(&hb));
    lo[i] = make_uint2(*reinterpret_cast<uint32_t*>(&la), *reinterpret_cast<uint32_t*>(&lb));
}

// ---------------------------------------------------------------------------
// attention weight kernels -> g_attn_hi/lo (B, 128): [pair | macro]
// ---------------------------------------------------------------------------
__global__ __launch_bounds__(128) void attn_pair_kernel(
    const float* __restrict__ ps, const float* __restrict__ keys,
    half* __restrict__ ahi, half* __restrict__ alo)
{
    int b = blockIdx.x, tid = threadIdx.x;
    __shared__ float q[PAIR_DIM];
    __shared__ float sc[NUM_SLOTS];
    __shared__ float red[NUM_SLOTS];

    float s = 0.f;
    #pragma unroll
    for (int p = 0; p < NUM_PAIRS; p++)
        s += ps[(size_t)b * D_ALL + p * PAIR_DIM + tid];
    q[tid] = s * (1.0f / NUM_PAIRS);
    __syncthreads();

    if (tid < NUM_SLOTS) {
        float acc = 0.f;
        #pragma unroll 4
        for (int d = 0; d < PAIR_DIM; d++)
            acc = fmaf(q[d], keys[tid * PAIR_DIM + d], acc);
        sc[tid] = acc * 0.08838834764831845f;
    }
    __syncthreads();

    if (tid < NUM_SLOTS) red[tid] = sc[tid];
    __syncthreads();
    for (int o = 32; o > 0; o >>= 1) {
        if (tid < o) red[tid] = fmaxf(red[tid], red[tid + o]);
        __syncthreads();
    }
    float mx = red[0];
    __syncthreads();

    float e = 0.f;
    if (tid < NUM_SLOTS) { e = expf(sc[tid] - mx); red[tid] = e; }
    __syncthreads();
    for (int o = 32; o > 0; o >>= 1) {
        if (tid < o) red[tid] += red[tid + o];
        __syncthreads();
    }
    if (tid < NUM_SLOTS) {
        half h, l;
        split_hl(e / red[0], h, l);
        ahi[(size_t)b * 128 + tid] = h;
        alo[(size_t)b * 128 + tid] = l;
    }
}

__global__ __launch_bounds__(128) void attn_macro_kernel(
    const float* __restrict__ ms, const float* __restrict__ keys,
    half* __restrict__ ahi, half* __restrict__ alo)
{
    int b = blockIdx.x, tid = threadIdx.x;
    __shared__ float q[MACRO_DIM];
    __shared__ float sc[NUM_SLOTS];
    __shared__ float red[NUM_SLOTS];

    q[tid]       = ms[(size_t)b * MACRO_DIM + tid];
    q[tid + 128] = ms[(size_t)b * MACRO_DIM + tid + 128];
    __syncthreads();

    if (tid < NUM_SLOTS) {
        float acc = 0.f;
        #pragma unroll 4
        for (int d = 0; d < MACRO_DIM; d++)
            acc = fmaf(q[d], keys[tid * MACRO_DIM + d], acc);
        sc[tid] = acc * 0.0625f;
    }
    __syncthreads();

    if (tid < NUM_SLOTS) red[tid] = sc[tid];
    __syncthreads();
    for (int o = 32; o > 0; o >>= 1) {
        if (tid < o) red[tid] = fmaxf(red[tid], red[tid + o]);
        __syncthreads();
    }
    float mx = red[0];
    __syncthreads();

    float e = 0.f;
    if (tid < NUM_SLOTS) { e = expf(sc[tid] - mx); red[tid] = e; }
    __syncthreads();
    for (int o = 32; o > 0; o >>= 1) {
        if (tid < o) red[tid] += red[tid + o];
        __syncthreads();
    }
    if (tid < NUM_SLOTS) {
        half h, l;
        split_hl(e / red[0], h, l);
        ahi[(size_t)b * 128 + 64 + tid] = h;
        alo[(size_t)b * 128 + 64 + tid] = l;
    }
}

// ---------------------------------------------------------------------------
// Zero kernel (for g_V before atomic fold)
// ---------------------------------------------------------------------------
__global__ __launch_bounds__(256) void zero_kernel(float* __restrict__ p, int n)
{
    int i = blockIdx.x * 256 + threadIdx.x;
    if (i < n) p[i] = 0.f;
}

// ---------------------------------------------------------------------------
// Fold v2: V[z*64 + m, n] += sum_k vals_z[m,k] * W1[z*3584 + k, n]
// Tile 64(M) x 256(N), BK=16, split-K=16, cp.async double-buffered.
// 256 threads, micro 8x8 (warp-uniform A rows -> broadcast LDS).
// ---------------------------------------------------------------------------
#define FK_KS   16
#define FK_KCH  (D_ALL / FK_KS)    // 224
#define FK_BK   16
#define FK_BN   256
// smem per buffer: As 64x20 fp32 (5120 B) + Bs 16x260 fp32 (16640 B) = 21760
#define FK_AS_B   5120
#define FK_STAGE  21760

__global__ __launch_bounds__(256, 2) void fold_kernel(
    const float* __restrict__ vals_p, const float* __restrict__ vals_m,
    const float* __restrict__ w1, float* __restrict__ V)
{
    extern __shared__ __align__(16) char sm[];
    const uint32_t smb = smem_u32(sm);

    const int nb = blockIdx.x;
    const int ks = blockIdx.y;
    const int z  = blockIdx.z;
    const float* vals = z ? vals_m : vals_p;
    const float* W    = w1 + (size_t)z * D_ALL * D_ALL;
    float* Vout       = V  + (size_t)z * 64 * D_ALL;

    const int tid = threadIdx.x;
    const int ty  = tid >> 5;          // warp id: m group of 8
    const int tx  = tid & 31;          // n group of 8
    const int n0  = nb * FK_BN;
    const int kb  = ks * FK_KCH;

    float acc[8][8];
    #pragma unroll
    for (int i = 0; i < 8; i++)
        #pragma unroll
        for (int j = 0; j < 8; j++) acc[i][j] = 0.f;

    #define FK_ISSUE(slot, k0) do {                                            \
        uint32_t base = smb + (uint32_t)(slot) * FK_STAGE;                     \
        {   int m = tid >> 2, c = tid & 3;                                     \
            cp16(base + m * 80 + c * 16,                                       \
                 vals + (size_t)m * D_ALL + (k0) + c * 4); }                   \
        _Pragma("unroll")                                                      \
        for (int l = 0; l < 4; ++l) {                                          \
            int idx = tid + l * 256;                                           \
            int r = idx >> 6, c4 = idx & 63;                                   \
            cp16(base + FK_AS_B + r * 1040 + c4 * 16,                          \
                 W + (size_t)((k0) + r) * D_ALL + n0 + c4 * 4); }              \
    } while (0)

    FK_ISSUE(0, kb); cp_commit();

    const int niter = FK_KCH / FK_BK;   // 14
    for (int it = 0; it < niter; ++it) {
        cp_wait0();
        __syncthreads();
        if (it + 1 < niter) { FK_ISSUE((it + 1) & 1, kb + (it + 1) * FK_BK); cp_commit(); }

        const float* As = reinterpret_cast<const float*>(sm + (it & 1) * FK_STAGE);
        const float* Bs = reinterpret_cast<const float*>(sm + (it & 1) * FK_STAGE + FK_AS_B);

        #pragma unroll
        for (int kk = 0; kk < FK_BK; ++kk) {
            float a[8];
            #pragma unroll
            for (int i = 0; i < 8; i++) a[i] = As[(ty * 8 + i) * 20 + kk];
            float4 bq0 = *reinterpret_cast<const float4*>(Bs + kk * 260 + tx * 8);
            float4 bq1 = *reinterpret_cast<const float4*>(Bs + kk * 260 + tx * 8 + 4);
            float b[8] = {bq0.x, bq0.y, bq0.z, bq0.w, bq1.x, bq1.y, bq1.z, bq1.w};
            #pragma unroll
            for (int i = 0; i < 8; i++)
                #pragma unroll
                for (int j = 0; j < 8; j++)
                    acc[i][j] = fmaf(a[i], b[j], acc[i][j]);
        }
    }
    #undef FK_ISSUE

    #pragma unroll
    for (int i = 0; i < 8; i++) {
        int m = ty * 8 + i;
        #pragma unroll
        for (int j = 0; j < 8; j++)
            atomicAdd(Vout + (size_t)m * D_ALL + n0 + tx * 8 + j, acc[i][j]);
    }
}

// ---------------------------------------------------------------------------
// LayerNorm + exact GELU over rows of length D_ALL; writes fp16 hi
// ---------------------------------------------------------------------------
__global__ __launch_bounds__(256) void ln_gelu_kernel(
    const float* __restrict__ h, const float* __restrict__ g, const float* __restrict__ b,
    half* __restrict__ ohi)
{
    __shared__ float row[D_ALL];
    __shared__ float red[256];
    int bi = blockIdx.x, tid = threadIdx.x;
    const float* hrow = h + (size_t)bi * D_ALL;

    float s = 0.f;
    for (int i = tid; i < D_ALL; i += 256) { float v = hrow[i]; row[i] = v; s += v; }
    red[tid] = s; __syncthreads();
    for (int o = 128; o > 0; o >>= 1) { if (tid < o) red[tid] += red[tid + o]; __syncthreads(); }
    float mu = red[0] * (1.0f / D_ALL);
    __syncthreads();

    float s2 = 0.f;
    for (int i = tid; i < D_ALL; i += 256) { float d = row[i] - mu; s2 += d * d; }
    red[tid] = s2; __syncthreads();
    for (int o = 128; o > 0; o >>= 1) { if (tid < o) red[tid] += red[tid + o]; __syncthreads(); }
    float rstd = rsqrtf(red[0] * (1.0f / D_ALL) + LN_EPS);

    for (int i = tid; i < D_ALL; i += 256) {
        float y = (row[i] - mu) * rstd * g[i] + b[i];
        float gl = 0.5f * y * (1.0f + erff(y * 0.70710678118654752f));
        ohi[(size_t)bi * D_ALL + i] = __float2half_rn(gl);
    }
}

// ---------------------------------------------------------------------------
// Build xcat (p, b, 256) fp16 hi/lo from pair_states | fused
// ---------------------------------------------------------------------------
__global__ __launch_bounds__(256) void build_xcat_kernel(
    const float* __restrict__ ps, const float* __restrict__ fused,
    half* __restrict__ xhi, half* __restrict__ xlo)
{
    size_t i = (size_t)blockIdx.x * 256 + threadIdx.x;
    int kc = (int)(i & 31);
    size_t pb = i >> 5;
    int b = (int)(pb & 4095);
    int p = (int)(pb >> 12);
    const float* src = (kc < 16)
        ? ps    + (size_t)b * D_ALL + p * 128 + kc * 8
        : fused + (size_t)b * D_ALL + p * 128 + (kc - 16) * 8;
    half h[8], l[8];
    #pragma unroll
    for (int j = 0; j < 8; j++) split_hl(src[j], h[j], l[j]);
    size_t dst = ((size_t)p * BATCH + b) * 256 + kc * 8;
    *reinterpret_cast<uint4*>(xhi + dst) = *reinterpret_cast<uint4*>(h);
    *reinterpret_cast<uint4*>(xlo + dst) = *reinterpret_cast<uint4*>(l);
}

// ---------------------------------------------------------------------------
// Launch
// ---------------------------------------------------------------------------
extern "C" void kernel_launch(void* const* d_in, const int* in_sizes, int n_in,
                              void* d_out, int out_size)
{
    const float* pair_states    = (const float*)d_in[0];
    const float* macro_state    = (const float*)d_in[1];
    const float* mem_pair_keys  = (const float*)d_in[2];
    const float* mem_pair_vals  = (const float*)d_in[3];
    const float* mem_macro_keys = (const float*)d_in[4];
    const float* mem_macro_vals = (const float*)d_in[5];
    const float* fusion_w1      = (const float*)d_in[6];
    const float* fusion_b1      = (const float*)d_in[7];
    const float* fusion_ln_g    = (const float*)d_in[8];
    const float* fusion_ln_b    = (const float*)d_in[9];
    const float* fusion_w2      = (const float*)d_in[10];
    const float* fusion_b2      = (const float*)d_in[11];
    const float* pair_w         = (const float*)d_in[12];
    const float* pair_b         = (const float*)d_in[13];
    const float* pair_ln_g      = (const float*)d_in[14];
    const float* pair_ln_b      = (const float*)d_in[15];
    float* out = (float*)d_out;

    float *V, *h, *fused;
    half *a_hi, *a_lo, *V_hi, *V_lo, *w2_hi, *w2_lo, *h_hi;
    half *x_hi, *x_lo, *pw_hi, *pw_lo;
    cudaGetSymbolAddress((void**)&a_hi,  g_attn_hi);
    cudaGetSymbolAddress((void**)&a_lo,  g_attn_lo);
    cudaGetSymbolAddress((void**)&V,     g_V);
    cudaGetSymbolAddress((void**)&V_hi,  g_V_hi);
    cudaGetSymbolAddress((void**)&V_lo,  g_V_lo);
    cudaGetSymbolAddress((void**)&w2_hi, g_w2_hi);
    cudaGetSymbolAddress((void**)&w2_lo, g_w2_lo);
    cudaGetSymbolAddress((void**)&h,     g_h);
    cudaGetSymbolAddress((void**)&h_hi,  g_h_hi);
    cudaGetSymbolAddress((void**)&fused, g_fused);
    cudaGetSymbolAddress((void**)&x_hi,  g_xcat_hi);
    cudaGetSymbolAddress((void**)&x_lo,  g_xcat_lo);
    cudaGetSymbolAddress((void**)&pw_hi, g_pw_hi);
    cudaGetSymbolAddress((void**)&pw_lo, g_pw_lo);

    const int SMEM2 = NSTAGE * 27648;            // 82944 (2-term)
    const int SMEM3 = NSTAGE * 37888;            // 113664 (3-term)
    const int SMEMP = 2 * 37888;                 // 75776 (pair, dbl buffer; os fits)
    const int SMEMF = 2 * FK_STAGE;              // 43520 (fold)
    cudaFuncSetAttribute(tc_gemm_kernel<2>,
                         cudaFuncAttributeMaxDynamicSharedMemorySize, SMEM2);
    cudaFuncSetAttribute(tc_gemm_kernel<3>,
                         cudaFuncAttributeMaxDynamicSharedMemorySize, SMEM3);
    cudaFuncSetAttribute(pair_gemm_ln_kernel,
                         cudaFuncAttributeMaxDynamicSharedMemorySize, SMEMP);
    cudaFuncSetAttribute(fold_kernel,
                         cudaFuncAttributeMaxDynamicSharedMemorySize, SMEMF);

    // 1) attention weights -> fp16 hi/lo (B, 128)
    attn_pair_kernel<<<BATCH, 128>>>(pair_states, mem_pair_keys, a_hi, a_lo);
    attn_macro_kernel<<<BATCH, 128>>>(macro_state, mem_macro_keys, a_hi, a_lo);

    // 2) fold: V = [vals_p @ W1top ; vals_m @ W1bot]  (128 x 3584 fp32)
    zero_kernel<<<(128 * D_ALL + 255) / 256, 256>>>(V, 128 * D_ALL);
    fold_kernel<<<dim3(D_ALL / FK_BN, FK_KS, 2), 256, SMEMF>>>(
        mem_pair_vals, mem_macro_vals, fusion_w1, V);
    {
        int n4 = (128 * D_ALL) / 4;
        cvt_split_kernel<<<(n4 + 255) / 256, 256>>>(
            (const float4*)V, (uint2*)V_hi, (uint2*)V_lo, n4);
    }

    // 2b) weight splits (w2, pair_w)
    {
        int n4 = (D_ALL * D_ALL) / 4;
        cvt_split_kernel<<<(n4 + 255) / 256, 256>>>(
            (const float4*)fusion_w2, (uint2*)w2_hi, (uint2*)w2_lo, n4);
        n4 = (NUM_PAIRS * 256 * 128) / 4;
        cvt_split_kernel<<<(n4 + 255) / 256, 256>>>(
            (const float4*)pair_w, (uint2*)pw_hi, (uint2*)pw_lo, n4);
    }

    // 3) h = attn @ V + b1  (tensor cores, 3-term, K=128)
    tc_gemm_kernel<3><<<dim3(D_ALL / 128, BATCH / 128), 256, SMEM3>>>(
        a_hi, a_lo, V_hi, V_lo, fusion_b1, h,
        BATCH, D_ALL, 128, 128, D_ALL, D_ALL);

    // 4) LN + GELU -> h_hi; GEMM2 via tensor cores (fp16 2-term)
    ln_gelu_kernel<<<BATCH, 256>>>(h, fusion_ln_g, fusion_ln_b, h_hi);
    tc_gemm_kernel<2><<<dim3(D_ALL / 128, BATCH / 128), 256, SMEM2>>>(
        h_hi, nullptr, w2_hi, w2_lo, fusion_b2, fused,
        BATCH, D_ALL, D_ALL, D_ALL, D_ALL, D_ALL);

    // 5) per-pair linear + fused LN -> output
    {
        size_t nchunk = (size_t)NUM_PAIRS * BATCH * 32;
        build_xcat_kernel<<<(unsigned)(nchunk / 256), 256>>>(pair_states, fused, x_hi, x_lo);
        pair_gemm_ln_kernel<<<dim3(BATCH / 128, NUM_PAIRS), 256, SMEMP>>>(
            x_hi, x_lo, pw_hi, pw_lo, pair_b, pair_ln_g, pair_ln_b, out);
    }
}

// round 9
// speedup vs baseline: 7.4271x; 1.0370x over previous
#include <cuda_runtime.h>
#include <cuda_fp16.h>
#include <math.h>
#include <stdint.h>

// ---------------------------------------------------------------------------
// Problem constants
// ---------------------------------------------------------------------------
#define BATCH      4096
#define NUM_PAIRS  28
#define PAIR_DIM   128
#define MACRO_DIM  256
#define NUM_SLOTS  64
#define D_ALL      3584          // NUM_PAIRS * PAIR_DIM
#define D_CAT      7168          // 2 * D_ALL
#define LN_EPS     1e-5f

// ---------------------------------------------------------------------------
// Scratch (device globals: allocation-free per harness rules)
// ---------------------------------------------------------------------------
__device__ half  g_attn_hi[BATCH * 128];                      // [attn_p | attn_m]
__device__ half  g_attn_lo[BATCH * 128];
__device__ float g_V[(size_t)128 * D_ALL];                    // [Vp@W1top ; Vm@W1bot]
__device__ half  g_V_hi[(size_t)128 * D_ALL];
__device__ half  g_V_lo[(size_t)128 * D_ALL];
__device__ half  g_w2_hi[(size_t)D_ALL * D_ALL];
__device__ half  g_w2_lo[(size_t)D_ALL * D_ALL];
__device__ float g_h[(size_t)BATCH * D_ALL];
__device__ half  g_h_hi[(size_t)BATCH * D_ALL];
__device__ half  g_xcat_hi[(size_t)NUM_PAIRS * BATCH * 256];  // (p,b,256)
__device__ half  g_xcat_lo[(size_t)NUM_PAIRS * BATCH * 256];
__device__ half  g_pw_hi[(size_t)NUM_PAIRS * 256 * 128];
__device__ half  g_pw_lo[(size_t)NUM_PAIRS * 256 * 128];

// ---------------------------------------------------------------------------
// Small helpers
// ---------------------------------------------------------------------------
__device__ __forceinline__ uint32_t smem_u32(const void* p) {
    uint32_t a;
    asm("{ .reg .u64 t; cvta.to.shared.u64 t, %1; cvt.u32.u64 %0, t; }" : "=r"(a) : "l"(p));
    return a;
}
__device__ __forceinline__ void cp16(uint32_t dst, const void* src) {
    asm volatile("cp.async.cg.shared.global [%0], [%1], 16;" :: "r"(dst), "l"(src));
}
__device__ __forceinline__ void cp_commit() {
    asm volatile("cp.async.commit_group;" ::: "memory");
}
__device__ __forceinline__ void cp_wait0() {
    asm volatile("cp.async.wait_group 0;" ::: "memory");
}
__device__ __forceinline__ void cp_wait1() {
    asm volatile("cp.async.wait_group 1;" ::: "memory");
}
__device__ __forceinline__ void ldsm_x4(uint32_t* r, uint32_t addr) {
    asm volatile("ldmatrix.sync.aligned.m8n8.x4.shared.b16 {%0,%1,%2,%3}, [%4];"
        : "=r"(r[0]), "=r"(r[1]), "=r"(r[2]), "=r"(r[3]) : "r"(addr));
}
__device__ __forceinline__ void ldsm_x2_trans(uint32_t* r, uint32_t addr) {
    asm volatile("ldmatrix.sync.aligned.m8n8.x2.trans.shared.b16 {%0,%1}, [%2];"
        : "=r"(r[0]), "=r"(r[1]) : "r"(addr));
}
__device__ __forceinline__ void mma_f16(float* c, const uint32_t* a, const uint32_t* b) {
    asm volatile(
        "mma.sync.aligned.m16n8k16.row.col.f32.f16.f16.f32 "
        "{%0,%1,%2,%3}, {%4,%5,%6,%7}, {%8,%9}, {%0,%1,%2,%3};"
        : "+f"(c[0]), "+f"(c[1]), "+f"(c[2]), "+f"(c[3])
        : "r"(a[0]), "r"(a[1]), "r"(a[2]), "r"(a[3]), "r"(b[0]), "r"(b[1]));
}
__device__ __forceinline__ void split_hl(float v, half& h, half& l) {
    h = __float2half_rn(v);
    l = __float2half_rn(v - __half2float(h));
}

// ---------------------------------------------------------------------------
// Tensor-core fp16 GEMM: 128x128 tile, BK=32, 3-stage cp.async, 2 CTAs/SM.
//   TERMS==2: D = Ahi*(Bhi+Blo);  TERMS==3: + Alo*Bhi
//   XCAT==1: instead of writing fp32 C, split to fp16 hi/lo and write the
//            "fused" half of xcat in (p, b, 256) layout (p = n-tile).
//   swz==1:  flat-grid L2 swizzle: groups of 4 n-tiles x 32 m-tiles
//            (896 blocks = 7 groups x 128).
// ---------------------------------------------------------------------------
#define TCB_K   32
#define NSTAGE  3

template<int TERMS, int XCAT>
__global__ void __launch_bounds__(256, 2)
tc_gemm_kernel(const half* __restrict__ Ahi, const half* __restrict__ Alo,
               const half* __restrict__ Bhi, const half* __restrict__ Blo,
               const float* __restrict__ bias, float* __restrict__ C,
               half* __restrict__ Xhi, half* __restrict__ Xlo,
               int M, int N, int K, int lda, int ldb, int ldc, int swz)
{
    constexpr int A_BYTES  = 10240;                    // 128 rows x 40 half
    constexpr int B_BYTES  = 8704;                     // 32 rows x 136 half
    constexpr int OFF_ALO  = A_BYTES;
    constexpr int OFF_BHI  = (TERMS == 3) ? 2 * A_BYTES : A_BYTES;
    constexpr int OFF_BLO  = OFF_BHI + B_BYTES;
    constexpr int STAGE    = OFF_BLO + B_BYTES;

    extern __shared__ __align__(16) char sm[];
    const uint32_t smb = smem_u32(sm);

    int bx, by;
    if (swz) {
        // 896 blocks: 7 groups of (4 n-tiles x 32 m-tiles)
        int id = blockIdx.x;
        int ng = id >> 7;          // group (0..6)
        int r  = id & 127;
        bx = ng * 4 + (r & 3);     // 0..27
        by = r >> 2;               // 0..31
    } else {
        bx = blockIdx.x; by = blockIdx.y;
    }

    const int tid  = threadIdx.x;
    const int wid  = tid >> 5;
    const int lane = tid & 31;
    const int wm   = wid & 1;
    const int wn   = wid >> 1;
    const int m0   = by * 128;
    const int n0   = bx * 128;

    const int tA = lane >> 3, rA = lane & 7;
    const int a_row_off = (tA & 1) * 8 + rA;
    const int a_kcol    = (tA >> 1) * 8;
    const uint32_t a_const = (uint32_t)((wm * 64 + a_row_off) * 40 + a_kcol) * 2;
    const int lB = lane & 15;
    const int b_krow = (lB >> 3) * 8 + (lB & 7);
    const uint32_t b_const = (uint32_t)(b_krow * 136 + wn * 32) * 2;

    float acc[4][4][4];
    #pragma unroll
    for (int i = 0; i < 4; i++)
        #pragma unroll
        for (int j = 0; j < 4; j++)
            #pragma unroll
            for (int q = 0; q < 4; q++) acc[i][j][q] = 0.f;

    const int nk = K / TCB_K;

    #define ISSUE_STAGE(slot, kt) do {                                         \
        uint32_t base = smb + (uint32_t)(slot) * STAGE;                        \
        int k0 = (kt) * TCB_K;                                                 \
        _Pragma("unroll")                                                      \
        for (int l = 0; l < 2; ++l) {                                          \
            int idx = tid + l * 256;                                           \
            int r = idx >> 2, c = idx & 3;                                     \
            cp16(base + r * 80 + c * 16,                                       \
                 Ahi + (size_t)(m0 + r) * lda + k0 + c * 8);                   \
            if constexpr (TERMS == 3)                                          \
                cp16(base + OFF_ALO + r * 80 + c * 16,                         \
                     Alo + (size_t)(m0 + r) * lda + k0 + c * 8);               \
        }                                                                      \
        _Pragma("unroll")                                                      \
        for (int l = 0; l < 2; ++l) {                                          \
            int idx = tid + l * 256;                                           \
            int r = idx >> 4, c = idx & 15;                                    \
            cp16(base + OFF_BHI + r * 272 + c * 16,                            \
                 Bhi + (size_t)(k0 + r) * ldb + n0 + c * 8);                   \
            cp16(base + OFF_BLO + r * 272 + c * 16,                            \
                 Blo + (size_t)(k0 + r) * ldb + n0 + c * 8);                   \
        }                                                                      \
    } while (0)

    ISSUE_STAGE(0, 0); cp_commit();
    ISSUE_STAGE(1, 1); cp_commit();

    for (int kt = 0; kt < nk; ++kt) {
        cp_wait1();
        __syncthreads();
        if (kt + 2 < nk) { ISSUE_STAGE((kt + 2) % NSTAGE, kt + 2); }
        cp_commit();

        const int slot = kt % NSTAGE;
        const uint32_t base = smb + (uint32_t)slot * STAGE;
        const uint32_t aHb = base + a_const;
        const uint32_t aLb = base + OFF_ALO + a_const;
        const uint32_t bHb = base + OFF_BHI + b_const;
        const uint32_t bLb = base + OFF_BLO + b_const;

        #pragma unroll
        for (int kk = 0; kk < 2; ++kk) {
            uint32_t aH[4][4], aL[4][4], bH[4][2], bL[4][2];
            const uint32_t akk = (uint32_t)(kk * 16 * 2);
            const uint32_t bkk = (uint32_t)(kk * 16 * 136 * 2);
            #pragma unroll
            for (int mf = 0; mf < 4; ++mf) {
                uint32_t off = (uint32_t)(mf * 16 * 40) * 2 + akk;
                ldsm_x4(aH[mf], aHb + off);
                if constexpr (TERMS == 3) ldsm_x4(aL[mf], aLb + off);
            }
            #pragma unroll
            for (int nf = 0; nf < 4; ++nf) {
                uint32_t off = (uint32_t)(nf * 8) * 2 + bkk;
                ldsm_x2_trans(bH[nf], bHb + off);
                ldsm_x2_trans(bL[nf], bLb + off);
            }
            #pragma unroll
            for (int mf = 0; mf < 4; ++mf)
                #pragma unroll
                for (int nf = 0; nf < 4; ++nf) {
                    mma_f16(acc[mf][nf], aH[mf], bH[nf]);
                    mma_f16(acc[mf][nf], aH[mf], bL[nf]);
                    if constexpr (TERMS == 3) mma_f16(acc[mf][nf], aL[mf], bH[nf]);
                }
        }
    }
    #undef ISSUE_STAGE

    const int g  = lane >> 2;
    const int tg = lane & 3;
    #pragma unroll
    for (int mf = 0; mf < 4; ++mf) {
        int r0 = m0 + wm * 64 + mf * 16 + g;
        #pragma unroll
        for (int nf = 0; nf < 4; ++nf) {
            int c = wn * 32 + nf * 8 + tg * 2;
            float b0 = bias[n0 + c], b1 = bias[n0 + c + 1];
            float v00 = acc[mf][nf][0] + b0, v01 = acc[mf][nf][1] + b1;
            float v10 = acc[mf][nf][2] + b0, v11 = acc[mf][nf][3] + b1;
            if constexpr (XCAT == 1) {
                // write xcat fused-half: (p=bx, b, 128+c) fp16 hi/lo
                half h00, l00, h01, l01, h10, l10, h11, l11;
                split_hl(v00, h00, l00); split_hl(v01, h01, l01);
                split_hl(v10, h10, l10); split_hl(v11, h11, l11);
                size_t d0 = ((size_t)bx * BATCH + r0) * 256 + 128 + c;
                size_t d1 = ((size_t)bx * BATCH + r0 + 8) * 256 + 128 + c;
                *reinterpret_cast<half2*>(Xhi + d0) = __halves2half2(h00, h01);
                *reinterpret_cast<half2*>(Xlo + d0) = __halves2half2(l00, l01);
                *reinterpret_cast<half2*>(Xhi + d1) = __halves2half2(h10, h11);
                *reinterpret_cast<half2*>(Xlo + d1) = __halves2half2(l10, l11);
            } else {
                *reinterpret_cast<float2*>(C + (size_t)r0 * ldc + n0 + c) =
                    make_float2(v00, v01);
                *reinterpret_cast<float2*>(C + (size_t)(r0 + 8) * ldc + n0 + c) =
                    make_float2(v10, v11);
            }
        }
    }
}

// ---------------------------------------------------------------------------
// Pair GEMM + fused LayerNorm: per p (blockIdx.y), C-tile 128(b) x 128(e),
// K=256, 3-term fp16, LN over the full 128-wide row in the epilogue.
// ---------------------------------------------------------------------------
__global__ void __launch_bounds__(256, 1)
pair_gemm_ln_kernel(const half* __restrict__ Xhi, const half* __restrict__ Xlo,
                    const half* __restrict__ PWhi, const half* __restrict__ PWlo,
                    const float* __restrict__ pb, const float* __restrict__ lng,
                    const float* __restrict__ lnb, float* __restrict__ out)
{
    constexpr int A_BYTES = 10240;
    constexpr int B_BYTES = 8704;
    constexpr int OFF_ALO = A_BYTES;
    constexpr int OFF_BHI = 2 * A_BYTES;
    constexpr int OFF_BLO = OFF_BHI + B_BYTES;
    constexpr int STAGE   = OFF_BLO + B_BYTES;   // 37888

    extern __shared__ __align__(16) char sm[];
    const uint32_t smb = smem_u32(sm);

    const int p   = blockIdx.y;
    const int m0  = blockIdx.x * 128;
    const int tid  = threadIdx.x;
    const int wid  = tid >> 5;
    const int lane = tid & 31;
    const int wm   = wid & 1;
    const int wn   = wid >> 1;

    const half* Ahi = Xhi + ((size_t)p * BATCH) * 256;
    const half* Alo = Xlo + ((size_t)p * BATCH) * 256;
    const half* Bhi = PWhi + (size_t)p * 256 * 128;
    const half* Blo = PWlo + (size_t)p * 256 * 128;

    const int tA = lane >> 3, rA = lane & 7;
    const int a_row_off = (tA & 1) * 8 + rA;
    const int a_kcol    = (tA >> 1) * 8;
    const uint32_t a_const = (uint32_t)((wm * 64 + a_row_off) * 40 + a_kcol) * 2;
    const int lB = lane & 15;
    const int b_krow = (lB >> 3) * 8 + (lB & 7);
    const uint32_t b_const = (uint32_t)(b_krow * 136 + wn * 32) * 2;

    float acc[4][4][4];
    #pragma unroll
    for (int i = 0; i < 4; i++)
        #pragma unroll
        for (int j = 0; j < 4; j++)
            #pragma unroll
            for (int q = 0; q < 4; q++) acc[i][j][q] = 0.f;

    #define P_ISSUE(slot, kt) do {                                             \
        uint32_t base = smb + (uint32_t)(slot) * STAGE;                        \
        int k0 = (kt) * TCB_K;                                                 \
        _Pragma("unroll")                                                      \
        for (int l = 0; l < 2; ++l) {                                          \
            int idx = tid + l * 256;                                           \
            int r = idx >> 2, c = idx & 3;                                     \
            cp16(base + r * 80 + c * 16,                                       \
                 Ahi + (size_t)(m0 + r) * 256 + k0 + c * 8);                   \
            cp16(base + OFF_ALO + r * 80 + c * 16,                             \
                 Alo + (size_t)(m0 + r) * 256 + k0 + c * 8);                   \
        }                                                                      \
        _Pragma("unroll")                                                      \
        for (int l = 0; l < 2; ++l) {                                          \
            int idx = tid + l * 256;                                           \
            int r = idx >> 4, c = idx & 15;                                    \
            cp16(base + OFF_BHI + r * 272 + c * 16,                            \
                 Bhi + (size_t)(k0 + r) * 128 + c * 8);                        \
            cp16(base + OFF_BLO + r * 272 + c * 16,                            \
                 Blo + (size_t)(k0 + r) * 128 + c * 8);                        \
        }                                                                      \
    } while (0)

    P_ISSUE(0, 0); cp_commit();

    #pragma unroll
    for (int kt = 0; kt < 8; ++kt) {           // K=256 -> 8 iters of 32
        cp_wait0();
        __syncthreads();
        if (kt + 1 < 8) { P_ISSUE((kt + 1) & 1, kt + 1); cp_commit(); }

        const uint32_t base = smb + (uint32_t)(kt & 1) * STAGE;
        const uint32_t aHb = base + a_const;
        const uint32_t aLb = base + OFF_ALO + a_const;
        const uint32_t bHb = base + OFF_BHI + b_const;
        const uint32_t bLb = base + OFF_BLO + b_const;

        #pragma unroll
        for (int kk = 0; kk < 2; ++kk) {
            uint32_t aH[4][4], aL[4][4], bH[4][2], bL[4][2];
            const uint32_t akk = (uint32_t)(kk * 16 * 2);
            const uint32_t bkk = (uint32_t)(kk * 16 * 136 * 2);
            #pragma unroll
            for (int mf = 0; mf < 4; ++mf) {
                uint32_t off = (uint32_t)(mf * 16 * 40) * 2 + akk;
                ldsm_x4(aH[mf], aHb + off);
                ldsm_x4(aL[mf], aLb + off);
            }
            #pragma unroll
            for (int nf = 0; nf < 4; ++nf) {
                uint32_t off = (uint32_t)(nf * 8) * 2 + bkk;
                ldsm_x2_trans(bH[nf], bHb + off);
                ldsm_x2_trans(bL[nf], bLb + off);
            }
            #pragma unroll
            for (int mf = 0; mf < 4; ++mf)
                #pragma unroll
                for (int nf = 0; nf < 4; ++nf) {
                    mma_f16(acc[mf][nf], aH[mf], bH[nf]);
                    mma_f16(acc[mf][nf], aH[mf], bL[nf]);
                    mma_f16(acc[mf][nf], aL[mf], bH[nf]);
                }
        }
    }
    #undef P_ISSUE

    // ---- epilogue: stage (bias-added) outputs in smem, then LN per row
    __syncthreads();                       // done with stage buffers
    float* os = reinterpret_cast<float*>(sm);   // [128][132]
    const int g  = lane >> 2;
    const int tg = lane & 3;
    #pragma unroll
    for (int mf = 0; mf < 4; ++mf) {
        int r0 = wm * 64 + mf * 16 + g;
        #pragma unroll
        for (int nf = 0; nf < 4; ++nf) {
            int c = wn * 32 + nf * 8 + tg * 2;
            float b0 = pb[p * 128 + c], b1 = pb[p * 128 + c + 1];
            os[r0 * 132 + c]           = acc[mf][nf][0] + b0;
            os[r0 * 132 + c + 1]       = acc[mf][nf][1] + b1;
            os[(r0 + 8) * 132 + c]     = acc[mf][nf][2] + b0;
            os[(r0 + 8) * 132 + c + 1] = acc[mf][nf][3] + b1;
        }
    }
    __syncthreads();

    #pragma unroll
    for (int rr = 0; rr < 16; ++rr) {
        int r = wid * 16 + rr;
        const float* t = os + r * 132;
        float v0 = t[lane], v1 = t[lane + 32], v2 = t[lane + 64], v3 = t[lane + 96];
        float s = v0 + v1 + v2 + v3;
        #pragma unroll
        for (int o = 16; o > 0; o >>= 1) s += __shfl_xor_sync(0xffffffff, s, o);
        float mu = s * (1.0f / 128.0f);
        float d0 = v0 - mu, d1 = v1 - mu, d2 = v2 - mu, d3 = v3 - mu;
        float s2 = d0 * d0 + d1 * d1 + d2 * d2 + d3 * d3;
        #pragma unroll
        for (int o = 16; o > 0; o >>= 1) s2 += __shfl_xor_sync(0xffffffff, s2, o);
        float rstd = rsqrtf(s2 * (1.0f / 128.0f) + LN_EPS);

        int b = m0 + r;
        size_t base = (size_t)b * D_ALL + p * 128;
        int gi = p * 128;
        out[base + lane]      = d0 * rstd * lng[gi + lane]      + lnb[gi + lane];
        out[base + lane + 32] = d1 * rstd * lng[gi + lane + 32] + lnb[gi + lane + 32];
        out[base + lane + 64] = d2 * rstd * lng[gi + lane + 64] + lnb[gi + lane + 64];
        out[base + lane + 96] = d3 * rstd * lng[gi + lane + 96] + lnb[gi + lane + 96];
    }
}

// ---------------------------------------------------------------------------
// fp32 -> fp16 hi/lo split (elementwise, vectorized)
// ---------------------------------------------------------------------------
__global__ __launch_bounds__(256) void cvt_split_kernel(
    const float4* __restrict__ x, uint2* __restrict__ hi, uint2* __restrict__ lo, int n4)
{
    int i = blockIdx.x * 256 + threadIdx.x;
    if (i >= n4) return;
    float4 v = x[i];
    half h0, l0, h1, l1, h2, l2, h3, l3;
    split_hl(v.x, h0, l0); split_hl(v.y, h1, l1);
    split_hl(v.z, h2, l2); split_hl(v.w, h3, l3);
    half2 ha = __halves2half2(h0, h1), hb = __halves2half2(h2, h3);
    half2 la = __halves2half2(l0, l1), lb = __halves2half2(l2, l3);
    hi[i] = make_uint2(*reinterpret_cast<uint32_t*>(&ha), *reinterpret_cast<uint32_t*>(&hb));
    lo[i] = make_uint2(*reinterpret_cast<uint32_t*>(&la), *reinterpret_cast<uint32_t*>(&lb));
}

// ---------------------------------------------------------------------------
// attention weight kernels -> g_attn_hi/lo (B, 128): [pair | macro]
// ---------------------------------------------------------------------------
__global__ __launch_bounds__(128) void attn_pair_kernel(
    const float* __restrict__ ps, const float* __restrict__ keys,
    half* __restrict__ ahi, half* __restrict__ alo)
{
    int b = blockIdx.x, tid = threadIdx.x;
    __shared__ float q[PAIR_DIM];
    __shared__ float sc[NUM_SLOTS];
    __shared__ float red[NUM_SLOTS];

    float s = 0.f;
    #pragma unroll
    for (int p = 0; p < NUM_PAIRS; p++)
        s += ps[(size_t)b * D_ALL + p * PAIR_DIM + tid];
    q[tid] = s * (1.0f / NUM_PAIRS);
    __syncthreads();

    if (tid < NUM_SLOTS) {
        float acc = 0.f;
        #pragma unroll 4
        for (int d = 0; d < PAIR_DIM; d++)
            acc = fmaf(q[d], keys[tid * PAIR_DIM + d], acc);
        sc[tid] = acc * 0.08838834764831845f;
    }
    __syncthreads();

    if (tid < NUM_SLOTS) red[tid] = sc[tid];
    __syncthreads();
    for (int o = 32; o > 0; o >>= 1) {
        if (tid < o) red[tid] = fmaxf(red[tid], red[tid + o]);
        __syncthreads();
    }
    float mx = red[0];
    __syncthreads();

    float e = 0.f;
    if (tid < NUM_SLOTS) { e = expf(sc[tid] - mx); red[tid] = e; }
    __syncthreads();
    for (int o = 32; o > 0; o >>= 1) {
        if (tid < o) red[tid] += red[tid + o];
        __syncthreads();
    }
    if (tid < NUM_SLOTS) {
        half h, l;
        split_hl(e / red[0], h, l);
        ahi[(size_t)b * 128 + tid] = h;
        alo[(size_t)b * 128 + tid] = l;
    }
}

__global__ __launch_bounds__(128) void attn_macro_kernel(
    const float* __restrict__ ms, const float* __restrict__ keys,
    half* __restrict__ ahi, half* __restrict__ alo)
{
    int b = blockIdx.x, tid = threadIdx.x;
    __shared__ float q[MACRO_DIM];
    __shared__ float sc[NUM_SLOTS];
    __shared__ float red[NUM_SLOTS];

    q[tid]       = ms[(size_t)b * MACRO_DIM + tid];
    q[tid + 128] = ms[(size_t)b * MACRO_DIM + tid + 128];
    __syncthreads();

    if (tid < NUM_SLOTS) {
        float acc = 0.f;
        #pragma unroll 4
        for (int d = 0; d < MACRO_DIM; d++)
            acc = fmaf(q[d], keys[tid * MACRO_DIM + d], acc);
        sc[tid] = acc * 0.0625f;
    }
    __syncthreads();

    if (tid < NUM_SLOTS) red[tid] = sc[tid];
    __syncthreads();
    for (int o = 32; o > 0; o >>= 1) {
        if (tid < o) red[tid] = fmaxf(red[tid], red[tid + o]);
        __syncthreads();
    }
    float mx = red[0];
    __syncthreads();

    float e = 0.f;
    if (tid < NUM_SLOTS) { e = expf(sc[tid] - mx); red[tid] = e; }
    __syncthreads();
    for (int o = 32; o > 0; o >>= 1) {
        if (tid < o) red[tid] += red[tid + o];
        __syncthreads();
    }
    if (tid < NUM_SLOTS) {
        half h, l;
        split_hl(e / red[0], h, l);
        ahi[(size_t)b * 128 + 64 + tid] = h;
        alo[(size_t)b * 128 + 64 + tid] = l;
    }
}

// ---------------------------------------------------------------------------
// Zero kernel (for g_V before atomic fold)
// ---------------------------------------------------------------------------
__global__ __launch_bounds__(256) void zero_kernel(float* __restrict__ p, int n)
{
    int i = blockIdx.x * 256 + threadIdx.x;
    if (i < n) p[i] = 0.f;
}

// ---------------------------------------------------------------------------
// Fold v3: V[z*64 + m, n] += sum_k vals_z[m,k] * W1[z*3584 + k, n]
// Tile 64(M) x 128(N), BK=16, split-K=16, cp.async double-buffered.
// 256 threads (8 warps x 8 rows; 32 lanes x 4 cols), micro 8x4. 4 CTAs/SM.
// ---------------------------------------------------------------------------
#define FK_KS   16
#define FK_KCH  (D_ALL / FK_KS)    // 224
#define FK_BK   16
#define FK_BN   128
// smem per buffer: As 64x20 fp32 (5120 B) + Bs 16x132 fp32 (8448 B) = 13568
#define FK_AS_B   5120
#define FK_STAGE  13568

__global__ __launch_bounds__(256, 4) void fold_kernel(
    const float* __restrict__ vals_p, const float* __restrict__ vals_m,
    const float* __restrict__ w1, float* __restrict__ V)
{
    extern __shared__ __align__(16) char sm[];
    const uint32_t smb = smem_u32(sm);

    const int nb = blockIdx.x;
    const int ks = blockIdx.y;
    const int z  = blockIdx.z;
    const float* vals = z ? vals_m : vals_p;
    const float* W    = w1 + (size_t)z * D_ALL * D_ALL;
    float* Vout       = V  + (size_t)z * 64 * D_ALL;

    const int tid = threadIdx.x;
    const int ty  = tid >> 5;          // warp id: 8 rows each
    const int tx  = tid & 31;          // lane: 4 cols each
    const int n0  = nb * FK_BN;
    const int kb  = ks * FK_KCH;

    float acc[8][4];
    #pragma unroll
    for (int i = 0; i < 8; i++)
        #pragma unroll
        for (int j = 0; j < 4; j++) acc[i][j] = 0.f;

    #define FK_ISSUE(slot, k0) do {                                            \
        uint32_t base = smb + (uint32_t)(slot) * FK_STAGE;                     \
        {   int m = tid >> 2, c = tid & 3;                                     \
            cp16(base + m * 80 + c * 16,                                       \
                 vals + (size_t)m * D_ALL + (k0) + c * 4); }                   \
        _Pragma("unroll")                                                      \
        for (int l = 0; l < 2; ++l) {                                          \
            int idx = tid + l * 256;                                           \
            int r = idx >> 5, c4 = idx & 31;                                   \
            cp16(base + FK_AS_B + r * 528 + c4 * 16,                           \
                 W + (size_t)((k0) + r) * D_ALL + n0 + c4 * 4); }              \
    } while (0)

    FK_ISSUE(0, kb); cp_commit();

    const int niter = FK_KCH / FK_BK;   // 14
    for (int it = 0; it < niter; ++it) {
        cp_wait0();
        __syncthreads();
        if (it + 1 < niter) { FK_ISSUE((it + 1) & 1, kb + (it + 1) * FK_BK); cp_commit(); }

        const float* As = reinterpret_cast<const float*>(sm + (it & 1) * FK_STAGE);
        const float* Bs = reinterpret_cast<const float*>(sm + (it & 1) * FK_STAGE + FK_AS_B);

        #pragma unroll
        for (int kk = 0; kk < FK_BK; ++kk) {
            float a[8];
            #pragma unroll
            for (int i = 0; i < 8; i++) a[i] = As[(ty * 8 + i) * 20 + kk];
            float4 bq = *reinterpret_cast<const float4*>(Bs + kk * 132 + tx * 4);
            float b[4] = {bq.x, bq.y, bq.z, bq.w};
            #pragma unroll
            for (int i = 0; i < 8; i++)
                #pragma unroll
                for (int j = 0; j < 4; j++)
                    acc[i][j] = fmaf(a[i], b[j], acc[i][j]);
        }
    }
    #undef FK_ISSUE

    #pragma unroll
    for (int i = 0; i < 8; i++) {
        int m = ty * 8 + i;
        #pragma unroll
        for (int j = 0; j < 4; j++)
            atomicAdd(Vout + (size_t)m * D_ALL + n0 + tx * 4 + j, acc[i][j]);
    }
}

// ---------------------------------------------------------------------------
// LayerNorm + exact GELU over rows of length D_ALL; writes fp16 hi.
// Single-pass (sum, sumsq), 512 threads, float4.
// ---------------------------------------------------------------------------
__global__ __launch_bounds__(512) void ln_gelu_kernel(
    const float* __restrict__ h, const float* __restrict__ g, const float* __restrict__ b,
    half* __restrict__ ohi)
{
    __shared__ float row[D_ALL];
    __shared__ float reds[16], reds2[16];
    int bi = blockIdx.x, tid = threadIdx.x;
    const float4* hrow = reinterpret_cast<const float4*>(h + (size_t)bi * D_ALL);
    float4* rowv = reinterpret_cast<float4*>(row);

    float s = 0.f, s2 = 0.f;
    for (int i = tid; i < D_ALL / 4; i += 512) {
        float4 v = hrow[i];
        rowv[i] = v;
        s  += v.x + v.y + v.z + v.w;
        s2 += v.x * v.x + v.y * v.y + v.z * v.z + v.w * v.w;
    }
    #pragma unroll
    for (int o = 16; o > 0; o >>= 1) {
        s  += __shfl_xor_sync(0xffffffff, s, o);
        s2 += __shfl_xor_sync(0xffffffff, s2, o);
    }
    int warp = tid >> 5, lane = tid & 31;
    if (lane == 0) { reds[warp] = s; reds2[warp] = s2; }
    __syncthreads();
    if (warp == 0) {
        float a = (lane < 16) ? reds[lane] : 0.f;
        float a2 = (lane < 16) ? reds2[lane] : 0.f;
        #pragma unroll
        for (int o = 8; o > 0; o >>= 1) {
            a  += __shfl_xor_sync(0xffffffff, a, o);
            a2 += __shfl_xor_sync(0xffffffff, a2, o);
        }
        if (lane == 0) { reds[0] = a; reds2[0] = a2; }
    }
    __syncthreads();
    float mu = reds[0] * (1.0f / D_ALL);
    float var = reds2[0] * (1.0f / D_ALL) - mu * mu;
    float rstd = rsqrtf(var + LN_EPS);

    half* orow = ohi + (size_t)bi * D_ALL;
    for (int i = tid; i < D_ALL / 4; i += 512) {
        float4 v = rowv[i];
        float4 gg = reinterpret_cast<const float4*>(g)[i];
        float4 bb = reinterpret_cast<const float4*>(b)[i];
        float y0 = (v.x - mu) * rstd * gg.x + bb.x;
        float y1 = (v.y - mu) * rstd * gg.y + bb.y;
        float y2 = (v.z - mu) * rstd * gg.z + bb.z;
        float y3 = (v.w - mu) * rstd * gg.w + bb.w;
        const float k = 0.70710678118654752f;
        half o0 = __float2half_rn(0.5f * y0 * (1.0f + erff(y0 * k)));
        half o1 = __float2half_rn(0.5f * y1 * (1.0f + erff(y1 * k)));
        half o2 = __float2half_rn(0.5f * y2 * (1.0f + erff(y2 * k)));
        half o3 = __float2half_rn(0.5f * y3 * (1.0f + erff(y3 * k)));
        half h4[4] = {o0, o1, o2, o3};
        *reinterpret_cast<uint2*>(orow + i * 4) = *reinterpret_cast<uint2*>(h4);
    }
}

// ---------------------------------------------------------------------------
// Build xcat pair_states half only: (p, b, 0..128) fp16 hi/lo
// ---------------------------------------------------------------------------
__global__ __launch_bounds__(256) void build_xps_kernel(
    const float* __restrict__ ps, half* __restrict__ xhi, half* __restrict__ xlo)
{
    size_t i = (size_t)blockIdx.x * 256 + threadIdx.x;   // 8-elem chunk id
    int kc = (int)(i & 15);
    size_t pb = i >> 4;
    int b = (int)(pb & 4095);
    int p = (int)(pb >> 12);
    const float* src = ps + (size_t)b * D_ALL + p * 128 + kc * 8;
    half h[8], l[8];
    #pragma unroll
    for (int j = 0; j < 8; j++) split_hl(src[j], h[j], l[j]);
    size_t dst = ((size_t)p * BATCH + b) * 256 + kc * 8;
    *reinterpret_cast<uint4*>(xhi + dst) = *reinterpret_cast<uint4*>(h);
    *reinterpret_cast<uint4*>(xlo + dst) = *reinterpret_cast<uint4*>(l);
}

// ---------------------------------------------------------------------------
// Launch
// ---------------------------------------------------------------------------
extern "C" void kernel_launch(void* const* d_in, const int* in_sizes, int n_in,
                              void* d_out, int out_size)
{
    const float* pair_states    = (const float*)d_in[0];
    const float* macro_state    = (const float*)d_in[1];
    const float* mem_pair_keys  = (const float*)d_in[2];
    const float* mem_pair_vals  = (const float*)d_in[3];
    const float* mem_macro_keys = (const float*)d_in[4];
    const float* mem_macro_vals = (const float*)d_in[5];
    const float* fusion_w1      = (const float*)d_in[6];
    const float* fusion_b1      = (const float*)d_in[7];
    const float* fusion_ln_g    = (const float*)d_in[8];
    const float* fusion_ln_b    = (const float*)d_in[9];
    const float* fusion_w2      = (const float*)d_in[10];
    const float* fusion_b2      = (const float*)d_in[11];
    const float* pair_w         = (const float*)d_in[12];
    const float* pair_b         = (const float*)d_in[13];
    const float* pair_ln_g      = (const float*)d_in[14];
    const float* pair_ln_b      = (const float*)d_in[15];
    float* out = (float*)d_out;

    float *V, *h;
    half *a_hi, *a_lo, *V_hi, *V_lo, *w2_hi, *w2_lo, *h_hi;
    half *x_hi, *x_lo, *pw_hi, *pw_lo;
    cudaGetSymbolAddress((void**)&a_hi,  g_attn_hi);
    cudaGetSymbolAddress((void**)&a_lo,  g_attn_lo);
    cudaGetSymbolAddress((void**)&V,     g_V);
    cudaGetSymbolAddress((void**)&V_hi,  g_V_hi);
    cudaGetSymbolAddress((void**)&V_lo,  g_V_lo);
    cudaGetSymbolAddress((void**)&w2_hi, g_w2_hi);
    cudaGetSymbolAddress((void**)&w2_lo, g_w2_lo);
    cudaGetSymbolAddress((void**)&h,     g_h);
    cudaGetSymbolAddress((void**)&h_hi,  g_h_hi);
    cudaGetSymbolAddress((void**)&x_hi,  g_xcat_hi);
    cudaGetSymbolAddress((void**)&x_lo,  g_xcat_lo);
    cudaGetSymbolAddress((void**)&pw_hi, g_pw_hi);
    cudaGetSymbolAddress((void**)&pw_lo, g_pw_lo);

    const int SMEM2 = NSTAGE * 27648;            // 82944 (2-term)
    const int SMEM3 = NSTAGE * 37888;            // 113664 (3-term)
    const int SMEMP = 2 * 37888;                 // 75776 (pair)
    const int SMEMF = 2 * FK_STAGE;              // 27136 (fold)
    cudaFuncSetAttribute(tc_gemm_kernel<2, 1>,
                         cudaFuncAttributeMaxDynamicSharedMemorySize, SMEM2);
    cudaFuncSetAttribute(tc_gemm_kernel<3, 0>,
                         cudaFuncAttributeMaxDynamicSharedMemorySize, SMEM3);
    cudaFuncSetAttribute(pair_gemm_ln_kernel,
                         cudaFuncAttributeMaxDynamicSharedMemorySize, SMEMP);
    cudaFuncSetAttribute(fold_kernel,
                         cudaFuncAttributeMaxDynamicSharedMemorySize, SMEMF);

    // 1) attention weights -> fp16 hi/lo (B, 128)
    attn_pair_kernel<<<BATCH, 128>>>(pair_states, mem_pair_keys, a_hi, a_lo);
    attn_macro_kernel<<<BATCH, 128>>>(macro_state, mem_macro_keys, a_hi, a_lo);

    // 2) fold: V = [vals_p @ W1top ; vals_m @ W1bot]  (128 x 3584 fp32)
    zero_kernel<<<(128 * D_ALL + 255) / 256, 256>>>(V, 128 * D_ALL);
    fold_kernel<<<dim3(D_ALL / FK_BN, FK_KS, 2), 256, SMEMF>>>(
        mem_pair_vals, mem_macro_vals, fusion_w1, V);
    {
        int n4 = (128 * D_ALL) / 4;
        cvt_split_kernel<<<(n4 + 255) / 256, 256>>>(
            (const float4*)V, (uint2*)V_hi, (uint2*)V_lo, n4);
    }

    // 2b) weight splits (w2, pair_w); xcat pair_states half
    {
        int n4 = (D_ALL * D_ALL) / 4;
        cvt_split_kernel<<<(n4 + 255) / 256, 256>>>(
            (const float4*)fusion_w2, (uint2*)w2_hi, (uint2*)w2_lo, n4);
        n4 = (NUM_PAIRS * 256 * 128) / 4;
        cvt_split_kernel<<<(n4 + 255) / 256, 256>>>(
            (const float4*)pair_w, (uint2*)pw_hi, (uint2*)pw_lo, n4);
        size_t nchunk = (size_t)NUM_PAIRS * BATCH * 16;
        build_xps_kernel<<<(unsigned)(nchunk / 256), 256>>>(pair_states, x_hi, x_lo);
    }

    // 3) h = attn @ V + b1  (tensor cores, 3-term, K=128)
    tc_gemm_kernel<3, 0><<<dim3(D_ALL / 128, BATCH / 128), 256, SMEM3>>>(
        a_hi, a_lo, V_hi, V_lo, fusion_b1, h, nullptr, nullptr,
        BATCH, D_ALL, 128, 128, D_ALL, D_ALL, 0);

    // 4) LN + GELU -> h_hi; GEMM2 (fp16 2-term) with fused xcat epilogue
    ln_gelu_kernel<<<BATCH, 512>>>(h, fusion_ln_g, fusion_ln_b, h_hi);
    tc_gemm_kernel<2, 1><<<dim3((D_ALL / 128) * (BATCH / 128), 1), 256, SMEM2>>>(
        h_hi, nullptr, w2_hi, w2_lo, fusion_b2, nullptr, x_hi, x_lo,
        BATCH, D_ALL, D_ALL, D_ALL, D_ALL, D_ALL, 1);

    // 5) per-pair linear + fused LN -> output
    pair_gemm_ln_kernel<<<dim3(BATCH / 128, NUM_PAIRS), 256, SMEMP>>>(
        x_hi, x_lo, pw_hi, pw_lo, pair_b, pair_ln_g, pair_ln_b, out);
}

// round 10
// speedup vs baseline: 9.6549x; 1.3000x over previous
#include <cuda_runtime.h>
#include <cuda_fp16.h>
#include <math.h>
#include <stdint.h>

// ---------------------------------------------------------------------------
// Problem constants
// ---------------------------------------------------------------------------
#define BATCH      4096
#define NUM_PAIRS  28
#define PAIR_DIM   128
#define MACRO_DIM  256
#define NUM_SLOTS  64
#define D_ALL      3584          // NUM_PAIRS * PAIR_DIM
#define D_CAT      7168          // 2 * D_ALL
#define LN_EPS     1e-5f

// ---------------------------------------------------------------------------
// Scratch (device globals: allocation-free per harness rules)
// ---------------------------------------------------------------------------
__device__ half  g_attn_hi[BATCH * 128];                      // [attn_p | attn_m]
__device__ half  g_attn_lo[BATCH * 128];
__device__ float g_V[(size_t)128 * D_ALL];                    // [Vp@W1top ; Vm@W1bot]
__device__ half  g_V_hi[(size_t)128 * D_ALL];
__device__ half  g_V_lo[(size_t)128 * D_ALL];
__device__ half  g_w2_hi[(size_t)D_ALL * D_ALL];
__device__ float g_h[(size_t)BATCH * D_ALL];
__device__ half  g_h_hi[(size_t)BATCH * D_ALL];
__device__ half  g_xcat_hi[(size_t)NUM_PAIRS * BATCH * 256];  // (p,b,256)
__device__ half  g_pw_hi[(size_t)NUM_PAIRS * 256 * 128];
__device__ half  g_pw_lo[(size_t)NUM_PAIRS * 256 * 128];

// ---------------------------------------------------------------------------
// Small helpers
// ---------------------------------------------------------------------------
__device__ __forceinline__ uint32_t smem_u32(const void* p) {
    uint32_t a;
    asm("{ .reg .u64 t; cvta.to.shared.u64 t, %1; cvt.u32.u64 %0, t; }" : "=r"(a) : "l"(p));
    return a;
}
__device__ __forceinline__ void cp16(uint32_t dst, const void* src) {
    asm volatile("cp.async.cg.shared.global [%0], [%1], 16;" :: "r"(dst), "l"(src));
}
__device__ __forceinline__ void cp_commit() {
    asm volatile("cp.async.commit_group;" ::: "memory");
}
__device__ __forceinline__ void cp_wait0() {
    asm volatile("cp.async.wait_group 0;" ::: "memory");
}
__device__ __forceinline__ void cp_wait1() {
    asm volatile("cp.async.wait_group 1;" ::: "memory");
}
__device__ __forceinline__ void ldsm_x4(uint32_t* r, uint32_t addr) {
    asm volatile("ldmatrix.sync.aligned.m8n8.x4.shared.b16 {%0,%1,%2,%3}, [%4];"
        : "=r"(r[0]), "=r"(r[1]), "=r"(r[2]), "=r"(r[3]) : "r"(addr));
}
__device__ __forceinline__ void ldsm_x2_trans(uint32_t* r, uint32_t addr) {
    asm volatile("ldmatrix.sync.aligned.m8n8.x2.trans.shared.b16 {%0,%1}, [%2];"
        : "=r"(r[0]), "=r"(r[1]) : "r"(addr));
}
__device__ __forceinline__ void mma_f16(float* c, const uint32_t* a, const uint32_t* b) {
    asm volatile(
        "mma.sync.aligned.m16n8k16.row.col.f32.f16.f16.f32 "
        "{%0,%1,%2,%3}, {%4,%5,%6,%7}, {%8,%9}, {%0,%1,%2,%3};"
        : "+f"(c[0]), "+f"(c[1]), "+f"(c[2]), "+f"(c[3])
        : "r"(a[0]), "r"(a[1]), "r"(a[2]), "r"(a[3]), "r"(b[0]), "r"(b[1]));
}
__device__ __forceinline__ void split_hl(float v, half& h, half& l) {
    h = __float2half_rn(v);
    l = __float2half_rn(v - __half2float(h));
}

// ---------------------------------------------------------------------------
// Tensor-core fp16 GEMM: 128x128 tile, BK=32, 3-stage cp.async, 2 CTAs/SM.
//   TERMS==1: D = Ahi*Bhi
//   TERMS==2: D = Ahi*(Bhi+Blo)
//   TERMS==3: D = Ahi*Bhi + Ahi*Blo + Alo*Bhi
//   XCAT==1: write fp16 (hi only) into xcat fused-half (p = n-tile, b, 256).
//   swz==1:  flat-grid L2 swizzle: 7 groups of (4 n-tiles x 32 m-tiles).
// ---------------------------------------------------------------------------
#define TCB_K   32
#define NSTAGE  3

template<int TERMS, int XCAT>
__global__ void __launch_bounds__(256, 2)
tc_gemm_kernel(const half* __restrict__ Ahi, const half* __restrict__ Alo,
               const half* __restrict__ Bhi, const half* __restrict__ Blo,
               const float* __restrict__ bias, float* __restrict__ C,
               half* __restrict__ Xhi,
               int M, int N, int K, int lda, int ldb, int ldc, int swz)
{
    constexpr int A_BYTES  = 10240;                    // 128 rows x 40 half
    constexpr int B_BYTES  = 8704;                     // 32 rows x 136 half
    constexpr int OFF_ALO  = A_BYTES;
    constexpr int OFF_BHI  = (TERMS == 3) ? 2 * A_BYTES : A_BYTES;
    constexpr int OFF_BLO  = OFF_BHI + B_BYTES;
    constexpr int STAGE    = (TERMS == 1) ? (OFF_BHI + B_BYTES)
                                          : (OFF_BLO + B_BYTES);

    extern __shared__ __align__(16) char sm[];
    const uint32_t smb = smem_u32(sm);

    int bx, by;
    if (swz) {
        int id = blockIdx.x;       // 896 blocks: 7 groups x (4 n x 32 m)
        int ng = id >> 7;
        int r  = id & 127;
        bx = ng * 4 + (r & 3);     // 0..27
        by = r >> 2;               // 0..31
    } else {
        bx = blockIdx.x; by = blockIdx.y;
    }

    const int tid  = threadIdx.x;
    const int wid  = tid >> 5;
    const int lane = tid & 31;
    const int wm   = wid & 1;
    const int wn   = wid >> 1;
    const int m0   = by * 128;
    const int n0   = bx * 128;

    const int tA = lane >> 3, rA = lane & 7;
    const int a_row_off = (tA & 1) * 8 + rA;
    const int a_kcol    = (tA >> 1) * 8;
    const uint32_t a_const = (uint32_t)((wm * 64 + a_row_off) * 40 + a_kcol) * 2;
    const int lB = lane & 15;
    const int b_krow = (lB >> 3) * 8 + (lB & 7);
    const uint32_t b_const = (uint32_t)(b_krow * 136 + wn * 32) * 2;

    float acc[4][4][4];
    #pragma unroll
    for (int i = 0; i < 4; i++)
        #pragma unroll
        for (int j = 0; j < 4; j++)
            #pragma unroll
            for (int q = 0; q < 4; q++) acc[i][j][q] = 0.f;

    const int nk = K / TCB_K;

    #define ISSUE_STAGE(slot, kt) do {                                         \
        uint32_t base = smb + (uint32_t)(slot) * STAGE;                        \
        int k0 = (kt) * TCB_K;                                                 \
        _Pragma("unroll")                                                      \
        for (int l = 0; l < 2; ++l) {                                          \
            int idx = tid + l * 256;                                           \
            int r = idx >> 2, c = idx & 3;                                     \
            cp16(base + r * 80 + c * 16,                                       \
                 Ahi + (size_t)(m0 + r) * lda + k0 + c * 8);                   \
            if constexpr (TERMS == 3)                                          \
                cp16(base + OFF_ALO + r * 80 + c * 16,                         \
                     Alo + (size_t)(m0 + r) * lda + k0 + c * 8);               \
        }                                                                      \
        _Pragma("unroll")                                                      \
        for (int l = 0; l < 2; ++l) {                                          \
            int idx = tid + l * 256;                                           \
            int r = idx >> 4, c = idx & 15;                                    \
            cp16(base + OFF_BHI + r * 272 + c * 16,                            \
                 Bhi + (size_t)(k0 + r) * ldb + n0 + c * 8);                   \
            if constexpr (TERMS >= 2)                                          \
                cp16(base + OFF_BLO + r * 272 + c * 16,                        \
                     Blo + (size_t)(k0 + r) * ldb + n0 + c * 8);               \
        }                                                                      \
    } while (0)

    ISSUE_STAGE(0, 0); cp_commit();
    ISSUE_STAGE(1, 1); cp_commit();

    for (int kt = 0; kt < nk; ++kt) {
        cp_wait1();
        __syncthreads();
        if (kt + 2 < nk) { ISSUE_STAGE((kt + 2) % NSTAGE, kt + 2); }
        cp_commit();

        const int slot = kt % NSTAGE;
        const uint32_t base = smb + (uint32_t)slot * STAGE;
        const uint32_t aHb = base + a_const;
        const uint32_t aLb = base + OFF_ALO + a_const;
        const uint32_t bHb = base + OFF_BHI + b_const;
        const uint32_t bLb = base + OFF_BLO + b_const;

        #pragma unroll
        for (int kk = 0; kk < 2; ++kk) {
            uint32_t aH[4][4], aL[4][4], bH[4][2], bL[4][2];
            const uint32_t akk = (uint32_t)(kk * 16 * 2);
            const uint32_t bkk = (uint32_t)(kk * 16 * 136 * 2);
            #pragma unroll
            for (int mf = 0; mf < 4; ++mf) {
                uint32_t off = (uint32_t)(mf * 16 * 40) * 2 + akk;
                ldsm_x4(aH[mf], aHb + off);
                if constexpr (TERMS == 3) ldsm_x4(aL[mf], aLb + off);
            }
            #pragma unroll
            for (int nf = 0; nf < 4; ++nf) {
                uint32_t off = (uint32_t)(nf * 8) * 2 + bkk;
                ldsm_x2_trans(bH[nf], bHb + off);
                if constexpr (TERMS >= 2) ldsm_x2_trans(bL[nf], bLb + off);
            }
            #pragma unroll
            for (int mf = 0; mf < 4; ++mf)
                #pragma unroll
                for (int nf = 0; nf < 4; ++nf) {
                    mma_f16(acc[mf][nf], aH[mf], bH[nf]);
                    if constexpr (TERMS >= 2) mma_f16(acc[mf][nf], aH[mf], bL[nf]);
                    if constexpr (TERMS == 3) mma_f16(acc[mf][nf], aL[mf], bH[nf]);
                }
        }
    }
    #undef ISSUE_STAGE

    const int g  = lane >> 2;
    const int tg = lane & 3;
    #pragma unroll
    for (int mf = 0; mf < 4; ++mf) {
        int r0 = m0 + wm * 64 + mf * 16 + g;
        #pragma unroll
        for (int nf = 0; nf < 4; ++nf) {
            int c = wn * 32 + nf * 8 + tg * 2;
            float b0 = bias[n0 + c], b1 = bias[n0 + c + 1];
            float v00 = acc[mf][nf][0] + b0, v01 = acc[mf][nf][1] + b1;
            float v10 = acc[mf][nf][2] + b0, v11 = acc[mf][nf][3] + b1;
            if constexpr (XCAT == 1) {
                // write xcat fused-half hi only: (p=bx, b, 128+c)
                size_t d0 = ((size_t)bx * BATCH + r0) * 256 + 128 + c;
                size_t d1 = ((size_t)bx * BATCH + r0 + 8) * 256 + 128 + c;
                *reinterpret_cast<half2*>(Xhi + d0) =
                    __halves2half2(__float2half_rn(v00), __float2half_rn(v01));
                *reinterpret_cast<half2*>(Xhi + d1) =
                    __halves2half2(__float2half_rn(v10), __float2half_rn(v11));
            } else {
                *reinterpret_cast<float2*>(C + (size_t)r0 * ldc + n0 + c) =
                    make_float2(v00, v01);
                *reinterpret_cast<float2*>(C + (size_t)(r0 + 8) * ldc + n0 + c) =
                    make_float2(v10, v11);
            }
        }
    }
}

// ---------------------------------------------------------------------------
// Pair GEMM + fused LayerNorm: per p (blockIdx.y), C-tile 128(b) x 128(e),
// K=256, 2-term (A-hi only; B = hi+lo), LN over the 128-wide row in epilogue.
// ---------------------------------------------------------------------------
__global__ void __launch_bounds__(256, 1)
pair_gemm_ln_kernel(const half* __restrict__ Xhi,
                    const half* __restrict__ PWhi, const half* __restrict__ PWlo,
                    const float* __restrict__ pb, const float* __restrict__ lng,
                    const float* __restrict__ lnb, float* __restrict__ out)
{
    constexpr int A_BYTES = 10240;
    constexpr int B_BYTES = 8704;
    constexpr int OFF_BHI = A_BYTES;
    constexpr int OFF_BLO = OFF_BHI + B_BYTES;
    constexpr int STAGE   = OFF_BLO + B_BYTES;   // 27648

    extern __shared__ __align__(16) char sm[];
    const uint32_t smb = smem_u32(sm);

    const int p   = blockIdx.y;
    const int m0  = blockIdx.x * 128;
    const int tid  = threadIdx.x;
    const int wid  = tid >> 5;
    const int lane = tid & 31;
    const int wm   = wid & 1;
    const int wn   = wid >> 1;

    const half* Ahi = Xhi + ((size_t)p * BATCH) * 256;
    const half* Bhi = PWhi + (size_t)p * 256 * 128;
    const half* Blo = PWlo + (size_t)p * 256 * 128;

    const int tA = lane >> 3, rA = lane & 7;
    const int a_row_off = (tA & 1) * 8 + rA;
    const int a_kcol    = (tA >> 1) * 8;
    const uint32_t a_const = (uint32_t)((wm * 64 + a_row_off) * 40 + a_kcol) * 2;
    const int lB = lane & 15;
    const int b_krow = (lB >> 3) * 8 + (lB & 7);
    const uint32_t b_const = (uint32_t)(b_krow * 136 + wn * 32) * 2;

    float acc[4][4][4];
    #pragma unroll
    for (int i = 0; i < 4; i++)
        #pragma unroll
        for (int j = 0; j < 4; j++)
            #pragma unroll
            for (int q = 0; q < 4; q++) acc[i][j][q] = 0.f;

    #define P_ISSUE(slot, kt) do {                                             \
        uint32_t base = smb + (uint32_t)(slot) * STAGE;                        \
        int k0 = (kt) * TCB_K;                                                 \
        _Pragma("unroll")                                                      \
        for (int l = 0; l < 2; ++l) {                                          \
            int idx = tid + l * 256;                                           \
            int r = idx >> 2, c = idx & 3;                                     \
            cp16(base + r * 80 + c * 16,                                       \
                 Ahi + (size_t)(m0 + r) * 256 + k0 + c * 8);                   \
        }                                                                      \
        _Pragma("unroll")                                                      \
        for (int l = 0; l < 2; ++l) {                                          \
            int idx = tid + l * 256;                                           \
            int r = idx >> 4, c = idx & 15;                                    \
            cp16(base + OFF_BHI + r * 272 + c * 16,                            \
                 Bhi + (size_t)(k0 + r) * 128 + c * 8);                        \
            cp16(base + OFF_BLO + r * 272 + c * 16,                            \
                 Blo + (size_t)(k0 + r) * 128 + c * 8);                        \
        }                                                                      \
    } while (0)

    P_ISSUE(0, 0); cp_commit();

    #pragma unroll
    for (int kt = 0; kt < 8; ++kt) {           // K=256 -> 8 iters of 32
        cp_wait0();
        __syncthreads();
        if (kt + 1 < 8) { P_ISSUE((kt + 1) & 1, kt + 1); cp_commit(); }

        const uint32_t base = smb + (uint32_t)(kt & 1) * STAGE;
        const uint32_t aHb = base + a_const;
        const uint32_t bHb = base + OFF_BHI + b_const;
        const uint32_t bLb = base + OFF_BLO + b_const;

        #pragma unroll
        for (int kk = 0; kk < 2; ++kk) {
            uint32_t aH[4][4], bH[4][2], bL[4][2];
            const uint32_t akk = (uint32_t)(kk * 16 * 2);
            const uint32_t bkk = (uint32_t)(kk * 16 * 136 * 2);
            #pragma unroll
            for (int mf = 0; mf < 4; ++mf) {
                uint32_t off = (uint32_t)(mf * 16 * 40) * 2 + akk;
                ldsm_x4(aH[mf], aHb + off);
            }
            #pragma unroll
            for (int nf = 0; nf < 4; ++nf) {
                uint32_t off = (uint32_t)(nf * 8) * 2 + bkk;
                ldsm_x2_trans(bH[nf], bHb + off);
                ldsm_x2_trans(bL[nf], bLb + off);
            }
            #pragma unroll
            for (int mf = 0; mf < 4; ++mf)
                #pragma unroll
                for (int nf = 0; nf < 4; ++nf) {
                    mma_f16(acc[mf][nf], aH[mf], bH[nf]);
                    mma_f16(acc[mf][nf], aH[mf], bL[nf]);
                }
        }
    }
    #undef P_ISSUE

    // ---- epilogue: stage (bias-added) outputs in smem, then LN per row
    __syncthreads();                       // done with stage buffers
    float* os = reinterpret_cast<float*>(sm);   // [128][132]
    const int g  = lane >> 2;
    const int tg = lane & 3;
    #pragma unroll
    for (int mf = 0; mf < 4; ++mf) {
        int r0 = wm * 64 + mf * 16 + g;
        #pragma unroll
        for (int nf = 0; nf < 4; ++nf) {
            int c = wn * 32 + nf * 8 + tg * 2;
            float b0 = pb[p * 128 + c], b1 = pb[p * 128 + c + 1];
            os[r0 * 132 + c]           = acc[mf][nf][0] + b0;
            os[r0 * 132 + c + 1]       = acc[mf][nf][1] + b1;
            os[(r0 + 8) * 132 + c]     = acc[mf][nf][2] + b0;
            os[(r0 + 8) * 132 + c + 1] = acc[mf][nf][3] + b1;
        }
    }
    __syncthreads();

    #pragma unroll
    for (int rr = 0; rr < 16; ++rr) {
        int r = wid * 16 + rr;
        const float* t = os + r * 132;
        float v0 = t[lane], v1 = t[lane + 32], v2 = t[lane + 64], v3 = t[lane + 96];
        float s = v0 + v1 + v2 + v3;
        #pragma unroll
        for (int o = 16; o > 0; o >>= 1) s += __shfl_xor_sync(0xffffffff, s, o);
        float mu = s * (1.0f / 128.0f);
        float d0 = v0 - mu, d1 = v1 - mu, d2 = v2 - mu, d3 = v3 - mu;
        float s2 = d0 * d0 + d1 * d1 + d2 * d2 + d3 * d3;
        #pragma unroll
        for (int o = 16; o > 0; o >>= 1) s2 += __shfl_xor_sync(0xffffffff, s2, o);
        float rstd = rsqrtf(s2 * (1.0f / 128.0f) + LN_EPS);

        int b = m0 + r;
        size_t base = (size_t)b * D_ALL + p * 128;
        int gi = p * 128;
        out[base + lane]      = d0 * rstd * lng[gi + lane]      + lnb[gi + lane];
        out[base + lane + 32] = d1 * rstd * lng[gi + lane + 32] + lnb[gi + lane + 32];
        out[base + lane + 64] = d2 * rstd * lng[gi + lane + 64] + lnb[gi + lane + 64];
        out[base + lane + 96] = d3 * rstd * lng[gi + lane + 96] + lnb[gi + lane + 96];
    }
}

// ---------------------------------------------------------------------------
// fp32 -> fp16 hi/lo split (elementwise, vectorized)
// ---------------------------------------------------------------------------
__global__ __launch_bounds__(256) void cvt_split_kernel(
    const float4* __restrict__ x, uint2* __restrict__ hi, uint2* __restrict__ lo, int n4)
{
    int i = blockIdx.x * 256 + threadIdx.x;
    if (i >= n4) return;
    float4 v = x[i];
    half h0, l0, h1, l1, h2, l2, h3, l3;
    split_hl(v.x, h0, l0); split_hl(v.y, h1, l1);
    split_hl(v.z, h2, l2); split_hl(v.w, h3, l3);
    half2 ha = __halves2half2(h0, h1), hb = __halves2half2(h2, h3);
    half2 la = __halves2half2(l0, l1), lb = __halves2half2(l2, l3);
    hi[i] = make_uint2(*reinterpret_cast<uint32_t*>(&ha), *reinterpret_cast<uint32_t*>(&hb));
    lo[i] = make_uint2(*reinterpret_cast<uint32_t*>(&la), *reinterpret_cast<uint32_t*>(&lb));
}

// fp32 -> fp16 hi only
__global__ __launch_bounds__(256) void cvt_hi_kernel(
    const float4* __restrict__ x, uint2* __restrict__ hi, int n4)
{
    int i = blockIdx.x * 256 + threadIdx.x;
    if (i >= n4) return;
    float4 v = x[i];
    half2 ha = __halves2half2(__float2half_rn(v.x), __float2half_rn(v.y));
    half2 hb = __halves2half2(__float2half_rn(v.z), __float2half_rn(v.w));
    hi[i] = make_uint2(*reinterpret_cast<uint32_t*>(&ha), *reinterpret_cast<uint32_t*>(&hb));
}

// ---------------------------------------------------------------------------
// attention weight kernels -> g_attn_hi/lo (B, 128): [pair | macro]
// ---------------------------------------------------------------------------
__global__ __launch_bounds__(128) void attn_pair_kernel(
    const float* __restrict__ ps, const float* __restrict__ keys,
    half* __restrict__ ahi, half* __restrict__ alo)
{
    int b = blockIdx.x, tid = threadIdx.x;
    __shared__ float q[PAIR_DIM];
    __shared__ float sc[NUM_SLOTS];
    __shared__ float red[NUM_SLOTS];

    float s = 0.f;
    #pragma unroll
    for (int p = 0; p < NUM_PAIRS; p++)
        s += ps[(size_t)b * D_ALL + p * PAIR_DIM + tid];
    q[tid] = s * (1.0f / NUM_PAIRS);
    __syncthreads();

    if (tid < NUM_SLOTS) {
        float acc = 0.f;
        #pragma unroll 4
        for (int d = 0; d < PAIR_DIM; d++)
            acc = fmaf(q[d], keys[tid * PAIR_DIM + d], acc);
        sc[tid] = acc * 0.08838834764831845f;
    }
    __syncthreads();

    if (tid < NUM_SLOTS) red[tid] = sc[tid];
    __syncthreads();
    for (int o = 32; o > 0; o >>= 1) {
        if (tid < o) red[tid] = fmaxf(red[tid], red[tid + o]);
        __syncthreads();
    }
    float mx = red[0];
    __syncthreads();

    float e = 0.f;
    if (tid < NUM_SLOTS) { e = expf(sc[tid] - mx); red[tid] = e; }
    __syncthreads();
    for (int o = 32; o > 0; o >>= 1) {
        if (tid < o) red[tid] += red[tid + o];
        __syncthreads();
    }
    if (tid < NUM_SLOTS) {
        half h, l;
        split_hl(e / red[0], h, l);
        ahi[(size_t)b * 128 + tid] = h;
        alo[(size_t)b * 128 + tid] = l;
    }
}

__global__ __launch_bounds__(128) void attn_macro_kernel(
    const float* __restrict__ ms, const float* __restrict__ keys,
    half* __restrict__ ahi, half* __restrict__ alo)
{
    int b = blockIdx.x, tid = threadIdx.x;
    __shared__ float q[MACRO_DIM];
    __shared__ float sc[NUM_SLOTS];
    __shared__ float red[NUM_SLOTS];

    q[tid]       = ms[(size_t)b * MACRO_DIM + tid];
    q[tid + 128] = ms[(size_t)b * MACRO_DIM + tid + 128];
    __syncthreads();

    if (tid < NUM_SLOTS) {
        float acc = 0.f;
        #pragma unroll 4
        for (int d = 0; d < MACRO_DIM; d++)
            acc = fmaf(q[d], keys[tid * MACRO_DIM + d], acc);
        sc[tid] = acc * 0.0625f;
    }
    __syncthreads();

    if (tid < NUM_SLOTS) red[tid] = sc[tid];
    __syncthreads();
    for (int o = 32; o > 0; o >>= 1) {
        if (tid < o) red[tid] = fmaxf(red[tid], red[tid + o]);
        __syncthreads();
    }
    float mx = red[0];
    __syncthreads();

    float e = 0.f;
    if (tid < NUM_SLOTS) { e = expf(sc[tid] - mx); red[tid] = e; }
    __syncthreads();
    for (int o = 32; o > 0; o >>= 1) {
        if (tid < o) red[tid] += red[tid + o];
        __syncthreads();
    }
    if (tid < NUM_SLOTS) {
        half h, l;
        split_hl(e / red[0], h, l);
        ahi[(size_t)b * 128 + 64 + tid] = h;
        alo[(size_t)b * 128 + 64 + tid] = l;
    }
}

// ---------------------------------------------------------------------------
// Zero kernel (for g_V before atomic fold)
// ---------------------------------------------------------------------------
__global__ __launch_bounds__(256) void zero_kernel(float* __restrict__ p, int n)
{
    int i = blockIdx.x * 256 + threadIdx.x;
    if (i < n) p[i] = 0.f;
}

// ---------------------------------------------------------------------------
// Fold v4: V[z*64 + m, n] += sum_k vals_z[m,k] * W1[z*3584 + k, n]
// Tile 64(M) x 128(N), BK=16, split-K=16, 3-stage cp.async (wait1 overlap).
// 256 threads (8 warps x 8 rows; 32 lanes x 4 cols), micro 8x4. 4 CTAs/SM.
// ---------------------------------------------------------------------------
#define FK_KS   16
#define FK_KCH  (D_ALL / FK_KS)    // 224
#define FK_BK   16
#define FK_BN   128
#define FK_AS_B   5120
#define FK_STAGE  13568
#define FK_NST    3

__global__ __launch_bounds__(256, 4) void fold_kernel(
    const float* __restrict__ vals_p, const float* __restrict__ vals_m,
    const float* __restrict__ w1, float* __restrict__ V)
{
    extern __shared__ __align__(16) char sm[];
    const uint32_t smb = smem_u32(sm);

    const int nb = blockIdx.x;
    const int ks = blockIdx.y;
    const int z  = blockIdx.z;
    const float* vals = z ? vals_m : vals_p;
    const float* W    = w1 + (size_t)z * D_ALL * D_ALL;
    float* Vout       = V  + (size_t)z * 64 * D_ALL;

    const int tid = threadIdx.x;
    const int ty  = tid >> 5;
    const int tx  = tid & 31;
    const int n0  = nb * FK_BN;
    const int kb  = ks * FK_KCH;

    float acc[8][4];
    #pragma unroll
    for (int i = 0; i < 8; i++)
        #pragma unroll
        for (int j = 0; j < 4; j++) acc[i][j] = 0.f;

    #define FK_ISSUE(slot, k0) do {                                            \
        uint32_t base = smb + (uint32_t)(slot) * FK_STAGE;                     \
        {   int m = tid >> 2, c = tid & 3;                                     \
            cp16(base + m * 80 + c * 16,                                       \
                 vals + (size_t)m * D_ALL + (k0) + c * 4); }                   \
        _Pragma("unroll")                                                      \
        for (int l = 0; l < 2; ++l) {                                          \
            int idx = tid + l * 256;                                           \
            int r = idx >> 5, c4 = idx & 31;                                   \
            cp16(base + FK_AS_B + r * 528 + c4 * 16,                           \
                 W + (size_t)((k0) + r) * D_ALL + n0 + c4 * 4); }              \
    } while (0)

    FK_ISSUE(0, kb); cp_commit();
    FK_ISSUE(1, kb + FK_BK); cp_commit();

    const int niter = FK_KCH / FK_BK;   // 14
    for (int it = 0; it < niter; ++it) {
        cp_wait1();
        __syncthreads();
        if (it + 2 < niter) { FK_ISSUE((it + 2) % FK_NST, kb + (it + 2) * FK_BK); }
        cp_commit();

        const int slot = it % FK_NST;
        const float* As = reinterpret_cast<const float*>(sm + slot * FK_STAGE);
        const float* Bs = reinterpret_cast<const float*>(sm + slot * FK_STAGE + FK_AS_B);

        #pragma unroll
        for (int kk = 0; kk < FK_BK; ++kk) {
            float a[8];
            #pragma unroll
            for (int i = 0; i < 8; i++) a[i] = As[(ty * 8 + i) * 20 + kk];
            float4 bq = *reinterpret_cast<const float4*>(Bs + kk * 132 + tx * 4);
            float b[4] = {bq.x, bq.y, bq.z, bq.w};
            #pragma unroll
            for (int i = 0; i < 8; i++)
                #pragma unroll
                for (int j = 0; j < 4; j++)
                    acc[i][j] = fmaf(a[i], b[j], acc[i][j]);
        }
    }
    #undef FK_ISSUE

    #pragma unroll
    for (int i = 0; i < 8; i++) {
        int m = ty * 8 + i;
        #pragma unroll
        for (int j = 0; j < 4; j++)
            atomicAdd(Vout + (size_t)m * D_ALL + n0 + tx * 4 + j, acc[i][j]);
    }
}

// ---------------------------------------------------------------------------
// LayerNorm + exact GELU over rows of length D_ALL; writes fp16 hi.
// ---------------------------------------------------------------------------
__global__ __launch_bounds__(512) void ln_gelu_kernel(
    const float* __restrict__ h, const float* __restrict__ g, const float* __restrict__ b,
    half* __restrict__ ohi)
{
    __shared__ float row[D_ALL];
    __shared__ float reds[16], reds2[16];
    int bi = blockIdx.x, tid = threadIdx.x;
    const float4* hrow = reinterpret_cast<const float4*>(h + (size_t)bi * D_ALL);
    float4* rowv = reinterpret_cast<float4*>(row);

    float s = 0.f, s2 = 0.f;
    for (int i = tid; i < D_ALL / 4; i += 512) {
        float4 v = hrow[i];
        rowv[i] = v;
        s  += v.x + v.y + v.z + v.w;
        s2 += v.x * v.x + v.y * v.y + v.z * v.z + v.w * v.w;
    }
    #pragma unroll
    for (int o = 16; o > 0; o >>= 1) {
        s  += __shfl_xor_sync(0xffffffff, s, o);
        s2 += __shfl_xor_sync(0xffffffff, s2, o);
    }
    int warp = tid >> 5, lane = tid & 31;
    if (lane == 0) { reds[warp] = s; reds2[warp] = s2; }
    __syncthreads();
    if (warp == 0) {
        float a = (lane < 16) ? reds[lane] : 0.f;
        float a2 = (lane < 16) ? reds2[lane] : 0.f;
        #pragma unroll
        for (int o = 8; o > 0; o >>= 1) {
            a  += __shfl_xor_sync(0xffffffff, a, o);
            a2 += __shfl_xor_sync(0xffffffff, a2, o);
        }
        if (lane == 0) { reds[0] = a; reds2[0] = a2; }
    }
    __syncthreads();
    float mu = reds[0] * (1.0f / D_ALL);
    float var = reds2[0] * (1.0f / D_ALL) - mu * mu;
    float rstd = rsqrtf(var + LN_EPS);

    half* orow = ohi + (size_t)bi * D_ALL;
    for (int i = tid; i < D_ALL / 4; i += 512) {
        float4 v = rowv[i];
        float4 gg = reinterpret_cast<const float4*>(g)[i];
        float4 bb = reinterpret_cast<const float4*>(b)[i];
        float y0 = (v.x - mu) * rstd * gg.x + bb.x;
        float y1 = (v.y - mu) * rstd * gg.y + bb.y;
        float y2 = (v.z - mu) * rstd * gg.z + bb.z;
        float y3 = (v.w - mu) * rstd * gg.w + bb.w;
        const float k = 0.70710678118654752f;
        half o0 = __float2half_rn(0.5f * y0 * (1.0f + erff(y0 * k)));
        half o1 = __float2half_rn(0.5f * y1 * (1.0f + erff(y1 * k)));
        half o2 = __float2half_rn(0.5f * y2 * (1.0f + erff(y2 * k)));
        half o3 = __float2half_rn(0.5f * y3 * (1.0f + erff(y3 * k)));
        half h4[4] = {o0, o1, o2, o3};
        *reinterpret_cast<uint2*>(orow + i * 4) = *reinterpret_cast<uint2*>(h4);
    }
}

// ---------------------------------------------------------------------------
// Build xcat pair_states half (hi only): (p, b, 0..128)
// ---------------------------------------------------------------------------
__global__ __launch_bounds__(256) void build_xps_kernel(
    const float* __restrict__ ps, half* __restrict__ xhi)
{
    size_t i = (size_t)blockIdx.x * 256 + threadIdx.x;   // 8-elem chunk id
    int kc = (int)(i & 15);
    size_t pb = i >> 4;
    int b = (int)(pb & 4095);
    int p = (int)(pb >> 12);
    const float* src = ps + (size_t)b * D_ALL + p * 128 + kc * 8;
    half h[8];
    #pragma unroll
    for (int j = 0; j < 8; j++) h[j] = __float2half_rn(src[j]);
    size_t dst = ((size_t)p * BATCH + b) * 256 + kc * 8;
    *reinterpret_cast<uint4*>(xhi + dst) = *reinterpret_cast<uint4*>(h);
}

// ---------------------------------------------------------------------------
// Launch
// ---------------------------------------------------------------------------
extern "C" void kernel_launch(void* const* d_in, const int* in_sizes, int n_in,
                              void* d_out, int out_size)
{
    const float* pair_states    = (const float*)d_in[0];
    const float* macro_state    = (const float*)d_in[1];
    const float* mem_pair_keys  = (const float*)d_in[2];
    const float* mem_pair_vals  = (const float*)d_in[3];
    const float* mem_macro_keys = (const float*)d_in[4];
    const float* mem_macro_vals = (const float*)d_in[5];
    const float* fusion_w1      = (const float*)d_in[6];
    const float* fusion_b1      = (const float*)d_in[7];
    const float* fusion_ln_g    = (const float*)d_in[8];
    const float* fusion_ln_b    = (const float*)d_in[9];
    const float* fusion_w2      = (const float*)d_in[10];
    const float* fusion_b2      = (const float*)d_in[11];
    const float* pair_w         = (const float*)d_in[12];
    const float* pair_b         = (const float*)d_in[13];
    const float* pair_ln_g      = (const float*)d_in[14];
    const float* pair_ln_b      = (const float*)d_in[15];
    float* out = (float*)d_out;

    float *V, *h;
    half *a_hi, *a_lo, *V_hi, *V_lo, *w2_hi, *h_hi;
    half *x_hi, *pw_hi, *pw_lo;
    cudaGetSymbolAddress((void**)&a_hi,  g_attn_hi);
    cudaGetSymbolAddress((void**)&a_lo,  g_attn_lo);
    cudaGetSymbolAddress((void**)&V,     g_V);
    cudaGetSymbolAddress((void**)&V_hi,  g_V_hi);
    cudaGetSymbolAddress((void**)&V_lo,  g_V_lo);
    cudaGetSymbolAddress((void**)&w2_hi, g_w2_hi);
    cudaGetSymbolAddress((void**)&h,     g_h);
    cudaGetSymbolAddress((void**)&h_hi,  g_h_hi);
    cudaGetSymbolAddress((void**)&x_hi,  g_xcat_hi);
    cudaGetSymbolAddress((void**)&pw_hi, g_pw_hi);
    cudaGetSymbolAddress((void**)&pw_lo, g_pw_lo);

    const int SMEM1 = NSTAGE * 18944;            // 56832 (1-term)
    const int SMEM3 = NSTAGE * 37888;            // 113664 (3-term)
    const int SMEMP = 128 * 132 * 4;             // 67584 (pair: os > 2 stages)
    const int SMEMF = FK_NST * FK_STAGE;         // 40704 (fold, 3-stage)
    cudaFuncSetAttribute(tc_gemm_kernel<1, 1>,
                         cudaFuncAttributeMaxDynamicSharedMemorySize, SMEM1);
    cudaFuncSetAttribute(tc_gemm_kernel<3, 0>,
                         cudaFuncAttributeMaxDynamicSharedMemorySize, SMEM3);
    cudaFuncSetAttribute(pair_gemm_ln_kernel,
                         cudaFuncAttributeMaxDynamicSharedMemorySize, SMEMP);
    cudaFuncSetAttribute(fold_kernel,
                         cudaFuncAttributeMaxDynamicSharedMemorySize, SMEMF);

    // 1) attention weights -> fp16 hi/lo (B, 128)
    attn_pair_kernel<<<BATCH, 128>>>(pair_states, mem_pair_keys, a_hi, a_lo);
    attn_macro_kernel<<<BATCH, 128>>>(macro_state, mem_macro_keys, a_hi, a_lo);

    // 2) fold: V = [vals_p @ W1top ; vals_m @ W1bot]  (128 x 3584 fp32)
    zero_kernel<<<(128 * D_ALL + 255) / 256, 256>>>(V, 128 * D_ALL);
    fold_kernel<<<dim3(D_ALL / FK_BN, FK_KS, 2), 256, SMEMF>>>(
        mem_pair_vals, mem_macro_vals, fusion_w1, V);
    {
        int n4 = (128 * D_ALL) / 4;
        cvt_split_kernel<<<(n4 + 255) / 256, 256>>>(
            (const float4*)V, (uint2*)V_hi, (uint2*)V_lo, n4);
    }

    // 2b) weight converts (w2 hi-only, pair_w hi/lo); xcat pair_states half
    {
        int n4 = (D_ALL * D_ALL) / 4;
        cvt_hi_kernel<<<(n4 + 255) / 256, 256>>>(
            (const float4*)fusion_w2, (uint2*)w2_hi, n4);
        n4 = (NUM_PAIRS * 256 * 128) / 4;
        cvt_split_kernel<<<(n4 + 255) / 256, 256>>>(
            (const float4*)pair_w, (uint2*)pw_hi, (uint2*)pw_lo, n4);
        size_t nchunk = (size_t)NUM_PAIRS * BATCH * 16;
        build_xps_kernel<<<(unsigned)(nchunk / 256), 256>>>(pair_states, x_hi);
    }

    // 3) h = attn @ V + b1  (tensor cores, 3-term, K=128)
    tc_gemm_kernel<3, 0><<<dim3(D_ALL / 128, BATCH / 128), 256, SMEM3>>>(
        a_hi, a_lo, V_hi, V_lo, fusion_b1, h, nullptr,
        BATCH, D_ALL, 128, 128, D_ALL, D_ALL, 0);

    // 4) LN + GELU -> h_hi; GEMM2 (fp16 1-term) with fused xcat epilogue
    ln_gelu_kernel<<<BATCH, 512>>>(h, fusion_ln_g, fusion_ln_b, h_hi);
    tc_gemm_kernel<1, 1><<<dim3((D_ALL / 128) * (BATCH / 128), 1), 256, SMEM1>>>(
        h_hi, nullptr, w2_hi, nullptr, fusion_b2, nullptr, x_hi,
        BATCH, D_ALL, D_ALL, D_ALL, D_ALL, D_ALL, 1);

    // 5) per-pair linear (2-term, A-hi) + fused LN -> output
    pair_gemm_ln_kernel<<<dim3(BATCH / 128, NUM_PAIRS), 256, SMEMP>>>(
        x_hi, pw_hi, pw_lo, pair_b, pair_ln_g, pair_ln_b, out);
}

// round 11
// speedup vs baseline: 10.1485x; 1.0511x over previous
#include <cuda_runtime.h>
#include <cuda_fp16.h>
#include <math.h>
#include <stdint.h>

// ---------------------------------------------------------------------------
// Problem constants
// ---------------------------------------------------------------------------
#define BATCH      4096
#define NUM_PAIRS  28
#define PAIR_DIM   128
#define MACRO_DIM  256
#define NUM_SLOTS  64
#define D_ALL      3584          // NUM_PAIRS * PAIR_DIM
#define D_CAT      7168          // 2 * D_ALL
#define LN_EPS     1e-5f

// ---------------------------------------------------------------------------
// Scratch (device globals: allocation-free per harness rules)
// ---------------------------------------------------------------------------
__device__ half  g_attn_hi[BATCH * 128];                      // [attn_p | attn_m]
__device__ half  g_attn_lo[BATCH * 128];
__device__ float g_V[(size_t)128 * D_ALL];                    // [Vp@W1top ; Vm@W1bot]
__device__ half  g_V_hi[(size_t)128 * D_ALL];
__device__ half  g_V_lo[(size_t)128 * D_ALL];
__device__ half  g_w2_hi[(size_t)D_ALL * D_ALL];
__device__ float g_h[(size_t)BATCH * D_ALL];
__device__ half  g_h_hi[(size_t)BATCH * D_ALL];
__device__ half  g_xcat_hi[(size_t)NUM_PAIRS * BATCH * 256];  // (p,b,256)
__device__ half  g_pw_hi[(size_t)NUM_PAIRS * 256 * 128];

// ---------------------------------------------------------------------------
// Small helpers
// ---------------------------------------------------------------------------
__device__ __forceinline__ uint32_t smem_u32(const void* p) {
    uint32_t a;
    asm("{ .reg .u64 t; cvta.to.shared.u64 t, %1; cvt.u32.u64 %0, t; }" : "=r"(a) : "l"(p));
    return a;
}
__device__ __forceinline__ void cp16(uint32_t dst, const void* src) {
    asm volatile("cp.async.cg.shared.global [%0], [%1], 16;" :: "r"(dst), "l"(src));
}
__device__ __forceinline__ void cp_commit() {
    asm volatile("cp.async.commit_group;" ::: "memory");
}
__device__ __forceinline__ void cp_wait0() {
    asm volatile("cp.async.wait_group 0;" ::: "memory");
}
__device__ __forceinline__ void cp_wait1() {
    asm volatile("cp.async.wait_group 1;" ::: "memory");
}
__device__ __forceinline__ void ldsm_x4(uint32_t* r, uint32_t addr) {
    asm volatile("ldmatrix.sync.aligned.m8n8.x4.shared.b16 {%0,%1,%2,%3}, [%4];"
        : "=r"(r[0]), "=r"(r[1]), "=r"(r[2]), "=r"(r[3]) : "r"(addr));
}
__device__ __forceinline__ void ldsm_x2_trans(uint32_t* r, uint32_t addr) {
    asm volatile("ldmatrix.sync.aligned.m8n8.x2.trans.shared.b16 {%0,%1}, [%2];"
        : "=r"(r[0]), "=r"(r[1]) : "r"(addr));
}
__device__ __forceinline__ void mma_f16(float* c, const uint32_t* a, const uint32_t* b) {
    asm volatile(
        "mma.sync.aligned.m16n8k16.row.col.f32.f16.f16.f32 "
        "{%0,%1,%2,%3}, {%4,%5,%6,%7}, {%8,%9}, {%0,%1,%2,%3};"
        : "+f"(c[0]), "+f"(c[1]), "+f"(c[2]), "+f"(c[3])
        : "r"(a[0]), "r"(a[1]), "r"(a[2]), "r"(a[3]), "r"(b[0]), "r"(b[1]));
}
__device__ __forceinline__ void split_hl(float v, half& h, half& l) {
    h = __float2half_rn(v);
    l = __float2half_rn(v - __half2float(h));
}

// ---------------------------------------------------------------------------
// Tensor-core fp16 GEMM: 128x128 tile, BK=32, NST-stage cp.async, 2 CTAs/SM.
//   TERMS==1: D = Ahi*Bhi
//   TERMS==2: D = Ahi*(Bhi+Blo)
//   TERMS==3: D = Ahi*Bhi + Ahi*Blo + Alo*Bhi
//   XCAT==1: write fp16 (hi only) into xcat fused-half (p = n-tile, b, 256).
//   swz==1:  flat-grid L2 swizzle: 7 groups of (4 n-tiles x 32 m-tiles).
// ---------------------------------------------------------------------------
#define TCB_K   32

template<int TERMS, int XCAT, int NST>
__global__ void __launch_bounds__(256, 2)
tc_gemm_kernel(const half* __restrict__ Ahi, const half* __restrict__ Alo,
               const half* __restrict__ Bhi, const half* __restrict__ Blo,
               const float* __restrict__ bias, float* __restrict__ C,
               half* __restrict__ Xhi,
               int M, int N, int K, int lda, int ldb, int ldc, int swz)
{
    constexpr int A_BYTES  = 10240;                    // 128 rows x 40 half
    constexpr int B_BYTES  = 8704;                     // 32 rows x 136 half
    constexpr int OFF_ALO  = A_BYTES;
    constexpr int OFF_BHI  = (TERMS == 3) ? 2 * A_BYTES : A_BYTES;
    constexpr int OFF_BLO  = OFF_BHI + B_BYTES;
    constexpr int STAGE    = (TERMS == 1) ? (OFF_BHI + B_BYTES)
                                          : (OFF_BLO + B_BYTES);

    extern __shared__ __align__(16) char sm[];
    const uint32_t smb = smem_u32(sm);

    int bx, by;
    if (swz) {
        int id = blockIdx.x;       // 896 blocks: 7 groups x (4 n x 32 m)
        int ng = id >> 7;
        int r  = id & 127;
        bx = ng * 4 + (r & 3);     // 0..27
        by = r >> 2;               // 0..31
    } else {
        bx = blockIdx.x; by = blockIdx.y;
    }

    const int tid  = threadIdx.x;
    const int wid  = tid >> 5;
    const int lane = tid & 31;
    const int wm   = wid & 1;
    const int wn   = wid >> 1;
    const int m0   = by * 128;
    const int n0   = bx * 128;

    const int tA = lane >> 3, rA = lane & 7;
    const int a_row_off = (tA & 1) * 8 + rA;
    const int a_kcol    = (tA >> 1) * 8;
    const uint32_t a_const = (uint32_t)((wm * 64 + a_row_off) * 40 + a_kcol) * 2;
    const int lB = lane & 15;
    const int b_krow = (lB >> 3) * 8 + (lB & 7);
    const uint32_t b_const = (uint32_t)(b_krow * 136 + wn * 32) * 2;

    float acc[4][4][4];
    #pragma unroll
    for (int i = 0; i < 4; i++)
        #pragma unroll
        for (int j = 0; j < 4; j++)
            #pragma unroll
            for (int q = 0; q < 4; q++) acc[i][j][q] = 0.f;

    const int nk = K / TCB_K;

    #define ISSUE_STAGE(slot, kt) do {                                         \
        uint32_t base = smb + (uint32_t)(slot) * STAGE;                        \
        int k0 = (kt) * TCB_K;                                                 \
        _Pragma("unroll")                                                      \
        for (int l = 0; l < 2; ++l) {                                          \
            int idx = tid + l * 256;                                           \
            int r = idx >> 2, c = idx & 3;                                     \
            cp16(base + r * 80 + c * 16,                                       \
                 Ahi + (size_t)(m0 + r) * lda + k0 + c * 8);                   \
            if constexpr (TERMS == 3)                                          \
                cp16(base + OFF_ALO + r * 80 + c * 16,                         \
                     Alo + (size_t)(m0 + r) * lda + k0 + c * 8);               \
        }                                                                      \
        _Pragma("unroll")                                                      \
        for (int l = 0; l < 2; ++l) {                                          \
            int idx = tid + l * 256;                                           \
            int r = idx >> 4, c = idx & 15;                                    \
            cp16(base + OFF_BHI + r * 272 + c * 16,                            \
                 Bhi + (size_t)(k0 + r) * ldb + n0 + c * 8);                   \
            if constexpr (TERMS >= 2)                                          \
                cp16(base + OFF_BLO + r * 272 + c * 16,                        \
                     Blo + (size_t)(k0 + r) * ldb + n0 + c * 8);               \
        }                                                                      \
    } while (0)

    #pragma unroll
    for (int s = 0; s < NST - 1; ++s) {
        if (s < nk) ISSUE_STAGE(s, s);
        cp_commit();
    }

    for (int kt = 0; kt < nk; ++kt) {
        asm volatile("cp.async.wait_group %0;" :: "n"(NST - 2) : "memory");
        __syncthreads();
        if (kt + NST - 1 < nk) { ISSUE_STAGE((kt + NST - 1) % NST, kt + NST - 1); }
        cp_commit();

        const int slot = kt % NST;
        const uint32_t base = smb + (uint32_t)slot * STAGE;
        const uint32_t aHb = base + a_const;
        const uint32_t aLb = base + OFF_ALO + a_const;
        const uint32_t bHb = base + OFF_BHI + b_const;
        const uint32_t bLb = base + OFF_BLO + b_const;

        #pragma unroll
        for (int kk = 0; kk < 2; ++kk) {
            uint32_t aH[4][4], aL[4][4], bH[4][2], bL[4][2];
            const uint32_t akk = (uint32_t)(kk * 16 * 2);
            const uint32_t bkk = (uint32_t)(kk * 16 * 136 * 2);
            #pragma unroll
            for (int mf = 0; mf < 4; ++mf) {
                uint32_t off = (uint32_t)(mf * 16 * 40) * 2 + akk;
                ldsm_x4(aH[mf], aHb + off);
                if constexpr (TERMS == 3) ldsm_x4(aL[mf], aLb + off);
            }
            #pragma unroll
            for (int nf = 0; nf < 4; ++nf) {
                uint32_t off = (uint32_t)(nf * 8) * 2 + bkk;
                ldsm_x2_trans(bH[nf], bHb + off);
                if constexpr (TERMS >= 2) ldsm_x2_trans(bL[nf], bLb + off);
            }
            #pragma unroll
            for (int mf = 0; mf < 4; ++mf)
                #pragma unroll
                for (int nf = 0; nf < 4; ++nf) {
                    mma_f16(acc[mf][nf], aH[mf], bH[nf]);
                    if constexpr (TERMS >= 2) mma_f16(acc[mf][nf], aH[mf], bL[nf]);
                    if constexpr (TERMS == 3) mma_f16(acc[mf][nf], aL[mf], bH[nf]);
                }
        }
    }
    #undef ISSUE_STAGE

    const int g  = lane >> 2;
    const int tg = lane & 3;
    #pragma unroll
    for (int mf = 0; mf < 4; ++mf) {
        int r0 = m0 + wm * 64 + mf * 16 + g;
        #pragma unroll
        for (int nf = 0; nf < 4; ++nf) {
            int c = wn * 32 + nf * 8 + tg * 2;
            float b0 = bias[n0 + c], b1 = bias[n0 + c + 1];
            float v00 = acc[mf][nf][0] + b0, v01 = acc[mf][nf][1] + b1;
            float v10 = acc[mf][nf][2] + b0, v11 = acc[mf][nf][3] + b1;
            if constexpr (XCAT == 1) {
                size_t d0 = ((size_t)bx * BATCH + r0) * 256 + 128 + c;
                size_t d1 = ((size_t)bx * BATCH + r0 + 8) * 256 + 128 + c;
                *reinterpret_cast<half2*>(Xhi + d0) =
                    __halves2half2(__float2half_rn(v00), __float2half_rn(v01));
                *reinterpret_cast<half2*>(Xhi + d1) =
                    __halves2half2(__float2half_rn(v10), __float2half_rn(v11));
            } else {
                *reinterpret_cast<float2*>(C + (size_t)r0 * ldc + n0 + c) =
                    make_float2(v00, v01);
                *reinterpret_cast<float2*>(C + (size_t)(r0 + 8) * ldc + n0 + c) =
                    make_float2(v10, v11);
            }
        }
    }
}

// ---------------------------------------------------------------------------
// Pair GEMM + fused LayerNorm: per p (blockIdx.y), C-tile 128(b) x 128(e),
// K=256, 1-term (A-hi x B-hi), LN over the 128-wide row in the epilogue.
// 2 CTAs/SM.
// ---------------------------------------------------------------------------
__global__ void __launch_bounds__(256, 2)
pair_gemm_ln_kernel(const half* __restrict__ Xhi,
                    const half* __restrict__ PWhi,
                    const float* __restrict__ pb, const float* __restrict__ lng,
                    const float* __restrict__ lnb, float* __restrict__ out)
{
    constexpr int A_BYTES = 10240;
    constexpr int B_BYTES = 8704;
    constexpr int OFF_BHI = A_BYTES;
    constexpr int STAGE   = OFF_BHI + B_BYTES;   // 18944

    extern __shared__ __align__(16) char sm[];
    const uint32_t smb = smem_u32(sm);

    const int p   = blockIdx.y;
    const int m0  = blockIdx.x * 128;
    const int tid  = threadIdx.x;
    const int wid  = tid >> 5;
    const int lane = tid & 31;
    const int wm   = wid & 1;
    const int wn   = wid >> 1;

    const half* Ahi = Xhi + ((size_t)p * BATCH) * 256;
    const half* Bhi = PWhi + (size_t)p * 256 * 128;

    const int tA = lane >> 3, rA = lane & 7;
    const int a_row_off = (tA & 1) * 8 + rA;
    const int a_kcol    = (tA >> 1) * 8;
    const uint32_t a_const = (uint32_t)((wm * 64 + a_row_off) * 40 + a_kcol) * 2;
    const int lB = lane & 15;
    const int b_krow = (lB >> 3) * 8 + (lB & 7);
    const uint32_t b_const = (uint32_t)(b_krow * 136 + wn * 32) * 2;

    float acc[4][4][4];
    #pragma unroll
    for (int i = 0; i < 4; i++)
        #pragma unroll
        for (int j = 0; j < 4; j++)
            #pragma unroll
            for (int q = 0; q < 4; q++) acc[i][j][q] = 0.f;

    #define P_ISSUE(slot, kt) do {                                             \
        uint32_t base = smb + (uint32_t)(slot) * STAGE;                        \
        int k0 = (kt) * TCB_K;                                                 \
        _Pragma("unroll")                                                      \
        for (int l = 0; l < 2; ++l) {                                          \
            int idx = tid + l * 256;                                           \
            int r = idx >> 2, c = idx & 3;                                     \
            cp16(base + r * 80 + c * 16,                                       \
                 Ahi + (size_t)(m0 + r) * 256 + k0 + c * 8);                   \
        }                                                                      \
        _Pragma("unroll")                                                      \
        for (int l = 0; l < 2; ++l) {                                          \
            int idx = tid + l * 256;                                           \
            int r = idx >> 4, c = idx & 15;                                    \
            cp16(base + OFF_BHI + r * 272 + c * 16,                            \
                 Bhi + (size_t)(k0 + r) * 128 + c * 8);                        \
        }                                                                      \
    } while (0)

    P_ISSUE(0, 0); cp_commit();

    #pragma unroll
    for (int kt = 0; kt < 8; ++kt) {           // K=256 -> 8 iters of 32
        cp_wait0();
        __syncthreads();
        if (kt + 1 < 8) { P_ISSUE((kt + 1) & 1, kt + 1); cp_commit(); }

        const uint32_t base = smb + (uint32_t)(kt & 1) * STAGE;
        const uint32_t aHb = base + a_const;
        const uint32_t bHb = base + OFF_BHI + b_const;

        #pragma unroll
        for (int kk = 0; kk < 2; ++kk) {
            uint32_t aH[4][4], bH[4][2];
            const uint32_t akk = (uint32_t)(kk * 16 * 2);
            const uint32_t bkk = (uint32_t)(kk * 16 * 136 * 2);
            #pragma unroll
            for (int mf = 0; mf < 4; ++mf) {
                uint32_t off = (uint32_t)(mf * 16 * 40) * 2 + akk;
                ldsm_x4(aH[mf], aHb + off);
            }
            #pragma unroll
            for (int nf = 0; nf < 4; ++nf) {
                uint32_t off = (uint32_t)(nf * 8) * 2 + bkk;
                ldsm_x2_trans(bH[nf], bHb + off);
            }
            #pragma unroll
            for (int mf = 0; mf < 4; ++mf)
                #pragma unroll
                for (int nf = 0; nf < 4; ++nf)
                    mma_f16(acc[mf][nf], aH[mf], bH[nf]);
        }
    }
    #undef P_ISSUE

    // ---- epilogue: stage (bias-added) outputs in smem, then LN per row
    __syncthreads();                       // done with stage buffers
    float* os = reinterpret_cast<float*>(sm);   // [128][132]
    const int g  = lane >> 2;
    const int tg = lane & 3;
    #pragma unroll
    for (int mf = 0; mf < 4; ++mf) {
        int r0 = wm * 64 + mf * 16 + g;
        #pragma unroll
        for (int nf = 0; nf < 4; ++nf) {
            int c = wn * 32 + nf * 8 + tg * 2;
            float b0 = pb[p * 128 + c], b1 = pb[p * 128 + c + 1];
            os[r0 * 132 + c]           = acc[mf][nf][0] + b0;
            os[r0 * 132 + c + 1]       = acc[mf][nf][1] + b1;
            os[(r0 + 8) * 132 + c]     = acc[mf][nf][2] + b0;
            os[(r0 + 8) * 132 + c + 1] = acc[mf][nf][3] + b1;
        }
    }
    __syncthreads();

    #pragma unroll
    for (int rr = 0; rr < 16; ++rr) {
        int r = wid * 16 + rr;
        const float* t = os + r * 132;
        float v0 = t[lane], v1 = t[lane + 32], v2 = t[lane + 64], v3 = t[lane + 96];
        float s = v0 + v1 + v2 + v3;
        #pragma unroll
        for (int o = 16; o > 0; o >>= 1) s += __shfl_xor_sync(0xffffffff, s, o);
        float mu = s * (1.0f / 128.0f);
        float d0 = v0 - mu, d1 = v1 - mu, d2 = v2 - mu, d3 = v3 - mu;
        float s2 = d0 * d0 + d1 * d1 + d2 * d2 + d3 * d3;
        #pragma unroll
        for (int o = 16; o > 0; o >>= 1) s2 += __shfl_xor_sync(0xffffffff, s2, o);
        float rstd = rsqrtf(s2 * (1.0f / 128.0f) + LN_EPS);

        int b = m0 + r;
        size_t base = (size_t)b * D_ALL + p * 128;
        int gi = p * 128;
        out[base + lane]      = d0 * rstd * lng[gi + lane]      + lnb[gi + lane];
        out[base + lane + 32] = d1 * rstd * lng[gi + lane + 32] + lnb[gi + lane + 32];
        out[base + lane + 64] = d2 * rstd * lng[gi + lane + 64] + lnb[gi + lane + 64];
        out[base + lane + 96] = d3 * rstd * lng[gi + lane + 96] + lnb[gi + lane + 96];
    }
}

// ---------------------------------------------------------------------------
// fp32 -> fp16 hi/lo split (elementwise, vectorized)
// ---------------------------------------------------------------------------
__global__ __launch_bounds__(256) void cvt_split_kernel(
    const float4* __restrict__ x, uint2* __restrict__ hi, uint2* __restrict__ lo, int n4)
{
    int i = blockIdx.x * 256 + threadIdx.x;
    if (i >= n4) return;
    float4 v = x[i];
    half h0, l0, h1, l1, h2, l2, h3, l3;
    split_hl(v.x, h0, l0); split_hl(v.y, h1, l1);
    split_hl(v.z, h2, l2); split_hl(v.w, h3, l3);
    half2 ha = __halves2half2(h0, h1), hb = __halves2half2(h2, h3);
    half2 la = __halves2half2(l0, l1), lb = __halves2half2(l2, l3);
    hi[i] = make_uint2(*reinterpret_cast<uint32_t*>(&ha), *reinterpret_cast<uint32_t*>(&hb));
    lo[i] = make_uint2(*reinterpret_cast<uint32_t*>(&la), *reinterpret_cast<uint32_t*>(&lb));
}

// fp32 -> fp16 hi only
__global__ __launch_bounds__(256) void cvt_hi_kernel(
    const float4* __restrict__ x, uint2* __restrict__ hi, int n4)
{
    int i = blockIdx.x * 256 + threadIdx.x;
    if (i >= n4) return;
    float4 v = x[i];
    half2 ha = __halves2half2(__float2half_rn(v.x), __float2half_rn(v.y));
    half2 hb = __halves2half2(__float2half_rn(v.z), __float2half_rn(v.w));
    hi[i] = make_uint2(*reinterpret_cast<uint32_t*>(&ha), *reinterpret_cast<uint32_t*>(&hb));
}

// ---------------------------------------------------------------------------
// attention weight kernels -> g_attn_hi/lo (B, 128): [pair | macro]
// ---------------------------------------------------------------------------
__global__ __launch_bounds__(128) void attn_pair_kernel(
    const float* __restrict__ ps, const float* __restrict__ keys,
    half* __restrict__ ahi, half* __restrict__ alo)
{
    int b = blockIdx.x, tid = threadIdx.x;
    __shared__ float q[PAIR_DIM];
    __shared__ float sc[NUM_SLOTS];
    __shared__ float red[NUM_SLOTS];

    float s = 0.f;
    #pragma unroll
    for (int p = 0; p < NUM_PAIRS; p++)
        s += ps[(size_t)b * D_ALL + p * PAIR_DIM + tid];
    q[tid] = s * (1.0f / NUM_PAIRS);
    __syncthreads();

    if (tid < NUM_SLOTS) {
        float acc = 0.f;
        #pragma unroll 4
        for (int d = 0; d < PAIR_DIM; d++)
            acc = fmaf(q[d], keys[tid * PAIR_DIM + d], acc);
        sc[tid] = acc * 0.08838834764831845f;
    }
    __syncthreads();

    if (tid < NUM_SLOTS) red[tid] = sc[tid];
    __syncthreads();
    for (int o = 32; o > 0; o >>= 1) {
        if (tid < o) red[tid] = fmaxf(red[tid], red[tid + o]);
        __syncthreads();
    }
    float mx = red[0];
    __syncthreads();

    float e = 0.f;
    if (tid < NUM_SLOTS) { e = expf(sc[tid] - mx); red[tid] = e; }
    __syncthreads();
    for (int o = 32; o > 0; o >>= 1) {
        if (tid < o) red[tid] += red[tid + o];
        __syncthreads();
    }
    if (tid < NUM_SLOTS) {
        half h, l;
        split_hl(e / red[0], h, l);
        ahi[(size_t)b * 128 + tid] = h;
        alo[(size_t)b * 128 + tid] = l;
    }
}

__global__ __launch_bounds__(128) void attn_macro_kernel(
    const float* __restrict__ ms, const float* __restrict__ keys,
    half* __restrict__ ahi, half* __restrict__ alo)
{
    int b = blockIdx.x, tid = threadIdx.x;
    __shared__ float q[MACRO_DIM];
    __shared__ float sc[NUM_SLOTS];
    __shared__ float red[NUM_SLOTS];

    q[tid]       = ms[(size_t)b * MACRO_DIM + tid];
    q[tid + 128] = ms[(size_t)b * MACRO_DIM + tid + 128];
    __syncthreads();

    if (tid < NUM_SLOTS) {
        float acc = 0.f;
        #pragma unroll 4
        for (int d = 0; d < MACRO_DIM; d++)
            acc = fmaf(q[d], keys[tid * MACRO_DIM + d], acc);
        sc[tid] = acc * 0.0625f;
    }
    __syncthreads();

    if (tid < NUM_SLOTS) red[tid] = sc[tid];
    __syncthreads();
    for (int o = 32; o > 0; o >>= 1) {
        if (tid < o) red[tid] = fmaxf(red[tid], red[tid + o]);
        __syncthreads();
    }
    float mx = red[0];
    __syncthreads();

    float e = 0.f;
    if (tid < NUM_SLOTS) { e = expf(sc[tid] - mx); red[tid] = e; }
    __syncthreads();
    for (int o = 32; o > 0; o >>= 1) {
        if (tid < o) red[tid] += red[tid + o];
        __syncthreads();
    }
    if (tid < NUM_SLOTS) {
        half h, l;
        split_hl(e / red[0], h, l);
        ahi[(size_t)b * 128 + 64 + tid] = h;
        alo[(size_t)b * 128 + 64 + tid] = l;
    }
}

// ---------------------------------------------------------------------------
// Zero kernel (for g_V before atomic fold)
// ---------------------------------------------------------------------------
__global__ __launch_bounds__(256) void zero_kernel(float* __restrict__ p, int n)
{
    int i = blockIdx.x * 256 + threadIdx.x;
    if (i < n) p[i] = 0.f;
}

// ---------------------------------------------------------------------------
// Fold v5: V[z*64 + m, n] += sum_k vals_z[m,k] * W1[z*3584 + k, n]
// Tile 64(M) x 128(N), BK=16, split-K=16, 3-stage cp.async.
// Inner loop: 4-k blocks, broadcast LDS.128 A loads. 3 CTAs/SM.
// ---------------------------------------------------------------------------
#define FK_KS   16
#define FK_KCH  (D_ALL / FK_KS)    // 224
#define FK_BK   16
#define FK_BN   128
#define FK_AS_B   5120
#define FK_STAGE  13568
#define FK_NST    3

__global__ __launch_bounds__(256, 3) void fold_kernel(
    const float* __restrict__ vals_p, const float* __restrict__ vals_m,
    const float* __restrict__ w1, float* __restrict__ V)
{
    extern __shared__ __align__(16) char sm[];
    const uint32_t smb = smem_u32(sm);

    const int nb = blockIdx.x;
    const int ks = blockIdx.y;
    const int z  = blockIdx.z;
    const float* vals = z ? vals_m : vals_p;
    const float* W    = w1 + (size_t)z * D_ALL * D_ALL;
    float* Vout       = V  + (size_t)z * 64 * D_ALL;

    const int tid = threadIdx.x;
    const int ty  = tid >> 5;
    const int tx  = tid & 31;
    const int n0  = nb * FK_BN;
    const int kb  = ks * FK_KCH;

    float acc[8][4];
    #pragma unroll
    for (int i = 0; i < 8; i++)
        #pragma unroll
        for (int j = 0; j < 4; j++) acc[i][j] = 0.f;

    #define FK_ISSUE(slot, k0) do {                                            \
        uint32_t base = smb + (uint32_t)(slot) * FK_STAGE;                     \
        {   int m = tid >> 2, c = tid & 3;                                     \
            cp16(base + m * 80 + c * 16,                                       \
                 vals + (size_t)m * D_ALL + (k0) + c * 4); }                   \
        _Pragma("unroll")                                                      \
        for (int l = 0; l < 2; ++l) {                                          \
            int idx = tid + l * 256;                                           \
            int r = idx >> 5, c4 = idx & 31;                                   \
            cp16(base + FK_AS_B + r * 528 + c4 * 16,                           \
                 W + (size_t)((k0) + r) * D_ALL + n0 + c4 * 4); }              \
    } while (0)

    FK_ISSUE(0, kb); cp_commit();
    FK_ISSUE(1, kb + FK_BK); cp_commit();

    const int niter = FK_KCH / FK_BK;   // 14
    for (int it = 0; it < niter; ++it) {
        cp_wait1();
        __syncthreads();
        if (it + 2 < niter) { FK_ISSUE((it + 2) % FK_NST, kb + (it + 2) * FK_BK); }
        cp_commit();

        const int slot = it % FK_NST;
        const float* As = reinterpret_cast<const float*>(sm + slot * FK_STAGE);
        const float* Bs = reinterpret_cast<const float*>(sm + slot * FK_STAGE + FK_AS_B);

        #pragma unroll
        for (int kb4 = 0; kb4 < FK_BK / 4; ++kb4) {
            float4 a4[8];
            #pragma unroll
            for (int i = 0; i < 8; i++)
                a4[i] = *reinterpret_cast<const float4*>(As + (ty * 8 + i) * 20 + kb4 * 4);
            const float* af = reinterpret_cast<const float*>(a4);
            #pragma unroll
            for (int kk = 0; kk < 4; ++kk) {
                float4 bq = *reinterpret_cast<const float4*>(
                    Bs + (kb4 * 4 + kk) * 132 + tx * 4);
                float b[4] = {bq.x, bq.y, bq.z, bq.w};
                #pragma unroll
                for (int i = 0; i < 8; i++) {
                    float a = af[i * 4 + kk];
                    #pragma unroll
                    for (int j = 0; j < 4; j++)
                        acc[i][j] = fmaf(a, b[j], acc[i][j]);
                }
            }
        }
    }
    #undef FK_ISSUE

    #pragma unroll
    for (int i = 0; i < 8; i++) {
        int m = ty * 8 + i;
        #pragma unroll
        for (int j = 0; j < 4; j++)
            atomicAdd(Vout + (size_t)m * D_ALL + n0 + tx * 4 + j, acc[i][j]);
    }
}

// ---------------------------------------------------------------------------
// LayerNorm + exact GELU over rows of length D_ALL; writes fp16 hi.
// ---------------------------------------------------------------------------
__global__ __launch_bounds__(512) void ln_gelu_kernel(
    const float* __restrict__ h, const float* __restrict__ g, const float* __restrict__ b,
    half* __restrict__ ohi)
{
    __shared__ float row[D_ALL];
    __shared__ float reds[16], reds2[16];
    int bi = blockIdx.x, tid = threadIdx.x;
    const float4* hrow = reinterpret_cast<const float4*>(h + (size_t)bi * D_ALL);
    float4* rowv = reinterpret_cast<float4*>(row);

    float s = 0.f, s2 = 0.f;
    for (int i = tid; i < D_ALL / 4; i += 512) {
        float4 v = hrow[i];
        rowv[i] = v;
        s  += v.x + v.y + v.z + v.w;
        s2 += v.x * v.x + v.y * v.y + v.z * v.z + v.w * v.w;
    }
    #pragma unroll
    for (int o = 16; o > 0; o >>= 1) {
        s  += __shfl_xor_sync(0xffffffff, s, o);
        s2 += __shfl_xor_sync(0xffffffff, s2, o);
    }
    int warp = tid >> 5, lane = tid & 31;
    if (lane == 0) { reds[warp] = s; reds2[warp] = s2; }
    __syncthreads();
    if (warp == 0) {
        float a = (lane < 16) ? reds[lane] : 0.f;
        float a2 = (lane < 16) ? reds2[lane] : 0.f;
        #pragma unroll
        for (int o = 8; o > 0; o >>= 1) {
            a  += __shfl_xor_sync(0xffffffff, a, o);
            a2 += __shfl_xor_sync(0xffffffff, a2, o);
        }
        if (lane == 0) { reds[0] = a; reds2[0] = a2; }
    }
    __syncthreads();
    float mu = reds[0] * (1.0f / D_ALL);
    float var = reds2[0] * (1.0f / D_ALL) - mu * mu;
    float rstd = rsqrtf(var + LN_EPS);

    half* orow = ohi + (size_t)bi * D_ALL;
    for (int i = tid; i < D_ALL / 4; i += 512) {
        float4 v = rowv[i];
        float4 gg = reinterpret_cast<const float4*>(g)[i];
        float4 bb = reinterpret_cast<const float4*>(b)[i];
        float y0 = (v.x - mu) * rstd * gg.x + bb.x;
        float y1 = (v.y - mu) * rstd * gg.y + bb.y;
        float y2 = (v.z - mu) * rstd * gg.z + bb.z;
        float y3 = (v.w - mu) * rstd * gg.w + bb.w;
        const float k = 0.70710678118654752f;
        half o0 = __float2half_rn(0.5f * y0 * (1.0f + erff(y0 * k)));
        half o1 = __float2half_rn(0.5f * y1 * (1.0f + erff(y1 * k)));
        half o2 = __float2half_rn(0.5f * y2 * (1.0f + erff(y2 * k)));
        half o3 = __float2half_rn(0.5f * y3 * (1.0f + erff(y3 * k)));
        half h4[4] = {o0, o1, o2, o3};
        *reinterpret_cast<uint2*>(orow + i * 4) = *reinterpret_cast<uint2*>(h4);
    }
}

// ---------------------------------------------------------------------------
// Build xcat pair_states half (hi only): (p, b, 0..128)
// ---------------------------------------------------------------------------
__global__ __launch_bounds__(256) void build_xps_kernel(
    const float* __restrict__ ps, half* __restrict__ xhi)
{
    size_t i = (size_t)blockIdx.x * 256 + threadIdx.x;   // 8-elem chunk id
    int kc = (int)(i & 15);
    size_t pb = i >> 4;
    int b = (int)(pb & 4095);
    int p = (int)(pb >> 12);
    const float* src = ps + (size_t)b * D_ALL + p * 128 + kc * 8;
    half h[8];
    #pragma unroll
    for (int j = 0; j < 8; j++) h[j] = __float2half_rn(src[j]);
    size_t dst = ((size_t)p * BATCH + b) * 256 + kc * 8;
    *reinterpret_cast<uint4*>(xhi + dst) = *reinterpret_cast<uint4*>(h);
}

// ---------------------------------------------------------------------------
// Launch
// ---------------------------------------------------------------------------
extern "C" void kernel_launch(void* const* d_in, const int* in_sizes, int n_in,
                              void* d_out, int out_size)
{
    const float* pair_states    = (const float*)d_in[0];
    const float* macro_state    = (const float*)d_in[1];
    const float* mem_pair_keys  = (const float*)d_in[2];
    const float* mem_pair_vals  = (const float*)d_in[3];
    const float* mem_macro_keys = (const float*)d_in[4];
    const float* mem_macro_vals = (const float*)d_in[5];
    const float* fusion_w1      = (const float*)d_in[6];
    const float* fusion_b1      = (const float*)d_in[7];
    const float* fusion_ln_g    = (const float*)d_in[8];
    const float* fusion_ln_b    = (const float*)d_in[9];
    const float* fusion_w2      = (const float*)d_in[10];
    const float* fusion_b2      = (const float*)d_in[11];
    const float* pair_w         = (const float*)d_in[12];
    const float* pair_b         = (const float*)d_in[13];
    const float* pair_ln_g      = (const float*)d_in[14];
    const float* pair_ln_b      = (const float*)d_in[15];
    float* out = (float*)d_out;

    float *V, *h;
    half *a_hi, *a_lo, *V_hi, *V_lo, *w2_hi, *h_hi;
    half *x_hi, *pw_hi;
    cudaGetSymbolAddress((void**)&a_hi,  g_attn_hi);
    cudaGetSymbolAddress((void**)&a_lo,  g_attn_lo);
    cudaGetSymbolAddress((void**)&V,     g_V);
    cudaGetSymbolAddress((void**)&V_hi,  g_V_hi);
    cudaGetSymbolAddress((void**)&V_lo,  g_V_lo);
    cudaGetSymbolAddress((void**)&w2_hi, g_w2_hi);
    cudaGetSymbolAddress((void**)&h,     g_h);
    cudaGetSymbolAddress((void**)&h_hi,  g_h_hi);
    cudaGetSymbolAddress((void**)&x_hi,  g_xcat_hi);
    cudaGetSymbolAddress((void**)&pw_hi, g_pw_hi);

    const int SMEM_G2 = 4 * 18944;               // 75776 (1-term, 4 stages)
    const int SMEM_G1 = 3 * 37888;               // 113664 (3-term, 3 stages)
    const int SMEMP   = 128 * 132 * 4;           // 67584 (pair: os dominates)
    const int SMEMF   = FK_NST * FK_STAGE;       // 40704 (fold, 3-stage)
    cudaFuncSetAttribute(tc_gemm_kernel<1, 1, 4>,
                         cudaFuncAttributeMaxDynamicSharedMemorySize, SMEM_G2);
    cudaFuncSetAttribute(tc_gemm_kernel<3, 0, 3>,
                         cudaFuncAttributeMaxDynamicSharedMemorySize, SMEM_G1);
    cudaFuncSetAttribute(pair_gemm_ln_kernel,
                         cudaFuncAttributeMaxDynamicSharedMemorySize, SMEMP);
    cudaFuncSetAttribute(fold_kernel,
                         cudaFuncAttributeMaxDynamicSharedMemorySize, SMEMF);

    // 1) attention weights -> fp16 hi/lo (B, 128)
    attn_pair_kernel<<<BATCH, 128>>>(pair_states, mem_pair_keys, a_hi, a_lo);
    attn_macro_kernel<<<BATCH, 128>>>(macro_state, mem_macro_keys, a_hi, a_lo);

    // 2) fold: V = [vals_p @ W1top ; vals_m @ W1bot]  (128 x 3584 fp32)
    zero_kernel<<<(128 * D_ALL + 255) / 256, 256>>>(V, 128 * D_ALL);
    fold_kernel<<<dim3(D_ALL / FK_BN, FK_KS, 2), 256, SMEMF>>>(
        mem_pair_vals, mem_macro_vals, fusion_w1, V);
    {
        int n4 = (128 * D_ALL) / 4;
        cvt_split_kernel<<<(n4 + 255) / 256, 256>>>(
            (const float4*)V, (uint2*)V_hi, (uint2*)V_lo, n4);
    }

    // 2b) weight converts (hi-only); xcat pair_states half
    {
        int n4 = (D_ALL * D_ALL) / 4;
        cvt_hi_kernel<<<(n4 + 255) / 256, 256>>>(
            (const float4*)fusion_w2, (uint2*)w2_hi, n4);
        n4 = (NUM_PAIRS * 256 * 128) / 4;
        cvt_hi_kernel<<<(n4 + 255) / 256, 256>>>(
            (const float4*)pair_w, (uint2*)pw_hi, n4);
        size_t nchunk = (size_t)NUM_PAIRS * BATCH * 16;
        build_xps_kernel<<<(unsigned)(nchunk / 256), 256>>>(pair_states, x_hi);
    }

    // 3) h = attn @ V + b1  (tensor cores, 3-term, K=128)
    tc_gemm_kernel<3, 0, 3><<<dim3(D_ALL / 128, BATCH / 128), 256, SMEM_G1>>>(
        a_hi, a_lo, V_hi, V_lo, fusion_b1, h, nullptr,
        BATCH, D_ALL, 128, 128, D_ALL, D_ALL, 0);

    // 4) LN + GELU -> h_hi; GEMM2 (fp16 1-term, 4-stage) with xcat epilogue
    ln_gelu_kernel<<<BATCH, 512>>>(h, fusion_ln_g, fusion_ln_b, h_hi);
    tc_gemm_kernel<1, 1, 4><<<dim3((D_ALL / 128) * (BATCH / 128), 1), 256, SMEM_G2>>>(
        h_hi, nullptr, w2_hi, nullptr, fusion_b2, nullptr, x_hi,
        BATCH, D_ALL, D_ALL, D_ALL, D_ALL, D_ALL, 1);

    // 5) per-pair linear (1-term) + fused LN -> output
    pair_gemm_ln_kernel<<<dim3(BATCH / 128, NUM_PAIRS), 256, SMEMP>>>(
        x_hi, pw_hi, pair_b, pair_ln_g, pair_ln_b, out);
}

// round 12
// speedup vs baseline: 10.3196x; 1.0169x over previous
#include <cuda_runtime.h>
#include <cuda_fp16.h>
#include <math.h>
#include <stdint.h>

// ---------------------------------------------------------------------------
// Problem constants
// ---------------------------------------------------------------------------
#define BATCH      4096
#define NUM_PAIRS  28
#define PAIR_DIM   128
#define MACRO_DIM  256
#define NUM_SLOTS  64
#define D_ALL      3584          // NUM_PAIRS * PAIR_DIM
#define D_CAT      7168          // 2 * D_ALL
#define LN_EPS     1e-5f

// ---------------------------------------------------------------------------
// Scratch (device globals: allocation-free per harness rules)
// ---------------------------------------------------------------------------
__device__ half  g_attn_hi[BATCH * 128];                      // [attn_p | attn_m]
__device__ float g_V[(size_t)128 * D_ALL];                    // [Vp@W1top ; Vm@W1bot]
__device__ half  g_V_hi[(size_t)128 * D_ALL];
__device__ half  g_V_lo[(size_t)128 * D_ALL];
__device__ half  g_w2_hi[(size_t)D_ALL * D_ALL];
__device__ float g_h[(size_t)BATCH * D_ALL];
__device__ half  g_h_hi[(size_t)BATCH * D_ALL];
__device__ half  g_xcat_hi[(size_t)NUM_PAIRS * BATCH * 256];  // (p,b,256)
__device__ half  g_pw_hi[(size_t)NUM_PAIRS * 256 * 128];

// ---------------------------------------------------------------------------
// Small helpers
// ---------------------------------------------------------------------------
__device__ __forceinline__ uint32_t smem_u32(const void* p) {
    uint32_t a;
    asm("{ .reg .u64 t; cvta.to.shared.u64 t, %1; cvt.u32.u64 %0, t; }" : "=r"(a) : "l"(p));
    return a;
}
__device__ __forceinline__ void cp16(uint32_t dst, const void* src) {
    asm volatile("cp.async.cg.shared.global [%0], [%1], 16;" :: "r"(dst), "l"(src));
}
__device__ __forceinline__ void cp_commit() {
    asm volatile("cp.async.commit_group;" ::: "memory");
}
__device__ __forceinline__ void cp_wait0() {
    asm volatile("cp.async.wait_group 0;" ::: "memory");
}
__device__ __forceinline__ void cp_wait1() {
    asm volatile("cp.async.wait_group 1;" ::: "memory");
}
__device__ __forceinline__ void ldsm_x4(uint32_t* r, uint32_t addr) {
    asm volatile("ldmatrix.sync.aligned.m8n8.x4.shared.b16 {%0,%1,%2,%3}, [%4];"
        : "=r"(r[0]), "=r"(r[1]), "=r"(r[2]), "=r"(r[3]) : "r"(addr));
}
__device__ __forceinline__ void ldsm_x2_trans(uint32_t* r, uint32_t addr) {
    asm volatile("ldmatrix.sync.aligned.m8n8.x2.trans.shared.b16 {%0,%1}, [%2];"
        : "=r"(r[0]), "=r"(r[1]) : "r"(addr));
}
__device__ __forceinline__ void mma_f16(float* c, const uint32_t* a, const uint32_t* b) {
    asm volatile(
        "mma.sync.aligned.m16n8k16.row.col.f32.f16.f16.f32 "
        "{%0,%1,%2,%3}, {%4,%5,%6,%7}, {%8,%9}, {%0,%1,%2,%3};"
        : "+f"(c[0]), "+f"(c[1]), "+f"(c[2]), "+f"(c[3])
        : "r"(a[0]), "r"(a[1]), "r"(a[2]), "r"(a[3]), "r"(b[0]), "r"(b[1]));
}
__device__ __forceinline__ void split_hl(float v, half& h, half& l) {
    h = __float2half_rn(v);
    l = __float2half_rn(v - __half2float(h));
}

// ---------------------------------------------------------------------------
// Tensor-core fp16 GEMM: 128x128 tile, BK=32, NST-stage cp.async, 2 CTAs/SM.
//   TERMS==1: D = Ahi*Bhi
//   TERMS==2: D = Ahi*(Bhi+Blo)
//   TERMS==3: D = Ahi*Bhi + Ahi*Blo + Alo*Bhi
//   XCAT==1: write fp16 (hi only) into xcat fused-half (p = n-tile, b, 256).
//   swz==1:  flat-grid L2 swizzle: 7 groups of (4 n-tiles x 32 m-tiles).
// ---------------------------------------------------------------------------
#define TCB_K   32

template<int TERMS, int XCAT, int NST>
__global__ void __launch_bounds__(256, 2)
tc_gemm_kernel(const half* __restrict__ Ahi, const half* __restrict__ Alo,
               const half* __restrict__ Bhi, const half* __restrict__ Blo,
               const float* __restrict__ bias, float* __restrict__ C,
               half* __restrict__ Xhi,
               int M, int N, int K, int lda, int ldb, int ldc, int swz)
{
    constexpr int A_BYTES  = 10240;                    // 128 rows x 40 half
    constexpr int B_BYTES  = 8704;                     // 32 rows x 136 half
    constexpr int OFF_ALO  = A_BYTES;
    constexpr int OFF_BHI  = (TERMS == 3) ? 2 * A_BYTES : A_BYTES;
    constexpr int OFF_BLO  = OFF_BHI + B_BYTES;
    constexpr int STAGE    = (TERMS == 1) ? (OFF_BHI + B_BYTES)
                                          : (OFF_BLO + B_BYTES);

    extern __shared__ __align__(16) char sm[];
    const uint32_t smb = smem_u32(sm);

    int bx, by;
    if (swz) {
        int id = blockIdx.x;       // 896 blocks: 7 groups x (4 n x 32 m)
        int ng = id >> 7;
        int r  = id & 127;
        bx = ng * 4 + (r & 3);     // 0..27
        by = r >> 2;               // 0..31
    } else {
        bx = blockIdx.x; by = blockIdx.y;
    }

    const int tid  = threadIdx.x;
    const int wid  = tid >> 5;
    const int lane = tid & 31;
    const int wm   = wid & 1;
    const int wn   = wid >> 1;
    const int m0   = by * 128;
    const int n0   = bx * 128;

    const int tA = lane >> 3, rA = lane & 7;
    const int a_row_off = (tA & 1) * 8 + rA;
    const int a_kcol    = (tA >> 1) * 8;
    const uint32_t a_const = (uint32_t)((wm * 64 + a_row_off) * 40 + a_kcol) * 2;
    const int lB = lane & 15;
    const int b_krow = (lB >> 3) * 8 + (lB & 7);
    const uint32_t b_const = (uint32_t)(b_krow * 136 + wn * 32) * 2;

    float acc[4][4][4];
    #pragma unroll
    for (int i = 0; i < 4; i++)
        #pragma unroll
        for (int j = 0; j < 4; j++)
            #pragma unroll
            for (int q = 0; q < 4; q++) acc[i][j][q] = 0.f;

    const int nk = K / TCB_K;

    #define ISSUE_STAGE(slot, kt) do {                                         \
        uint32_t base = smb + (uint32_t)(slot) * STAGE;                        \
        int k0 = (kt) * TCB_K;                                                 \
        _Pragma("unroll")                                                      \
        for (int l = 0; l < 2; ++l) {                                          \
            int idx = tid + l * 256;                                           \
            int r = idx >> 2, c = idx & 3;                                     \
            cp16(base + r * 80 + c * 16,                                       \
                 Ahi + (size_t)(m0 + r) * lda + k0 + c * 8);                   \
            if constexpr (TERMS == 3)                                          \
                cp16(base + OFF_ALO + r * 80 + c * 16,                         \
                     Alo + (size_t)(m0 + r) * lda + k0 + c * 8);               \
        }                                                                      \
        _Pragma("unroll")                                                      \
        for (int l = 0; l < 2; ++l) {                                          \
            int idx = tid + l * 256;                                           \
            int r = idx >> 4, c = idx & 15;                                    \
            cp16(base + OFF_BHI + r * 272 + c * 16,                            \
                 Bhi + (size_t)(k0 + r) * ldb + n0 + c * 8);                   \
            if constexpr (TERMS >= 2)                                          \
                cp16(base + OFF_BLO + r * 272 + c * 16,                        \
                     Blo + (size_t)(k0 + r) * ldb + n0 + c * 8);               \
        }                                                                      \
    } while (0)

    #pragma unroll
    for (int s = 0; s < NST - 1; ++s) {
        if (s < nk) ISSUE_STAGE(s, s);
        cp_commit();
    }

    for (int kt = 0; kt < nk; ++kt) {
        asm volatile("cp.async.wait_group %0;" :: "n"(NST - 2) : "memory");
        __syncthreads();
        if (kt + NST - 1 < nk) { ISSUE_STAGE((kt + NST - 1) % NST, kt + NST - 1); }
        cp_commit();

        const int slot = kt % NST;
        const uint32_t base = smb + (uint32_t)slot * STAGE;
        const uint32_t aHb = base + a_const;
        const uint32_t aLb = base + OFF_ALO + a_const;
        const uint32_t bHb = base + OFF_BHI + b_const;
        const uint32_t bLb = base + OFF_BLO + b_const;

        #pragma unroll
        for (int kk = 0; kk < 2; ++kk) {
            uint32_t aH[4][4], aL[4][4], bH[4][2], bL[4][2];
            const uint32_t akk = (uint32_t)(kk * 16 * 2);
            const uint32_t bkk = (uint32_t)(kk * 16 * 136 * 2);
            #pragma unroll
            for (int mf = 0; mf < 4; ++mf) {
                uint32_t off = (uint32_t)(mf * 16 * 40) * 2 + akk;
                ldsm_x4(aH[mf], aHb + off);
                if constexpr (TERMS == 3) ldsm_x4(aL[mf], aLb + off);
            }
            #pragma unroll
            for (int nf = 0; nf < 4; ++nf) {
                uint32_t off = (uint32_t)(nf * 8) * 2 + bkk;
                ldsm_x2_trans(bH[nf], bHb + off);
                if constexpr (TERMS >= 2) ldsm_x2_trans(bL[nf], bLb + off);
            }
            #pragma unroll
            for (int mf = 0; mf < 4; ++mf)
                #pragma unroll
                for (int nf = 0; nf < 4; ++nf) {
                    mma_f16(acc[mf][nf], aH[mf], bH[nf]);
                    if constexpr (TERMS >= 2) mma_f16(acc[mf][nf], aH[mf], bL[nf]);
                    if constexpr (TERMS == 3) mma_f16(acc[mf][nf], aL[mf], bH[nf]);
                }
        }
    }
    #undef ISSUE_STAGE

    const int g  = lane >> 2;
    const int tg = lane & 3;
    #pragma unroll
    for (int mf = 0; mf < 4; ++mf) {
        int r0 = m0 + wm * 64 + mf * 16 + g;
        #pragma unroll
        for (int nf = 0; nf < 4; ++nf) {
            int c = wn * 32 + nf * 8 + tg * 2;
            float b0 = bias[n0 + c], b1 = bias[n0 + c + 1];
            float v00 = acc[mf][nf][0] + b0, v01 = acc[mf][nf][1] + b1;
            float v10 = acc[mf][nf][2] + b0, v11 = acc[mf][nf][3] + b1;
            if constexpr (XCAT == 1) {
                size_t d0 = ((size_t)bx * BATCH + r0) * 256 + 128 + c;
                size_t d1 = ((size_t)bx * BATCH + r0 + 8) * 256 + 128 + c;
                *reinterpret_cast<half2*>(Xhi + d0) =
                    __halves2half2(__float2half_rn(v00), __float2half_rn(v01));
                *reinterpret_cast<half2*>(Xhi + d1) =
                    __halves2half2(__float2half_rn(v10), __float2half_rn(v11));
            } else {
                *reinterpret_cast<float2*>(C + (size_t)r0 * ldc + n0 + c) =
                    make_float2(v00, v01);
                *reinterpret_cast<float2*>(C + (size_t)(r0 + 8) * ldc + n0 + c) =
                    make_float2(v10, v11);
            }
        }
    }
}

// ---------------------------------------------------------------------------
// Pair GEMM + fused LayerNorm: per p (blockIdx.y), C-tile 128(b) x 128(e),
// K=256, 1-term (A-hi x B-hi), LN over the 128-wide row in the epilogue.
// 2 CTAs/SM.
// ---------------------------------------------------------------------------
__global__ void __launch_bounds__(256, 2)
pair_gemm_ln_kernel(const half* __restrict__ Xhi,
                    const half* __restrict__ PWhi,
                    const float* __restrict__ pb, const float* __restrict__ lng,
                    const float* __restrict__ lnb, float* __restrict__ out)
{
    constexpr int A_BYTES = 10240;
    constexpr int B_BYTES = 8704;
    constexpr int OFF_BHI = A_BYTES;
    constexpr int STAGE   = OFF_BHI + B_BYTES;   // 18944

    extern __shared__ __align__(16) char sm[];
    const uint32_t smb = smem_u32(sm);

    const int p   = blockIdx.y;
    const int m0  = blockIdx.x * 128;
    const int tid  = threadIdx.x;
    const int wid  = tid >> 5;
    const int lane = tid & 31;
    const int wm   = wid & 1;
    const int wn   = wid >> 1;

    const half* Ahi = Xhi + ((size_t)p * BATCH) * 256;
    const half* Bhi = PWhi + (size_t)p * 256 * 128;

    const int tA = lane >> 3, rA = lane & 7;
    const int a_row_off = (tA & 1) * 8 + rA;
    const int a_kcol    = (tA >> 1) * 8;
    const uint32_t a_const = (uint32_t)((wm * 64 + a_row_off) * 40 + a_kcol) * 2;
    const int lB = lane & 15;
    const int b_krow = (lB >> 3) * 8 + (lB & 7);
    const uint32_t b_const = (uint32_t)(b_krow * 136 + wn * 32) * 2;

    float acc[4][4][4];
    #pragma unroll
    for (int i = 0; i < 4; i++)
        #pragma unroll
        for (int j = 0; j < 4; j++)
            #pragma unroll
            for (int q = 0; q < 4; q++) acc[i][j][q] = 0.f;

    #define P_ISSUE(slot, kt) do {                                             \
        uint32_t base = smb + (uint32_t)(slot) * STAGE;                        \
        int k0 = (kt) * TCB_K;                                                 \
        _Pragma("unroll")                                                      \
        for (int l = 0; l < 2; ++l) {                                          \
            int idx = tid + l * 256;                                           \
            int r = idx >> 2, c = idx & 3;                                     \
            cp16(base + r * 80 + c * 16,                                       \
                 Ahi + (size_t)(m0 + r) * 256 + k0 + c * 8);                   \
        }                                                                      \
        _Pragma("unroll")                                                      \
        for (int l = 0; l < 2; ++l) {                                          \
            int idx = tid + l * 256;                                           \
            int r = idx >> 4, c = idx & 15;                                    \
            cp16(base + OFF_BHI + r * 272 + c * 16,                            \
                 Bhi + (size_t)(k0 + r) * 128 + c * 8);                        \
        }                                                                      \
    } while (0)

    P_ISSUE(0, 0); cp_commit();

    #pragma unroll
    for (int kt = 0; kt < 8; ++kt) {           // K=256 -> 8 iters of 32
        cp_wait0();
        __syncthreads();
        if (kt + 1 < 8) { P_ISSUE((kt + 1) & 1, kt + 1); cp_commit(); }

        const uint32_t base = smb + (uint32_t)(kt & 1) * STAGE;
        const uint32_t aHb = base + a_const;
        const uint32_t bHb = base + OFF_BHI + b_const;

        #pragma unroll
        for (int kk = 0; kk < 2; ++kk) {
            uint32_t aH[4][4], bH[4][2];
            const uint32_t akk = (uint32_t)(kk * 16 * 2);
            const uint32_t bkk = (uint32_t)(kk * 16 * 136 * 2);
            #pragma unroll
            for (int mf = 0; mf < 4; ++mf) {
                uint32_t off = (uint32_t)(mf * 16 * 40) * 2 + akk;
                ldsm_x4(aH[mf], aHb + off);
            }
            #pragma unroll
            for (int nf = 0; nf < 4; ++nf) {
                uint32_t off = (uint32_t)(nf * 8) * 2 + bkk;
                ldsm_x2_trans(bH[nf], bHb + off);
            }
            #pragma unroll
            for (int mf = 0; mf < 4; ++mf)
                #pragma unroll
                for (int nf = 0; nf < 4; ++nf)
                    mma_f16(acc[mf][nf], aH[mf], bH[nf]);
        }
    }
    #undef P_ISSUE

    // ---- epilogue: stage (bias-added) outputs in smem, then LN per row
    __syncthreads();                       // done with stage buffers
    float* os = reinterpret_cast<float*>(sm);   // [128][132]
    const int g  = lane >> 2;
    const int tg = lane & 3;
    #pragma unroll
    for (int mf = 0; mf < 4; ++mf) {
        int r0 = wm * 64 + mf * 16 + g;
        #pragma unroll
        for (int nf = 0; nf < 4; ++nf) {
            int c = wn * 32 + nf * 8 + tg * 2;
            float b0 = pb[p * 128 + c], b1 = pb[p * 128 + c + 1];
            os[r0 * 132 + c]           = acc[mf][nf][0] + b0;
            os[r0 * 132 + c + 1]       = acc[mf][nf][1] + b1;
            os[(r0 + 8) * 132 + c]     = acc[mf][nf][2] + b0;
            os[(r0 + 8) * 132 + c + 1] = acc[mf][nf][3] + b1;
        }
    }
    __syncthreads();

    #pragma unroll
    for (int rr = 0; rr < 16; ++rr) {
        int r = wid * 16 + rr;
        const float* t = os + r * 132;
        float v0 = t[lane], v1 = t[lane + 32], v2 = t[lane + 64], v3 = t[lane + 96];
        float s = v0 + v1 + v2 + v3;
        #pragma unroll
        for (int o = 16; o > 0; o >>= 1) s += __shfl_xor_sync(0xffffffff, s, o);
        float mu = s * (1.0f / 128.0f);
        float d0 = v0 - mu, d1 = v1 - mu, d2 = v2 - mu, d3 = v3 - mu;
        float s2 = d0 * d0 + d1 * d1 + d2 * d2 + d3 * d3;
        #pragma unroll
        for (int o = 16; o > 0; o >>= 1) s2 += __shfl_xor_sync(0xffffffff, s2, o);
        float rstd = rsqrtf(s2 * (1.0f / 128.0f) + LN_EPS);

        int b = m0 + r;
        size_t base = (size_t)b * D_ALL + p * 128;
        int gi = p * 128;
        out[base + lane]      = d0 * rstd * lng[gi + lane]      + lnb[gi + lane];
        out[base + lane + 32] = d1 * rstd * lng[gi + lane + 32] + lnb[gi + lane + 32];
        out[base + lane + 64] = d2 * rstd * lng[gi + lane + 64] + lnb[gi + lane + 64];
        out[base + lane + 96] = d3 * rstd * lng[gi + lane + 96] + lnb[gi + lane + 96];
    }
}

// ---------------------------------------------------------------------------
// fp32 -> fp16 hi/lo split (elementwise, vectorized)
// ---------------------------------------------------------------------------
__global__ __launch_bounds__(256) void cvt_split_kernel(
    const float4* __restrict__ x, uint2* __restrict__ hi, uint2* __restrict__ lo, int n4)
{
    int i = blockIdx.x * 256 + threadIdx.x;
    if (i >= n4) return;
    float4 v = x[i];
    half h0, l0, h1, l1, h2, l2, h3, l3;
    split_hl(v.x, h0, l0); split_hl(v.y, h1, l1);
    split_hl(v.z, h2, l2); split_hl(v.w, h3, l3);
    half2 ha = __halves2half2(h0, h1), hb = __halves2half2(h2, h3);
    half2 la = __halves2half2(l0, l1), lb = __halves2half2(l2, l3);
    hi[i] = make_uint2(*reinterpret_cast<uint32_t*>(&ha), *reinterpret_cast<uint32_t*>(&hb));
    lo[i] = make_uint2(*reinterpret_cast<uint32_t*>(&la), *reinterpret_cast<uint32_t*>(&lb));
}

// fp32 -> fp16 hi only
__global__ __launch_bounds__(256) void cvt_hi_kernel(
    const float4* __restrict__ x, uint2* __restrict__ hi, int n4)
{
    int i = blockIdx.x * 256 + threadIdx.x;
    if (i >= n4) return;
    float4 v = x[i];
    half2 ha = __halves2half2(__float2half_rn(v.x), __float2half_rn(v.y));
    half2 hb = __halves2half2(__float2half_rn(v.z), __float2half_rn(v.w));
    hi[i] = make_uint2(*reinterpret_cast<uint32_t*>(&ha), *reinterpret_cast<uint32_t*>(&hb));
}

// ---------------------------------------------------------------------------
// attention weight kernels -> g_attn_hi (B, 128): [pair | macro]
// attn_pair also emits the xcat pair_states half (hi fp16) for row b.
// ---------------------------------------------------------------------------
__global__ __launch_bounds__(128) void attn_pair_kernel(
    const float* __restrict__ ps, const float* __restrict__ keys,
    half* __restrict__ ahi, half* __restrict__ xhi)
{
    int b = blockIdx.x, tid = threadIdx.x;
    __shared__ float q[PAIR_DIM];
    __shared__ float sc[NUM_SLOTS];
    __shared__ float red[NUM_SLOTS];

    const float* psrow = ps + (size_t)b * D_ALL;

    float s = 0.f;
    #pragma unroll
    for (int p = 0; p < NUM_PAIRS; p++)
        s += psrow[p * PAIR_DIM + tid];
    q[tid] = s * (1.0f / NUM_PAIRS);
    __syncthreads();

    if (tid < NUM_SLOTS) {
        float acc = 0.f;
        #pragma unroll 4
        for (int d = 0; d < PAIR_DIM; d++)
            acc = fmaf(q[d], keys[tid * PAIR_DIM + d], acc);
        sc[tid] = acc * 0.08838834764831845f;
    }
    __syncthreads();

    if (tid < NUM_SLOTS) red[tid] = sc[tid];
    __syncthreads();
    for (int o = 32; o > 0; o >>= 1) {
        if (tid < o) red[tid] = fmaxf(red[tid], red[tid + o]);
        __syncthreads();
    }
    float mx = red[0];
    __syncthreads();

    float e = 0.f;
    if (tid < NUM_SLOTS) { e = expf(sc[tid] - mx); red[tid] = e; }
    __syncthreads();
    for (int o = 32; o > 0; o >>= 1) {
        if (tid < o) red[tid] += red[tid + o];
        __syncthreads();
    }
    if (tid < NUM_SLOTS)
        ahi[(size_t)b * 128 + tid] = __float2half_rn(e / red[0]);

    // ---- fused: write xcat pair_states half (hi fp16), row b, all 28 pairs
    #pragma unroll
    for (int p = 0; p < NUM_PAIRS; p++) {
        float v = psrow[p * PAIR_DIM + tid];
        xhi[((size_t)p * BATCH + b) * 256 + tid] = __float2half_rn(v);
    }
}

__global__ __launch_bounds__(128) void attn_macro_kernel(
    const float* __restrict__ ms, const float* __restrict__ keys,
    half* __restrict__ ahi)
{
    int b = blockIdx.x, tid = threadIdx.x;
    __shared__ float q[MACRO_DIM];
    __shared__ float sc[NUM_SLOTS];
    __shared__ float red[NUM_SLOTS];

    q[tid]       = ms[(size_t)b * MACRO_DIM + tid];
    q[tid + 128] = ms[(size_t)b * MACRO_DIM + tid + 128];
    __syncthreads();

    if (tid < NUM_SLOTS) {
        float acc = 0.f;
        #pragma unroll 4
        for (int d = 0; d < MACRO_DIM; d++)
            acc = fmaf(q[d], keys[tid * MACRO_DIM + d], acc);
        sc[tid] = acc * 0.0625f;
    }
    __syncthreads();

    if (tid < NUM_SLOTS) red[tid] = sc[tid];
    __syncthreads();
    for (int o = 32; o > 0; o >>= 1) {
        if (tid < o) red[tid] = fmaxf(red[tid], red[tid + o]);
        __syncthreads();
    }
    float mx = red[0];
    __syncthreads();

    float e = 0.f;
    if (tid < NUM_SLOTS) { e = expf(sc[tid] - mx); red[tid] = e; }
    __syncthreads();
    for (int o = 32; o > 0; o >>= 1) {
        if (tid < o) red[tid] += red[tid + o];
        __syncthreads();
    }
    if (tid < NUM_SLOTS)
        ahi[(size_t)b * 128 + 64 + tid] = __float2half_rn(e / red[0]);
}

// ---------------------------------------------------------------------------
// Zero kernel (for g_V before atomic fold)
// ---------------------------------------------------------------------------
__global__ __launch_bounds__(256) void zero_kernel(float* __restrict__ p, int n)
{
    int i = blockIdx.x * 256 + threadIdx.x;
    if (i < n) p[i] = 0.f;
}

// ---------------------------------------------------------------------------
// Fold v6: V[z*64 + m, n] += sum_k vals_z[m,k] * W1[z*3584 + k, n]
// Tile 64(M) x 128(N), BK=16, split-K=8 (448 CTAs = 1 wave @ 3/SM),
// 3-stage cp.async. Inner loop: 4-k blocks, broadcast LDS.128 A loads.
// ---------------------------------------------------------------------------
#define FK_KS   8
#define FK_KCH  (D_ALL / FK_KS)    // 448
#define FK_BK   16
#define FK_BN   128
#define FK_AS_B   5120
#define FK_STAGE  13568
#define FK_NST    3

__global__ __launch_bounds__(256, 3) void fold_kernel(
    const float* __restrict__ vals_p, const float* __restrict__ vals_m,
    const float* __restrict__ w1, float* __restrict__ V)
{
    extern __shared__ __align__(16) char sm[];
    const uint32_t smb = smem_u32(sm);

    const int nb = blockIdx.x;
    const int ks = blockIdx.y;
    const int z  = blockIdx.z;
    const float* vals = z ? vals_m : vals_p;
    const float* W    = w1 + (size_t)z * D_ALL * D_ALL;
    float* Vout       = V  + (size_t)z * 64 * D_ALL;

    const int tid = threadIdx.x;
    const int ty  = tid >> 5;
    const int tx  = tid & 31;
    const int n0  = nb * FK_BN;
    const int kb  = ks * FK_KCH;

    float acc[8][4];
    #pragma unroll
    for (int i = 0; i < 8; i++)
        #pragma unroll
        for (int j = 0; j < 4; j++) acc[i][j] = 0.f;

    #define FK_ISSUE(slot, k0) do {                                            \
        uint32_t base = smb + (uint32_t)(slot) * FK_STAGE;                     \
        {   int m = tid >> 2, c = tid & 3;                                     \
            cp16(base + m * 80 + c * 16,                                       \
                 vals + (size_t)m * D_ALL + (k0) + c * 4); }                   \
        _Pragma("unroll")                                                      \
        for (int l = 0; l < 2; ++l) {                                          \
            int idx = tid + l * 256;                                           \
            int r = idx >> 5, c4 = idx & 31;                                   \
            cp16(base + FK_AS_B + r * 528 + c4 * 16,                           \
                 W + (size_t)((k0) + r) * D_ALL + n0 + c4 * 4); }              \
    } while (0)

    FK_ISSUE(0, kb); cp_commit();
    FK_ISSUE(1, kb + FK_BK); cp_commit();

    const int niter = FK_KCH / FK_BK;   // 28
    for (int it = 0; it < niter; ++it) {
        cp_wait1();
        __syncthreads();
        if (it + 2 < niter) { FK_ISSUE((it + 2) % FK_NST, kb + (it + 2) * FK_BK); }
        cp_commit();

        const int slot = it % FK_NST;
        const float* As = reinterpret_cast<const float*>(sm + slot * FK_STAGE);
        const float* Bs = reinterpret_cast<const float*>(sm + slot * FK_STAGE + FK_AS_B);

        #pragma unroll
        for (int kb4 = 0; kb4 < FK_BK / 4; ++kb4) {
            float4 a4[8];
            #pragma unroll
            for (int i = 0; i < 8; i++)
                a4[i] = *reinterpret_cast<const float4*>(As + (ty * 8 + i) * 20 + kb4 * 4);
            const float* af = reinterpret_cast<const float*>(a4);
            #pragma unroll
            for (int kk = 0; kk < 4; ++kk) {
                float4 bq = *reinterpret_cast<const float4*>(
                    Bs + (kb4 * 4 + kk) * 132 + tx * 4);
                float b[4] = {bq.x, bq.y, bq.z, bq.w};
                #pragma unroll
                for (int i = 0; i < 8; i++) {
                    float a = af[i * 4 + kk];
                    #pragma unroll
                    for (int j = 0; j < 4; j++)
                        acc[i][j] = fmaf(a, b[j], acc[i][j]);
                }
            }
        }
    }
    #undef FK_ISSUE

    #pragma unroll
    for (int i = 0; i < 8; i++) {
        int m = ty * 8 + i;
        #pragma unroll
        for (int j = 0; j < 4; j++)
            atomicAdd(Vout + (size_t)m * D_ALL + n0 + tx * 4 + j, acc[i][j]);
    }
}

// ---------------------------------------------------------------------------
// LayerNorm + exact GELU over rows of length D_ALL; writes fp16 hi.
// ---------------------------------------------------------------------------
__global__ __launch_bounds__(512) void ln_gelu_kernel(
    const float* __restrict__ h, const float* __restrict__ g, const float* __restrict__ b,
    half* __restrict__ ohi)
{
    __shared__ float row[D_ALL];
    __shared__ float reds[16], reds2[16];
    int bi = blockIdx.x, tid = threadIdx.x;
    const float4* hrow = reinterpret_cast<const float4*>(h + (size_t)bi * D_ALL);
    float4* rowv = reinterpret_cast<float4*>(row);

    float s = 0.f, s2 = 0.f;
    for (int i = tid; i < D_ALL / 4; i += 512) {
        float4 v = hrow[i];
        rowv[i] = v;
        s  += v.x + v.y + v.z + v.w;
        s2 += v.x * v.x + v.y * v.y + v.z * v.z + v.w * v.w;
    }
    #pragma unroll
    for (int o = 16; o > 0; o >>= 1) {
        s  += __shfl_xor_sync(0xffffffff, s, o);
        s2 += __shfl_xor_sync(0xffffffff, s2, o);
    }
    int warp = tid >> 5, lane = tid & 31;
    if (lane == 0) { reds[warp] = s; reds2[warp] = s2; }
    __syncthreads();
    if (warp == 0) {
        float a = (lane < 16) ? reds[lane] : 0.f;
        float a2 = (lane < 16) ? reds2[lane] : 0.f;
        #pragma unroll
        for (int o = 8; o > 0; o >>= 1) {
            a  += __shfl_xor_sync(0xffffffff, a, o);
            a2 += __shfl_xor_sync(0xffffffff, a2, o);
        }
        if (lane == 0) { reds[0] = a; reds2[0] = a2; }
    }
    __syncthreads();
    float mu = reds[0] * (1.0f / D_ALL);
    float var = reds2[0] * (1.0f / D_ALL) - mu * mu;
    float rstd = rsqrtf(var + LN_EPS);

    half* orow = ohi + (size_t)bi * D_ALL;
    for (int i = tid; i < D_ALL / 4; i += 512) {
        float4 v = rowv[i];
        float4 gg = reinterpret_cast<const float4*>(g)[i];
        float4 bb = reinterpret_cast<const float4*>(b)[i];
        float y0 = (v.x - mu) * rstd * gg.x + bb.x;
        float y1 = (v.y - mu) * rstd * gg.y + bb.y;
        float y2 = (v.z - mu) * rstd * gg.z + bb.z;
        float y3 = (v.w - mu) * rstd * gg.w + bb.w;
        const float k = 0.70710678118654752f;
        half o0 = __float2half_rn(0.5f * y0 * (1.0f + erff(y0 * k)));
        half o1 = __float2half_rn(0.5f * y1 * (1.0f + erff(y1 * k)));
        half o2 = __float2half_rn(0.5f * y2 * (1.0f + erff(y2 * k)));
        half o3 = __float2half_rn(0.5f * y3 * (1.0f + erff(y3 * k)));
        half h4[4] = {o0, o1, o2, o3};
        *reinterpret_cast<uint2*>(orow + i * 4) = *reinterpret_cast<uint2*>(h4);
    }
}

// ---------------------------------------------------------------------------
// Launch
// ---------------------------------------------------------------------------
extern "C" void kernel_launch(void* const* d_in, const int* in_sizes, int n_in,
                              void* d_out, int out_size)
{
    const float* pair_states    = (const float*)d_in[0];
    const float* macro_state    = (const float*)d_in[1];
    const float* mem_pair_keys  = (const float*)d_in[2];
    const float* mem_pair_vals  = (const float*)d_in[3];
    const float* mem_macro_keys = (const float*)d_in[4];
    const float* mem_macro_vals = (const float*)d_in[5];
    const float* fusion_w1      = (const float*)d_in[6];
    const float* fusion_b1      = (const float*)d_in[7];
    const float* fusion_ln_g    = (const float*)d_in[8];
    const float* fusion_ln_b    = (const float*)d_in[9];
    const float* fusion_w2      = (const float*)d_in[10];
    const float* fusion_b2      = (const float*)d_in[11];
    const float* pair_w         = (const float*)d_in[12];
    const float* pair_b         = (const float*)d_in[13];
    const float* pair_ln_g      = (const float*)d_in[14];
    const float* pair_ln_b      = (const float*)d_in[15];
    float* out = (float*)d_out;

    float *V, *h;
    half *a_hi, *V_hi, *V_lo, *w2_hi, *h_hi, *x_hi, *pw_hi;
    cudaGetSymbolAddress((void**)&a_hi,  g_attn_hi);
    cudaGetSymbolAddress((void**)&V,     g_V);
    cudaGetSymbolAddress((void**)&V_hi,  g_V_hi);
    cudaGetSymbolAddress((void**)&V_lo,  g_V_lo);
    cudaGetSymbolAddress((void**)&w2_hi, g_w2_hi);
    cudaGetSymbolAddress((void**)&h,     g_h);
    cudaGetSymbolAddress((void**)&h_hi,  g_h_hi);
    cudaGetSymbolAddress((void**)&x_hi,  g_xcat_hi);
    cudaGetSymbolAddress((void**)&pw_hi, g_pw_hi);

    const int SMEM_G2 = 4 * 18944;               // 75776 (1-term, 4 stages)
    const int SMEM_G1 = 3 * 27648;               // 82944 (2-term, 3 stages)
    const int SMEMP   = 128 * 132 * 4;           // 67584 (pair: os dominates)
    const int SMEMF   = FK_NST * FK_STAGE;       // 40704 (fold, 3-stage)
    cudaFuncSetAttribute(tc_gemm_kernel<1, 1, 4>,
                         cudaFuncAttributeMaxDynamicSharedMemorySize, SMEM_G2);
    cudaFuncSetAttribute(tc_gemm_kernel<2, 0, 3>,
                         cudaFuncAttributeMaxDynamicSharedMemorySize, SMEM_G1);
    cudaFuncSetAttribute(pair_gemm_ln_kernel,
                         cudaFuncAttributeMaxDynamicSharedMemorySize, SMEMP);
    cudaFuncSetAttribute(fold_kernel,
                         cudaFuncAttributeMaxDynamicSharedMemorySize, SMEMF);

    // 1) attention weights -> fp16 hi (B, 128); attn_pair also fills xcat
    //    pair_states half
    attn_pair_kernel<<<BATCH, 128>>>(pair_states, mem_pair_keys, a_hi, x_hi);
    attn_macro_kernel<<<BATCH, 128>>>(macro_state, mem_macro_keys, a_hi);

    // 2) fold: V = [vals_p @ W1top ; vals_m @ W1bot]  (128 x 3584 fp32)
    zero_kernel<<<(128 * D_ALL + 255) / 256, 256>>>(V, 128 * D_ALL);
    fold_kernel<<<dim3(D_ALL / FK_BN, FK_KS, 2), 256, SMEMF>>>(
        mem_pair_vals, mem_macro_vals, fusion_w1, V);
    {
        int n4 = (128 * D_ALL) / 4;
        cvt_split_kernel<<<(n4 + 255) / 256, 256>>>(
            (const float4*)V, (uint2*)V_hi, (uint2*)V_lo, n4);
    }

    // 2b) weight converts (hi-only)
    {
        int n4 = (D_ALL * D_ALL) / 4;
        cvt_hi_kernel<<<(n4 + 255) / 256, 256>>>(
            (const float4*)fusion_w2, (uint2*)w2_hi, n4);
        n4 = (NUM_PAIRS * 256 * 128) / 4;
        cvt_hi_kernel<<<(n4 + 255) / 256, 256>>>(
            (const float4*)pair_w, (uint2*)pw_hi, n4);
    }

    // 3) h = attn @ V + b1  (tensor cores, 2-term: A hi, B hi+lo, K=128)
    tc_gemm_kernel<2, 0, 3><<<dim3(D_ALL / 128, BATCH / 128), 256, SMEM_G1>>>(
        a_hi, nullptr, V_hi, V_lo, fusion_b1, h, nullptr,
        BATCH, D_ALL, 128, 128, D_ALL, D_ALL, 0);

    // 4) LN + GELU -> h_hi; GEMM2 (fp16 1-term, 4-stage) with xcat epilogue
    ln_gelu_kernel<<<BATCH, 512>>>(h, fusion_ln_g, fusion_ln_b, h_hi);
    tc_gemm_kernel<1, 1, 4><<<dim3((D_ALL / 128) * (BATCH / 128), 1), 256, SMEM_G2>>>(
        h_hi, nullptr, w2_hi, nullptr, fusion_b2, nullptr, x_hi,
        BATCH, D_ALL, D_ALL, D_ALL, D_ALL, D_ALL, 1);

    // 5) per-pair linear (1-term) + fused LN -> output
    pair_gemm_ln_kernel<<<dim3(BATCH / 128, NUM_PAIRS), 256, SMEMP>>>(
        x_hi, pw_hi, pair_b, pair_ln_g, pair_ln_b, out);
}

// round 14
// speedup vs baseline: 10.4898x; 1.0165x over previous
#include <cuda_runtime.h>
#include <cuda_fp16.h>
#include <math.h>
#include <stdint.h>

// ---------------------------------------------------------------------------
// Problem constants
// ---------------------------------------------------------------------------
#define BATCH      4096
#define NUM_PAIRS  28
#define PAIR_DIM   128
#define MACRO_DIM  256
#define NUM_SLOTS  64
#define D_ALL      3584          // NUM_PAIRS * PAIR_DIM
#define D_CAT      7168          // 2 * D_ALL
#define LN_EPS     1e-5f

// ---------------------------------------------------------------------------
// Scratch (device globals: allocation-free per harness rules)
// ---------------------------------------------------------------------------
__device__ half  g_attn_hi[BATCH * 128];                      // [attn_p | attn_m]
__device__ float g_V[(size_t)128 * D_ALL];                    // [Vp@W1top ; Vm@W1bot]
__device__ half  g_V_hi[(size_t)128 * D_ALL];
__device__ half  g_V_lo[(size_t)128 * D_ALL];
__device__ half  g_w2_hi[(size_t)D_ALL * D_ALL];
__device__ float g_h[(size_t)BATCH * D_ALL];
__device__ half  g_h_hi[(size_t)BATCH * D_ALL];
__device__ half  g_xcat_hi[(size_t)NUM_PAIRS * BATCH * 256];  // (p,b,256)
__device__ half  g_pw_hi[(size_t)NUM_PAIRS * 256 * 128];

// ---------------------------------------------------------------------------
// Small helpers
// ---------------------------------------------------------------------------
__device__ __forceinline__ uint32_t smem_u32(const void* p) {
    uint32_t a;
    asm("{ .reg .u64 t; cvta.to.shared.u64 t, %1; cvt.u32.u64 %0, t; }" : "=r"(a) : "l"(p));
    return a;
}
__device__ __forceinline__ void cp16(uint32_t dst, const void* src) {
    asm volatile("cp.async.cg.shared.global [%0], [%1], 16;" :: "r"(dst), "l"(src));
}
__device__ __forceinline__ void cp_commit() {
    asm volatile("cp.async.commit_group;" ::: "memory");
}
__device__ __forceinline__ void cp_wait0() {
    asm volatile("cp.async.wait_group 0;" ::: "memory");
}
__device__ __forceinline__ void cp_wait1() {
    asm volatile("cp.async.wait_group 1;" ::: "memory");
}
__device__ __forceinline__ void ldsm_x4(uint32_t* r, uint32_t addr) {
    asm volatile("ldmatrix.sync.aligned.m8n8.x4.shared.b16 {%0,%1,%2,%3}, [%4];"
        : "=r"(r[0]), "=r"(r[1]), "=r"(r[2]), "=r"(r[3]) : "r"(addr));
}
// x4 transposed: one instruction yields B fragments for TWO adjacent n8 tiles
// (lanes 0-15 address cols c..c+7, lanes 16-31 address cols c+8..c+15).
__device__ __forceinline__ void ldsm_x4_trans(uint32_t* r0, uint32_t* r1, uint32_t addr) {
    asm volatile("ldmatrix.sync.aligned.m8n8.x4.trans.shared.b16 {%0,%1,%2,%3}, [%4];"
        : "=r"(r0[0]), "=r"(r0[1]), "=r"(r1[0]), "=r"(r1[1]) : "r"(addr));
}
__device__ __forceinline__ void mma_f16(float* c, const uint32_t* a, const uint32_t* b) {
    asm volatile(
        "mma.sync.aligned.m16n8k16.row.col.f32.f16.f16.f32 "
        "{%0,%1,%2,%3}, {%4,%5,%6,%7}, {%8,%9}, {%0,%1,%2,%3};"
        : "+f"(c[0]), "+f"(c[1]), "+f"(c[2]), "+f"(c[3])
        : "r"(a[0]), "r"(a[1]), "r"(a[2]), "r"(a[3]), "r"(b[0]), "r"(b[1]));
}
__device__ __forceinline__ void split_hl(float v, half& h, half& l) {
    h = __float2half_rn(v);
    l = __float2half_rn(v - __half2float(h));
}

// ---------------------------------------------------------------------------
// Tensor-core fp16 GEMM: 128x128 tile, BK=32, NST-stage cp.async, 2 CTAs/SM.
//   TERMS==1: D = Ahi*Bhi
//   TERMS==2: D = Ahi*(Bhi+Blo)
//   TERMS==3: D = Ahi*Bhi + Ahi*Blo + Alo*Bhi
//   XCAT==1: write fp16 (hi only) into xcat fused-half (p = n-tile, b, 256).
//   swz==1:  flat-grid L2 swizzle: 7 groups of (4 n-tiles x 32 m-tiles).
// B fragments loaded with ldmatrix.x4.trans (2 n8 tiles per instruction).
// ---------------------------------------------------------------------------
#define TCB_K   32

template<int TERMS, int XCAT, int NST>
__global__ void __launch_bounds__(256, 2)
tc_gemm_kernel(const half* __restrict__ Ahi, const half* __restrict__ Alo,
               const half* __restrict__ Bhi, const half* __restrict__ Blo,
               const float* __restrict__ bias, float* __restrict__ C,
               half* __restrict__ Xhi,
               int M, int N, int K, int lda, int ldb, int ldc, int swz)
{
    constexpr int A_BYTES  = 10240;                    // 128 rows x 40 half
    constexpr int B_BYTES  = 8704;                     // 32 rows x 136 half
    constexpr int OFF_ALO  = A_BYTES;
    constexpr int OFF_BHI  = (TERMS == 3) ? 2 * A_BYTES : A_BYTES;
    constexpr int OFF_BLO  = OFF_BHI + B_BYTES;
    constexpr int STAGE    = (TERMS == 1) ? (OFF_BHI + B_BYTES)
                                          : (OFF_BLO + B_BYTES);

    extern __shared__ __align__(16) char sm[];
    const uint32_t smb = smem_u32(sm);

    int bx, by;
    if (swz) {
        int id = blockIdx.x;       // 896 blocks: 7 groups x (4 n x 32 m)
        int ng = id >> 7;
        int r  = id & 127;
        bx = ng * 4 + (r & 3);     // 0..27
        by = r >> 2;               // 0..31
    } else {
        bx = blockIdx.x; by = blockIdx.y;
    }

    const int tid  = threadIdx.x;
    const int wid  = tid >> 5;
    const int lane = tid & 31;
    const int wm   = wid & 1;
    const int wn   = wid >> 1;
    const int m0   = by * 128;
    const int n0   = bx * 128;

    const int tA = lane >> 3, rA = lane & 7;
    const int a_row_off = (tA & 1) * 8 + rA;
    const int a_kcol    = (tA >> 1) * 8;
    const uint32_t a_const = (uint32_t)((wm * 64 + a_row_off) * 40 + a_kcol) * 2;
    // x4.trans B addressing: lanes 0-15 -> rows k0..15 at col base; lanes
    // 16-31 -> rows k0..15 at col base + 8.
    const uint32_t b_const =
        (uint32_t)((lane & 15) * 136 + wn * 32 + (lane >> 4) * 8) * 2;

    float acc[4][4][4];
    #pragma unroll
    for (int i = 0; i < 4; i++)
        #pragma unroll
        for (int j = 0; j < 4; j++)
            #pragma unroll
            for (int q = 0; q < 4; q++) acc[i][j][q] = 0.f;

    const int nk = K / TCB_K;

    #define ISSUE_STAGE(slot, kt) do {                                         \
        uint32_t base = smb + (uint32_t)(slot) * STAGE;                        \
        int k0 = (kt) * TCB_K;                                                 \
        _Pragma("unroll")                                                      \
        for (int l = 0; l < 2; ++l) {                                          \
            int idx = tid + l * 256;                                           \
            int r = idx >> 2, c = idx & 3;                                     \
            cp16(base + r * 80 + c * 16,                                       \
                 Ahi + (size_t)(m0 + r) * lda + k0 + c * 8);                   \
            if constexpr (TERMS == 3)                                          \
                cp16(base + OFF_ALO + r * 80 + c * 16,                         \
                     Alo + (size_t)(m0 + r) * lda + k0 + c * 8);               \
        }                                                                      \
        _Pragma("unroll")                                                      \
        for (int l = 0; l < 2; ++l) {                                          \
            int idx = tid + l * 256;                                           \
            int r = idx >> 4, c = idx & 15;                                    \
            cp16(base + OFF_BHI + r * 272 + c * 16,                            \
                 Bhi + (size_t)(k0 + r) * ldb + n0 + c * 8);                   \
            if constexpr (TERMS >= 2)                                          \
                cp16(base + OFF_BLO + r * 272 + c * 16,                        \
                     Blo + (size_t)(k0 + r) * ldb + n0 + c * 8);               \
        }                                                                      \
    } while (0)

    #pragma unroll
    for (int s = 0; s < NST - 1; ++s) {
        if (s < nk) ISSUE_STAGE(s, s);
        cp_commit();
    }

    for (int kt = 0; kt < nk; ++kt) {
        asm volatile("cp.async.wait_group %0;" :: "n"(NST - 2) : "memory");
        __syncthreads();
        if (kt + NST - 1 < nk) { ISSUE_STAGE((kt + NST - 1) % NST, kt + NST - 1); }
        cp_commit();

        const int slot = kt % NST;
        const uint32_t base = smb + (uint32_t)slot * STAGE;
        const uint32_t aHb = base + a_const;
        const uint32_t aLb = base + OFF_ALO + a_const;
        const uint32_t bHb = base + OFF_BHI + b_const;
        const uint32_t bLb = base + OFF_BLO + b_const;

        #pragma unroll
        for (int kk = 0; kk < 2; ++kk) {
            uint32_t aH[4][4], aL[4][4], bH[4][2], bL[4][2];
            const uint32_t akk = (uint32_t)(kk * 16 * 2);
            const uint32_t bkk = (uint32_t)(kk * 16 * 136 * 2);
            #pragma unroll
            for (int mf = 0; mf < 4; ++mf) {
                uint32_t off = (uint32_t)(mf * 16 * 40) * 2 + akk;
                ldsm_x4(aH[mf], aHb + off);
                if constexpr (TERMS == 3) ldsm_x4(aL[mf], aLb + off);
            }
            #pragma unroll
            for (int nf = 0; nf < 4; nf += 2) {
                uint32_t off = (uint32_t)(nf * 8) * 2 + bkk;
                ldsm_x4_trans(bH[nf], bH[nf + 1], bHb + off);
                if constexpr (TERMS >= 2)
                    ldsm_x4_trans(bL[nf], bL[nf + 1], bLb + off);
            }
            #pragma unroll
            for (int mf = 0; mf < 4; ++mf)
                #pragma unroll
                for (int nf = 0; nf < 4; ++nf) {
                    mma_f16(acc[mf][nf], aH[mf], bH[nf]);
                    if constexpr (TERMS >= 2) mma_f16(acc[mf][nf], aH[mf], bL[nf]);
                    if constexpr (TERMS == 3) mma_f16(acc[mf][nf], aL[mf], bH[nf]);
                }
        }
    }
    #undef ISSUE_STAGE

    const int g  = lane >> 2;
    const int tg = lane & 3;
    #pragma unroll
    for (int mf = 0; mf < 4; ++mf) {
        int r0 = m0 + wm * 64 + mf * 16 + g;
        #pragma unroll
        for (int nf = 0; nf < 4; ++nf) {
            int c = wn * 32 + nf * 8 + tg * 2;
            float b0 = bias[n0 + c], b1 = bias[n0 + c + 1];
            float v00 = acc[mf][nf][0] + b0, v01 = acc[mf][nf][1] + b1;
            float v10 = acc[mf][nf][2] + b0, v11 = acc[mf][nf][3] + b1;
            if constexpr (XCAT == 1) {
                size_t d0 = ((size_t)bx * BATCH + r0) * 256 + 128 + c;
                size_t d1 = ((size_t)bx * BATCH + r0 + 8) * 256 + 128 + c;
                *reinterpret_cast<half2*>(Xhi + d0) =
                    __halves2half2(__float2half_rn(v00), __float2half_rn(v01));
                *reinterpret_cast<half2*>(Xhi + d1) =
                    __halves2half2(__float2half_rn(v10), __float2half_rn(v11));
            } else {
                *reinterpret_cast<float2*>(C + (size_t)r0 * ldc + n0 + c) =
                    make_float2(v00, v01);
                *reinterpret_cast<float2*>(C + (size_t)(r0 + 8) * ldc + n0 + c) =
                    make_float2(v10, v11);
            }
        }
    }
}

// ---------------------------------------------------------------------------
// Pair GEMM + fused LayerNorm: per p (blockIdx.y), C-tile 128(b) x 128(e),
// K=256, 1-term (A-hi x B-hi), LN over the 128-wide row in the epilogue.
// 2 CTAs/SM. B via ldmatrix.x4.trans.
// ---------------------------------------------------------------------------
__global__ void __launch_bounds__(256, 2)
pair_gemm_ln_kernel(const half* __restrict__ Xhi,
                    const half* __restrict__ PWhi,
                    const float* __restrict__ pb, const float* __restrict__ lng,
                    const float* __restrict__ lnb, float* __restrict__ out)
{
    constexpr int A_BYTES = 10240;
    constexpr int B_BYTES = 8704;
    constexpr int OFF_BHI = A_BYTES;
    constexpr int STAGE   = OFF_BHI + B_BYTES;   // 18944

    extern __shared__ __align__(16) char sm[];
    const uint32_t smb = smem_u32(sm);

    const int p   = blockIdx.y;
    const int m0  = blockIdx.x * 128;
    const int tid  = threadIdx.x;
    const int wid  = tid >> 5;
    const int lane = tid & 31;
    const int wm   = wid & 1;
    const int wn   = wid >> 1;

    const half* Ahi = Xhi + ((size_t)p * BATCH) * 256;
    const half* Bhi = PWhi + (size_t)p * 256 * 128;

    const int tA = lane >> 3, rA = lane & 7;
    const int a_row_off = (tA & 1) * 8 + rA;
    const int a_kcol    = (tA >> 1) * 8;
    const uint32_t a_const = (uint32_t)((wm * 64 + a_row_off) * 40 + a_kcol) * 2;
    const uint32_t b_const =
        (uint32_t)((lane & 15) * 136 + wn * 32 + (lane >> 4) * 8) * 2;

    float acc[4][4][4];
    #pragma unroll
    for (int i = 0; i < 4; i++)
        #pragma unroll
        for (int j = 0; j < 4; j++)
            #pragma unroll
            for (int q = 0; q < 4; q++) acc[i][j][q] = 0.f;

    #define P_ISSUE(slot, kt) do {                                             \
        uint32_t base = smb + (uint32_t)(slot) * STAGE;                        \
        int k0 = (kt) * TCB_K;                                                 \
        _Pragma("unroll")                                                      \
        for (int l = 0; l < 2; ++l) {                                          \
            int idx = tid + l * 256;                                           \
            int r = idx >> 2, c = idx & 3;                                     \
            cp16(base + r * 80 + c * 16,                                       \
                 Ahi + (size_t)(m0 + r) * 256 + k0 + c * 8);                   \
        }                                                                      \
        _Pragma("unroll")                                                      \
        for (int l = 0; l < 2; ++l) {                                          \
            int idx = tid + l * 256;                                           \
            int r = idx >> 4, c = idx & 15;                                    \
            cp16(base + OFF_BHI + r * 272 + c * 16,                            \
                 Bhi + (size_t)(k0 + r) * 128 + c * 8);                        \
        }                                                                      \
    } while (0)

    P_ISSUE(0, 0); cp_commit();

    #pragma unroll
    for (int kt = 0; kt < 8; ++kt) {           // K=256 -> 8 iters of 32
        cp_wait0();
        __syncthreads();
        if (kt + 1 < 8) { P_ISSUE((kt + 1) & 1, kt + 1); cp_commit(); }

        const uint32_t base = smb + (uint32_t)(kt & 1) * STAGE;
        const uint32_t aHb = base + a_const;
        const uint32_t bHb = base + OFF_BHI + b_const;

        #pragma unroll
        for (int kk = 0; kk < 2; ++kk) {
            uint32_t aH[4][4], bH[4][2];
            const uint32_t akk = (uint32_t)(kk * 16 * 2);
            const uint32_t bkk = (uint32_t)(kk * 16 * 136 * 2);
            #pragma unroll
            for (int mf = 0; mf < 4; ++mf) {
                uint32_t off = (uint32_t)(mf * 16 * 40) * 2 + akk;
                ldsm_x4(aH[mf], aHb + off);
            }
            #pragma unroll
            for (int nf = 0; nf < 4; nf += 2) {
                uint32_t off = (uint32_t)(nf * 8) * 2 + bkk;
                ldsm_x4_trans(bH[nf], bH[nf + 1], bHb + off);
            }
            #pragma unroll
            for (int mf = 0; mf < 4; ++mf)
                #pragma unroll
                for (int nf = 0; nf < 4; ++nf)
                    mma_f16(acc[mf][nf], aH[mf], bH[nf]);
        }
    }
    #undef P_ISSUE

    // ---- epilogue: stage (bias-added) outputs in smem, then LN per row
    __syncthreads();                       // done with stage buffers
    float* os = reinterpret_cast<float*>(sm);   // [128][132]
    const int g  = lane >> 2;
    const int tg = lane & 3;
    #pragma unroll
    for (int mf = 0; mf < 4; ++mf) {
        int r0 = wm * 64 + mf * 16 + g;
        #pragma unroll
        for (int nf = 0; nf < 4; ++nf) {
            int c = wn * 32 + nf * 8 + tg * 2;
            float b0 = pb[p * 128 + c], b1 = pb[p * 128 + c + 1];
            os[r0 * 132 + c]           = acc[mf][nf][0] + b0;
            os[r0 * 132 + c + 1]       = acc[mf][nf][1] + b1;
            os[(r0 + 8) * 132 + c]     = acc[mf][nf][2] + b0;
            os[(r0 + 8) * 132 + c + 1] = acc[mf][nf][3] + b1;
        }
    }
    __syncthreads();

    #pragma unroll
    for (int rr = 0; rr < 16; ++rr) {
        int r = wid * 16 + rr;
        const float* t = os + r * 132;
        float v0 = t[lane], v1 = t[lane + 32], v2 = t[lane + 64], v3 = t[lane + 96];
        float s = v0 + v1 + v2 + v3;
        #pragma unroll
        for (int o = 16; o > 0; o >>= 1) s += __shfl_xor_sync(0xffffffff, s, o);
        float mu = s * (1.0f / 128.0f);
        float d0 = v0 - mu, d1 = v1 - mu, d2 = v2 - mu, d3 = v3 - mu;
        float s2 = d0 * d0 + d1 * d1 + d2 * d2 + d3 * d3;
        #pragma unroll
        for (int o = 16; o > 0; o >>= 1) s2 += __shfl_xor_sync(0xffffffff, s2, o);
        float rstd = rsqrtf(s2 * (1.0f / 128.0f) + LN_EPS);

        int b = m0 + r;
        size_t base = (size_t)b * D_ALL + p * 128;
        int gi = p * 128;
        out[base + lane]      = d0 * rstd * lng[gi + lane]      + lnb[gi + lane];
        out[base + lane + 32] = d1 * rstd * lng[gi + lane + 32] + lnb[gi + lane + 32];
        out[base + lane + 64] = d2 * rstd * lng[gi + lane + 64] + lnb[gi + lane + 64];
        out[base + lane + 96] = d3 * rstd * lng[gi + lane + 96] + lnb[gi + lane + 96];
    }
}

// ---------------------------------------------------------------------------
// fp32 -> fp16 hi/lo split (elementwise, vectorized)
// ---------------------------------------------------------------------------
__global__ __launch_bounds__(256) void cvt_split_kernel(
    const float4* __restrict__ x, uint2* __restrict__ hi, uint2* __restrict__ lo, int n4)
{
    int i = blockIdx.x * 256 + threadIdx.x;
    if (i >= n4) return;
    float4 v = x[i];
    half h0, l0, h1, l1, h2, l2, h3, l3;
    split_hl(v.x, h0, l0); split_hl(v.y, h1, l1);
    split_hl(v.z, h2, l2); split_hl(v.w, h3, l3);
    half2 ha = __halves2half2(h0, h1), hb = __halves2half2(h2, h3);
    half2 la = __halves2half2(l0, l1), lb = __halves2half2(l2, l3);
    hi[i] = make_uint2(*reinterpret_cast<uint32_t*>(&ha), *reinterpret_cast<uint32_t*>(&hb));
    lo[i] = make_uint2(*reinterpret_cast<uint32_t*>(&la), *reinterpret_cast<uint32_t*>(&lb));
}

// fp32 -> fp16 hi only
__global__ __launch_bounds__(256) void cvt_hi_kernel(
    const float4* __restrict__ x, uint2* __restrict__ hi, int n4)
{
    int i = blockIdx.x * 256 + threadIdx.x;
    if (i >= n4) return;
    float4 v = x[i];
    half2 ha = __halves2half2(__float2half_rn(v.x), __float2half_rn(v.y));
    half2 hb = __halves2half2(__float2half_rn(v.z), __float2half_rn(v.w));
    hi[i] = make_uint2(*reinterpret_cast<uint32_t*>(&ha), *reinterpret_cast<uint32_t*>(&hb));
}

// ---------------------------------------------------------------------------
// attention weight kernels -> g_attn_hi (B, 128): [pair | macro]
// attn_pair also emits the xcat pair_states half (hi fp16) for row b.
// ---------------------------------------------------------------------------
__global__ __launch_bounds__(128) void attn_pair_kernel(
    const float* __restrict__ ps, const float* __restrict__ keys,
    half* __restrict__ ahi, half* __restrict__ xhi)
{
    int b = blockIdx.x, tid = threadIdx.x;
    __shared__ float q[PAIR_DIM];
    __shared__ float sc[NUM_SLOTS];
    __shared__ float red[NUM_SLOTS];

    const float* psrow = ps + (size_t)b * D_ALL;

    float s = 0.f;
    #pragma unroll
    for (int p = 0; p < NUM_PAIRS; p++)
        s += psrow[p * PAIR_DIM + tid];
    q[tid] = s * (1.0f / NUM_PAIRS);
    __syncthreads();

    if (tid < NUM_SLOTS) {
        float acc = 0.f;
        #pragma unroll 4
        for (int d = 0; d < PAIR_DIM; d++)
            acc = fmaf(q[d], keys[tid * PAIR_DIM + d], acc);
        sc[tid] = acc * 0.08838834764831845f;
    }
    __syncthreads();

    if (tid < NUM_SLOTS) red[tid] = sc[tid];
    __syncthreads();
    for (int o = 32; o > 0; o >>= 1) {
        if (tid < o) red[tid] = fmaxf(red[tid], red[tid + o]);
        __syncthreads();
    }
    float mx = red[0];
    __syncthreads();

    float e = 0.f;
    if (tid < NUM_SLOTS) { e = expf(sc[tid] - mx); red[tid] = e; }
    __syncthreads();
    for (int o = 32; o > 0; o >>= 1) {
        if (tid < o) red[tid] += red[tid + o];
        __syncthreads();
    }
    if (tid < NUM_SLOTS)
        ahi[(size_t)b * 128 + tid] = __float2half_rn(e / red[0]);

    // ---- fused: write xcat pair_states half (hi fp16), row b, all 28 pairs
    #pragma unroll
    for (int p = 0; p < NUM_PAIRS; p++) {
        float v = psrow[p * PAIR_DIM + tid];
        xhi[((size_t)p * BATCH + b) * 256 + tid] = __float2half_rn(v);
    }
}

__global__ __launch_bounds__(128) void attn_macro_kernel(
    const float* __restrict__ ms, const float* __restrict__ keys,
    half* __restrict__ ahi)
{
    int b = blockIdx.x, tid = threadIdx.x;
    __shared__ float q[MACRO_DIM];
    __shared__ float sc[NUM_SLOTS];
    __shared__ float red[NUM_SLOTS];

    q[tid]       = ms[(size_t)b * MACRO_DIM + tid];
    q[tid + 128] = ms[(size_t)b * MACRO_DIM + tid + 128];
    __syncthreads();

    if (tid < NUM_SLOTS) {
        float acc = 0.f;
        #pragma unroll 4
        for (int d = 0; d < MACRO_DIM; d++)
            acc = fmaf(q[d], keys[tid * MACRO_DIM + d], acc);
        sc[tid] = acc * 0.0625f;
    }
    __syncthreads();

    if (tid < NUM_SLOTS) red[tid] = sc[tid];
    __syncthreads();
    for (int o = 32; o > 0; o >>= 1) {
        if (tid < o) red[tid] = fmaxf(red[tid], red[tid + o]);
        __syncthreads();
    }
    float mx = red[0];
    __syncthreads();

    float e = 0.f;
    if (tid < NUM_SLOTS) { e = expf(sc[tid] - mx); red[tid] = e; }
    __syncthreads();
    for (int o = 32; o > 0; o >>= 1) {
        if (tid < o) red[tid] += red[tid + o];
        __syncthreads();
    }
    if (tid < NUM_SLOTS)
        ahi[(size_t)b * 128 + 64 + tid] = __float2half_rn(e / red[0]);
}

// ---------------------------------------------------------------------------
// Zero kernel (for g_V before atomic fold)
// ---------------------------------------------------------------------------
__global__ __launch_bounds__(256) void zero_kernel(float* __restrict__ p, int n)
{
    int i = blockIdx.x * 256 + threadIdx.x;
    if (i < n) p[i] = 0.f;
}

// ---------------------------------------------------------------------------
// Fold (v5 config): V[z*64 + m, n] += sum_k vals_z[m,k] * W1[z*3584 + k, n]
// Tile 64(M) x 128(N), BK=16, split-K=16, 3-stage cp.async.
// Inner loop: 4-k blocks, broadcast LDS.128 A loads. 3 CTAs/SM.
// ---------------------------------------------------------------------------
#define FK_KS   16
#define FK_KCH  (D_ALL / FK_KS)    // 224
#define FK_BK   16
#define FK_BN   128
#define FK_AS_B   5120
#define FK_STAGE  13568
#define FK_NST    3

__global__ __launch_bounds__(256, 3) void fold_kernel(
    const float* __restrict__ vals_p, const float* __restrict__ vals_m,
    const float* __restrict__ w1, float* __restrict__ V)
{
    extern __shared__ __align__(16) char sm[];
    const uint32_t smb = smem_u32(sm);

    const int nb = blockIdx.x;
    const int ks = blockIdx.y;
    const int z  = blockIdx.z;
    const float* vals = z ? vals_m : vals_p;
    const float* W    = w1 + (size_t)z * D_ALL * D_ALL;
    float* Vout       = V  + (size_t)z * 64 * D_ALL;

    const int tid = threadIdx.x;
    const int ty  = tid >> 5;
    const int tx  = tid & 31;
    const int n0  = nb * FK_BN;
    const int kb  = ks * FK_KCH;

    float acc[8][4];
    #pragma unroll
    for (int i = 0; i < 8; i++)
        #pragma unroll
        for (int j = 0; j < 4; j++) acc[i][j] = 0.f;

    #define FK_ISSUE(slot, k0) do {                                            \
        uint32_t base = smb + (uint32_t)(slot) * FK_STAGE;                     \
        {   int m = tid >> 2, c = tid & 3;                                     \
            cp16(base + m * 80 + c * 16,                                       \
                 vals + (size_t)m * D_ALL + (k0) + c * 4); }                   \
        _Pragma("unroll")                                                      \
        for (int l = 0; l < 2; ++l) {                                          \
            int idx = tid + l * 256;                                           \
            int r = idx >> 5, c4 = idx & 31;                                   \
            cp16(base + FK_AS_B + r * 528 + c4 * 16,                           \
                 W + (size_t)((k0) + r) * D_ALL + n0 + c4 * 4); }              \
    } while (0)

    FK_ISSUE(0, kb); cp_commit();
    FK_ISSUE(1, kb + FK_BK); cp_commit();

    const int niter = FK_KCH / FK_BK;   // 14
    for (int it = 0; it < niter; ++it) {
        cp_wait1();
        __syncthreads();
        if (it + 2 < niter) { FK_ISSUE((it + 2) % FK_NST, kb + (it + 2) * FK_BK); }
        cp_commit();

        const int slot = it % FK_NST;
        const float* As = reinterpret_cast<const float*>(sm + slot * FK_STAGE);
        const float* Bs = reinterpret_cast<const float*>(sm + slot * FK_STAGE + FK_AS_B);

        #pragma unroll
        for (int kb4 = 0; kb4 < FK_BK / 4; ++kb4) {
            float4 a4[8];
            #pragma unroll
            for (int i = 0; i < 8; i++)
                a4[i] = *reinterpret_cast<const float4*>(As + (ty * 8 + i) * 20 + kb4 * 4);
            const float* af = reinterpret_cast<const float*>(a4);
            #pragma unroll
            for (int kk = 0; kk < 4; ++kk) {
                float4 bq = *reinterpret_cast<const float4*>(
                    Bs + (kb4 * 4 + kk) * 132 + tx * 4);
                float b[4] = {bq.x, bq.y, bq.z, bq.w};
                #pragma unroll
                for (int i = 0; i < 8; i++) {
                    float a = af[i * 4 + kk];
                    #pragma unroll
                    for (int j = 0; j < 4; j++)
                        acc[i][j] = fmaf(a, b[j], acc[i][j]);
                }
            }
        }
    }
    #undef FK_ISSUE

    #pragma unroll
    for (int i = 0; i < 8; i++) {
        int m = ty * 8 + i;
        #pragma unroll
        for (int j = 0; j < 4; j++)
            atomicAdd(Vout + (size_t)m * D_ALL + n0 + tx * 4 + j, acc[i][j]);
    }
}

// ---------------------------------------------------------------------------
// LayerNorm + exact GELU over rows of length D_ALL; writes fp16 hi.
// ---------------------------------------------------------------------------
__global__ __launch_bounds__(512) void ln_gelu_kernel(
    const float* __restrict__ h, const float* __restrict__ g, const float* __restrict__ b,
    half* __restrict__ ohi)
{
    __shared__ float row[D_ALL];
    __shared__ float reds[16], reds2[16];
    int bi = blockIdx.x, tid = threadIdx.x;
    const float4* hrow = reinterpret_cast<const float4*>(h + (size_t)bi * D_ALL);
    float4* rowv = reinterpret_cast<float4*>(row);

    float s = 0.f, s2 = 0.f;
    for (int i = tid; i < D_ALL / 4; i += 512) {
        float4 v = hrow[i];
        rowv[i] = v;
        s  += v.x + v.y + v.z + v.w;
        s2 += v.x * v.x + v.y * v.y + v.z * v.z + v.w * v.w;
    }
    #pragma unroll
    for (int o = 16; o > 0; o >>= 1) {
        s  += __shfl_xor_sync(0xffffffff, s, o);
        s2 += __shfl_xor_sync(0xffffffff, s2, o);
    }
    int warp = tid >> 5, lane = tid & 31;
    if (lane == 0) { reds[warp] = s; reds2[warp] = s2; }
    __syncthreads();
    if (warp == 0) {
        float a = (lane < 16) ? reds[lane] : 0.f;
        float a2 = (lane < 16) ? reds2[lane] : 0.f;
        #pragma unroll
        for (int o = 8; o > 0; o >>= 1) {
            a  += __shfl_xor_sync(0xffffffff, a, o);
            a2 += __shfl_xor_sync(0xffffffff, a2, o);
        }
        if (lane == 0) { reds[0] = a; reds2[0] = a2; }
    }
    __syncthreads();
    float mu = reds[0] * (1.0f / D_ALL);
    float var = reds2[0] * (1.0f / D_ALL) - mu * mu;
    float rstd = rsqrtf(var + LN_EPS);

    half* orow = ohi + (size_t)bi * D_ALL;
    for (int i = tid; i < D_ALL / 4; i += 512) {
        float4 v = rowv[i];
        float4 gg = reinterpret_cast<const float4*>(g)[i];
        float4 bb = reinterpret_cast<const float4*>(b)[i];
        float y0 = (v.x - mu) * rstd * gg.x + bb.x;
        float y1 = (v.y - mu) * rstd * gg.y + bb.y;
        float y2 = (v.z - mu) * rstd * gg.z + bb.z;
        float y3 = (v.w - mu) * rstd * gg.w + bb.w;
        const float k = 0.70710678118654752f;
        half o0 = __float2half_rn(0.5f * y0 * (1.0f + erff(y0 * k)));
        half o1 = __float2half_rn(0.5f * y1 * (1.0f + erff(y1 * k)));
        half o2 = __float2half_rn(0.5f * y2 * (1.0f + erff(y2 * k)));
        half o3 = __float2half_rn(0.5f * y3 * (1.0f + erff(y3 * k)));
        half h4[4] = {o0, o1, o2, o3};
        *reinterpret_cast<uint2*>(orow + i * 4) = *reinterpret_cast<uint2*>(h4);
    }
}

// ---------------------------------------------------------------------------
// Launch
// ---------------------------------------------------------------------------
extern "C" void kernel_launch(void* const* d_in, const int* in_sizes, int n_in,
                              void* d_out, int out_size)
{
    const float* pair_states    = (const float*)d_in[0];
    const float* macro_state    = (const float*)d_in[1];
    const float* mem_pair_keys  = (const float*)d_in[2];
    const float* mem_pair_vals  = (const float*)d_in[3];
    const float* mem_macro_keys = (const float*)d_in[4];
    const float* mem_macro_vals = (const float*)d_in[5];
    const float* fusion_w1      = (const float*)d_in[6];
    const float* fusion_b1      = (const float*)d_in[7];
    const float* fusion_ln_g    = (const float*)d_in[8];
    const float* fusion_ln_b    = (const float*)d_in[9];
    const float* fusion_w2      = (const float*)d_in[10];
    const float* fusion_b2      = (const float*)d_in[11];
    const float* pair_w         = (const float*)d_in[12];
    const float* pair_b         = (const float*)d_in[13];
    const float* pair_ln_g      = (const float*)d_in[14];
    const float* pair_ln_b      = (const float*)d_in[15];
    float* out = (float*)d_out;

    float *V, *h;
    half *a_hi, *V_hi, *V_lo, *w2_hi, *h_hi, *x_hi, *pw_hi;
    cudaGetSymbolAddress((void**)&a_hi,  g_attn_hi);
    cudaGetSymbolAddress((void**)&V,     g_V);
    cudaGetSymbolAddress((void**)&V_hi,  g_V_hi);
    cudaGetSymbolAddress((void**)&V_lo,  g_V_lo);
    cudaGetSymbolAddress((void**)&w2_hi, g_w2_hi);
    cudaGetSymbolAddress((void**)&h,     g_h);
    cudaGetSymbolAddress((void**)&h_hi,  g_h_hi);
    cudaGetSymbolAddress((void**)&x_hi,  g_xcat_hi);
    cudaGetSymbolAddress((void**)&pw_hi, g_pw_hi);

    const int SMEM_G2 = 4 * 18944;               // 75776 (1-term, 4 stages)
    const int SMEM_G1 = 3 * 27648;               // 82944 (2-term, 3 stages)
    const int SMEMP   = 128 * 132 * 4;           // 67584 (pair: os dominates)
    const int SMEMF   = FK_NST * FK_STAGE;       // 40704 (fold, 3-stage)
    cudaFuncSetAttribute(tc_gemm_kernel<1, 1, 4>,
                         cudaFuncAttributeMaxDynamicSharedMemorySize, SMEM_G2);
    cudaFuncSetAttribute(tc_gemm_kernel<2, 0, 3>,
                         cudaFuncAttributeMaxDynamicSharedMemorySize, SMEM_G1);
    cudaFuncSetAttribute(pair_gemm_ln_kernel,
                         cudaFuncAttributeMaxDynamicSharedMemorySize, SMEMP);
    cudaFuncSetAttribute(fold_kernel,
                         cudaFuncAttributeMaxDynamicSharedMemorySize, SMEMF);

    // 1) attention weights -> fp16 hi (B, 128); attn_pair also fills xcat
    //    pair_states half
    attn_pair_kernel<<<BATCH, 128>>>(pair_states, mem_pair_keys, a_hi, x_hi);
    attn_macro_kernel<<<BATCH, 128>>>(macro_state, mem_macro_keys, a_hi);

    // 2) fold: V = [vals_p @ W1top ; vals_m @ W1bot]  (128 x 3584 fp32)
    zero_kernel<<<(128 * D_ALL + 255) / 256, 256>>>(V, 128 * D_ALL);
    fold_kernel<<<dim3(D_ALL / FK_BN, FK_KS, 2), 256, SMEMF>>>(
        mem_pair_vals, mem_macro_vals, fusion_w1, V);
    {
        int n4 = (128 * D_ALL) / 4;
        cvt_split_kernel<<<(n4 + 255) / 256, 256>>>(
            (const float4*)V, (uint2*)V_hi, (uint2*)V_lo, n4);
    }

    // 2b) weight converts (hi-only)
    {
        int n4 = (D_ALL * D_ALL) / 4;
        cvt_hi_kernel<<<(n4 + 255) / 256, 256>>>(
            (const float4*)fusion_w2, (uint2*)w2_hi, n4);
        n4 = (NUM_PAIRS * 256 * 128) / 4;
        cvt_hi_kernel<<<(n4 + 255) / 256, 256>>>(
            (const float4*)pair_w, (uint2*)pw_hi, n4);
    }

    // 3) h = attn @ V + b1  (tensor cores, 2-term: A hi, B hi+lo, K=128)
    tc_gemm_kernel<2, 0, 3><<<dim3(D_ALL / 128, BATCH / 128), 256, SMEM_G1>>>(
        a_hi, nullptr, V_hi, V_lo, fusion_b1, h, nullptr,
        BATCH, D_ALL, 128, 128, D_ALL, D_ALL, 0);

    // 4) LN + GELU -> h_hi; GEMM2 (fp16 1-term, 4-stage) with xcat epilogue
    ln_gelu_kernel<<<BATCH, 512>>>(h, fusion_ln_g, fusion_ln_b, h_hi);
    tc_gemm_kernel<1, 1, 4><<<dim3((D_ALL / 128) * (BATCH / 128), 1), 256, SMEM_G2>>>(
        h_hi, nullptr, w2_hi, nullptr, fusion_b2, nullptr, x_hi,
        BATCH, D_ALL, D_ALL, D_ALL, D_ALL, D_ALL, 1);

    // 5) per-pair linear (1-term) + fused LN -> output
    pair_gemm_ln_kernel<<<dim3(BATCH / 128, NUM_PAIRS), 256, SMEMP>>>(
        x_hi, pw_hi, pair_b, pair_ln_g, pair_ln_b, out);
}